// round 5
// baseline (speedup 1.0000x reference)
#include <cuda_runtime.h>
#include <math.h>
#include <stdint.h>

#define B_  2
#define N_  2048
#define C_  1024
#define H_  16
#define DH_ 64
#define M_  (B_*N_)
#define BH_ (B_*H_)

// Pre-split interleaved (hi,lo) scratch + plain tf32 V.
__device__ float2 g_xi [M_ * C_];        // x split
__device__ float2 g_wqi[3 * C_ * C_];    // qkv_w split
__device__ float2 g_wpi[C_ * C_];        // proj_w split
__device__ float2 g_qi [BH_ * N_ * DH_]; // q (rope'd, pre-scaled 1/8) split
__device__ float2 g_ki [BH_ * N_ * DH_]; // k (rope'd) split
__device__ float  g_v  [BH_ * N_ * DH_]; // v tf32-rounded
__device__ float2 g_aoi[M_ * C_];        // attention output split

__constant__ float c_invf[16] = {
    1.0f, 0.7498942093324559f, 0.5623413251903491f, 0.4216965034285822f,
    0.31622776601683794f, 0.23713737056616552f, 0.1778279410038923f,
    0.13335214321633237f, 0.1f, 0.07498942093324558f, 0.05623413251903491f,
    0.04216965034285822f, 0.031622776601683794f, 0.023713737056616552f,
    0.01778279410038923f, 0.013335214321633237f
};

__device__ __forceinline__ float tf32r(float x) {
    uint32_t u;
    asm("cvt.rna.tf32.f32 %0, %1;" : "=r"(u) : "f"(x));
    return __uint_as_float(u);
}
__device__ __forceinline__ void mma8(float* d, const uint32_t* a, const uint32_t* b) {
    asm volatile(
        "mma.sync.aligned.m16n8k8.row.col.f32.tf32.tf32.f32 "
        "{%0,%1,%2,%3}, {%4,%5,%6,%7}, {%8,%9}, {%0,%1,%2,%3};"
        : "+f"(d[0]), "+f"(d[1]), "+f"(d[2]), "+f"(d[3])
        : "r"(a[0]), "r"(a[1]), "r"(a[2]), "r"(a[3]), "r"(b[0]), "r"(b[1]));
}
__device__ __forceinline__ uint32_t smem_u32(const void* p) {
    uint32_t a;
    asm("{ .reg .u64 t; cvta.to.shared.u64 t, %1; cvt.u32.u64 %0, t; }"
        : "=r"(a) : "l"(p));
    return a;
}
__device__ __forceinline__ void cpa16(uint32_t dst, const void* src) {
    asm volatile("cp.async.ca.shared.global [%0], [%1], 16;" :: "r"(dst), "l"(src));
}
#define CP_COMMIT() asm volatile("cp.async.commit_group;" ::: "memory")
#define CP_WAIT1()  asm volatile("cp.async.wait_group 1;" ::: "memory")
#define CP_WAIT0()  asm volatile("cp.async.wait_group 0;" ::: "memory")

__device__ __forceinline__ void store_split2(float* b, size_t idx, float v0, float v1) {
    float h0 = tf32r(v0), l0 = tf32r(v0 - h0);
    float h1 = tf32r(v1), l1 = tf32r(v1 - h1);
    *(float4*)(b + idx * 2) = make_float4(h0, l0, h1, l1);
}

// ---------------------------------------------------------------------------
// Split kernel: float4 src -> two float4 of (hi,lo,hi,lo)
// ---------------------------------------------------------------------------
__global__ __launch_bounds__(256) void split2_kernel(
    const float4* __restrict__ src, float4* __restrict__ dst, int n4)
{
    int i = blockIdx.x * blockDim.x + threadIdx.x;
    if (i < n4) {
        float4 v = src[i];
        float h0 = tf32r(v.x), h1 = tf32r(v.y), h2 = tf32r(v.z), h3 = tf32r(v.w);
        dst[2*i]   = make_float4(h0, tf32r(v.x - h0), h1, tf32r(v.y - h1));
        dst[2*i+1] = make_float4(h2, tf32r(v.z - h2), h3, tf32r(v.w - h3));
    }
}

// ===========================================================================
// GEMM mainloop: acc (warp 64x32) = A2[m0:128,:1024] @ B2[n0:128,:1024]^T
// Inputs pre-split (hi,lo) float2. cp.async 2-stage pipeline, BK=16.
// 256 threads = 8 warps (2m x 4n). tf32x2 (3 mma passes).
// ===========================================================================
#define SAW 20   // float2 per smem row (16 data + 4 pad); 160B, 16B-aligned
#define GEMM_SMEM (2 * 2 * 128 * SAW * (int)sizeof(float2))   // 81920 B

__device__ __forceinline__ void gemm_ml2(
    const float2* __restrict__ A2, const float2* __restrict__ B2,
    int m0, int n0, float2* sA, float2* sB, uint32_t sAu, uint32_t sBu,
    float acc[4][4][4])
{
    const int tid = threadIdx.x, lane = tid & 31, wid = tid >> 5;
    const int gid = lane >> 2, tig = lane & 3;
    const int wm = (wid >> 2) * 64, wn = (wid & 3) * 32;

#define PREFETCH(IT, ST) do {                                                   \
    int _k0 = (IT) * 16;                                                        \
    _Pragma("unroll")                                                           \
    for (int s = 0; s < 4; ++s) {                                               \
        int c = tid + s * 256, row = c >> 3, q = (c & 7) * 2;                   \
        cpa16(sAu + (((ST) * 128 + row) * SAW + q) * 8,                         \
              A2 + (size_t)(m0 + row) * 1024 + _k0 + q);                        \
        cpa16(sBu + (((ST) * 128 + row) * SAW + q) * 8,                         \
              B2 + (size_t)(n0 + row) * 1024 + _k0 + q);                        \
    }                                                                           \
} while (0)

    PREFETCH(0, 0); CP_COMMIT();
    PREFETCH(1, 1); CP_COMMIT();

    for (int it = 0; it < 64; ++it) {
        const int st = it & 1;
        CP_WAIT1();
        __syncthreads();

        const float2* cA = sA + st * 128 * SAW;
        const float2* cB = sB + st * 128 * SAW;
#pragma unroll
        for (int ks = 0; ks < 2; ++ks) {
            uint32_t ah[4][4], al[4][4], bh[4][2], bl[4][2];
#pragma unroll
            for (int i = 0; i < 4; ++i) {
                int r = wm + i * 16 + gid, cc = ks * 8 + tig;
                float2 p0 = cA[r * SAW + cc],       p1 = cA[(r + 8) * SAW + cc];
                float2 p2 = cA[r * SAW + cc + 4],   p3 = cA[(r + 8) * SAW + cc + 4];
                ah[i][0] = __float_as_uint(p0.x); ah[i][1] = __float_as_uint(p1.x);
                ah[i][2] = __float_as_uint(p2.x); ah[i][3] = __float_as_uint(p3.x);
                al[i][0] = __float_as_uint(p0.y); al[i][1] = __float_as_uint(p1.y);
                al[i][2] = __float_as_uint(p2.y); al[i][3] = __float_as_uint(p3.y);
            }
#pragma unroll
            for (int j = 0; j < 4; ++j) {
                int r = wn + j * 8 + gid, cc = ks * 8 + tig;
                float2 p0 = cB[r * SAW + cc], p1 = cB[r * SAW + cc + 4];
                bh[j][0] = __float_as_uint(p0.x); bh[j][1] = __float_as_uint(p1.x);
                bl[j][0] = __float_as_uint(p0.y); bl[j][1] = __float_as_uint(p1.y);
            }
#pragma unroll
            for (int i = 0; i < 4; ++i)
#pragma unroll
                for (int j = 0; j < 4; ++j) {
                    mma8(acc[i][j], ah[i], bh[j]);
                    mma8(acc[i][j], ah[i], bl[j]);
                    mma8(acc[i][j], al[i], bh[j]);
                }
        }
        __syncthreads();
        if (it + 2 < 64) PREFETCH(it + 2, st);
        CP_COMMIT();
    }
#undef PREFETCH
}

// ---------------------------------------------------------------------------
// Kernel A: qkv GEMM + RoPE; writes pre-split q/k and tf32 v. Grid (24, 32).
// ---------------------------------------------------------------------------
__global__ __launch_bounds__(256) void qkv_mma_kernel(const int* __restrict__ pos)
{
    extern __shared__ char smraw[];
    float2* sA = (float2*)smraw;
    float2* sB = sA + 2 * 128 * SAW;
    uint32_t sAu = smem_u32(sA), sBu = smem_u32(sB);

    const int tid = threadIdx.x, lane = tid & 31, wid = tid >> 5;
    const int gid = lane >> 2, tig = lane & 3;
    const int wm = (wid >> 2) * 64, wn = (wid & 3) * 32;
    const int m0 = blockIdx.y * 128, n0 = blockIdx.x * 128;

    float acc[4][4][4];
#pragma unroll
    for (int i = 0; i < 4; ++i)
#pragma unroll
        for (int j = 0; j < 4; ++j)
#pragma unroll
            for (int c = 0; c < 4; ++c) acc[i][j][c] = 0.f;

    gemm_ml2(g_xi, g_wqi, m0, n0, sA, sB, sAu, sBu, acc);

    const int which = n0 >> 10;                       // 0=q 1=k 2=v
    const int h  = (((n0 & 1023) + wn) >> 6);
    const int db = wn & 32;
    const float sc = (which == 0) ? 0.125f : 1.f;
    float* dsf = (which == 0) ? (float*)g_qi : (float*)g_ki;

#pragma unroll
    for (int i = 0; i < 4; ++i) {
        int mA = m0 + wm + i * 16 + gid;
        int mB = mA + 8;
        size_t baseA = ((size_t)((mA >> 11) * 16 + h) * 2048 + (mA & 2047)) << 6;
        size_t baseB = ((size_t)((mB >> 11) * 16 + h) * 2048 + (mB & 2047)) << 6;
        if (which == 2) {
#pragma unroll
            for (int j = 0; j < 4; ++j) {
                int d = db + j * 8 + 2 * tig;
                *(float2*)(g_v + baseA + d) =
                    make_float2(tf32r(acc[i][j][0]), tf32r(acc[i][j][1]));
                *(float2*)(g_v + baseB + d) =
                    make_float2(tf32r(acc[i][j][2]), tf32r(acc[i][j][3]));
            }
        } else {
            int2 pA = ((const int2*)pos)[mA];
            int2 pB = ((const int2*)pos)[mB];
            float pa = db ? (float)pA.y : (float)pA.x;
            float pb = db ? (float)pB.y : (float)pB.x;
#pragma unroll
            for (int j = 0; j < 2; ++j) {
                int dd = j * 8 + 2 * tig;
                float s0a,c0a,s1a,c1a,s0b,c0b,s1b,c1b;
                sincosf(pa * c_invf[dd],     &s0a, &c0a);
                sincosf(pa * c_invf[dd + 1], &s1a, &c1a);
                sincosf(pb * c_invf[dd],     &s0b, &c0b);
                sincosf(pb * c_invf[dd + 1], &s1b, &c1b);
                float y10 = acc[i][j][0], y20 = acc[i][j+2][0];
                float y11 = acc[i][j][1], y21 = acc[i][j+2][1];
                store_split2(dsf, baseA + db + dd,
                             (y10*c0a - y20*s0a)*sc, (y11*c1a - y21*s1a)*sc);
                store_split2(dsf, baseA + db + dd + 16,
                             (y10*s0a + y20*c0a)*sc, (y11*s1a + y21*c1a)*sc);
                float z10 = acc[i][j][2], z20 = acc[i][j+2][2];
                float z11 = acc[i][j][3], z21 = acc[i][j+2][3];
                store_split2(dsf, baseB + db + dd,
                             (z10*c0b - z20*s0b)*sc, (z11*c1b - z21*s1b)*sc);
                store_split2(dsf, baseB + db + dd + 16,
                             (z10*s0b + z20*c0b)*sc, (z11*s1b + z21*c1b)*sc);
            }
        }
    }
}

// ---------------------------------------------------------------------------
// Kernel C: out = ao @ proj_w^T + bias. Grid (8, 32).
// ---------------------------------------------------------------------------
__global__ __launch_bounds__(256) void proj_mma_kernel(
    const float* __restrict__ bias, float* __restrict__ out)
{
    extern __shared__ char smraw[];
    float2* sA = (float2*)smraw;
    float2* sB = sA + 2 * 128 * SAW;
    uint32_t sAu = smem_u32(sA), sBu = smem_u32(sB);

    const int tid = threadIdx.x, lane = tid & 31, wid = tid >> 5;
    const int gid = lane >> 2, tig = lane & 3;
    const int wm = (wid >> 2) * 64, wn = (wid & 3) * 32;
    const int m0 = blockIdx.y * 128, n0 = blockIdx.x * 128;

    float acc[4][4][4];
#pragma unroll
    for (int i = 0; i < 4; ++i)
#pragma unroll
        for (int j = 0; j < 4; ++j)
#pragma unroll
            for (int c = 0; c < 4; ++c) acc[i][j][c] = 0.f;

    gemm_ml2(g_aoi, g_wpi, m0, n0, sA, sB, sAu, sBu, acc);

#pragma unroll
    for (int i = 0; i < 4; ++i) {
        int mA = m0 + wm + i * 16 + gid;
#pragma unroll
        for (int j = 0; j < 4; ++j) {
            int n = n0 + wn + j * 8 + 2 * tig;
            float b0 = bias[n], b1 = bias[n + 1];
            *(float2*)(out + (size_t)mA * 1024 + n) =
                make_float2(acc[i][j][0] + b0, acc[i][j][1] + b1);
            *(float2*)(out + (size_t)(mA + 8) * 1024 + n) =
                make_float2(acc[i][j][2] + b0, acc[i][j][3] + b1);
        }
    }
}

// ---------------------------------------------------------------------------
// Kernel B: flash attention, pre-split Q/K, tf32 V, cp.async tile loads.
// 128 threads, Tq=64, Tkv=64. Writes pre-split attn-out for proj.
// ---------------------------------------------------------------------------
#define SQF 68   // float2 stride for Q/K rows
#define SV  72
#define SP  68
#define ATTN_SMEM ((2*64*SQF)*8 + (64*SV)*4 + (4*16*SP)*4)

__global__ __launch_bounds__(128) void attn_mma_kernel()
{
    extern __shared__ char smraw[];
    float2* sQ = (float2*)smraw;             // 64 x SQF
    float2* sK = sQ + 64 * SQF;              // 64 x SQF
    float*  sV = (float*)(sK + 64 * SQF);    // 64 x SV
    float*  sP = sV + 64 * SV;               // 4 x 16 x SP
    uint32_t sQu = smem_u32(sQ), sKu = smem_u32(sK), sVu = smem_u32(sV);

    const int tid = threadIdx.x, lane = tid & 31, wid = tid >> 5;
    const int gid = lane >> 2, tig = lane & 3;
    const int bh = blockIdx.y, q0 = blockIdx.x * 64;

    const float2* Qg = g_qi + ((size_t)bh * N_ + q0) * DH_;
    const float2* Kg = g_ki + (size_t)bh * N_ * DH_;
    const float*  Vg = g_v  + (size_t)bh * N_ * DH_;

    // Q tile (pre-scaled & pre-split): 64 rows x 64 float2, 16B = 2 float2/cp
#pragma unroll
    for (int s = 0; s < 16; ++s) {
        int c = tid + s * 128, row = c >> 5, q = (c & 31) * 2;
        cpa16(sQu + (row * SQF + q) * 8, Qg + (size_t)row * 64 + q);
    }
    CP_COMMIT();

    float o[8][4];
#pragma unroll
    for (int j = 0; j < 8; ++j)
#pragma unroll
        for (int c = 0; c < 4; ++c) o[j][c] = 0.f;
    float m0r = -1e30f, m1r = -1e30f, l0 = 0.f, l1 = 0.f;

    float* wP = sP + wid * 16 * SP;
    const uint32_t* uP = (const uint32_t*)wP;
    const uint32_t* uV = (const uint32_t*)sV;

    for (int kv0 = 0; kv0 < N_; kv0 += 64) {
        __syncthreads();
#pragma unroll
        for (int s = 0; s < 16; ++s) {
            int c = tid + s * 128, row = c >> 5, q = (c & 31) * 2;
            cpa16(sKu + (row * SQF + q) * 8, Kg + (size_t)(kv0 + row) * 64 + q);
        }
        // V tile: 64 rows x 64 floats, 16B = 4 floats/cp -> 1024 cps: row=c>>4
#pragma unroll
        for (int s = 0; s < 8; ++s) {
            int c = tid + s * 128, row = c >> 4, q = (c & 15) * 4;
            cpa16(sVu + (row * SV + q) * 4, Vg + (size_t)(kv0 + row) * 64 + q);
        }
        CP_COMMIT();
        CP_WAIT0();
        __syncthreads();

        // S = (Q/8) K^T, tf32x2
        float s8[8][4];
#pragma unroll
        for (int j = 0; j < 8; ++j)
#pragma unroll
            for (int c = 0; c < 4; ++c) s8[j][c] = 0.f;
#pragma unroll
        for (int kc = 0; kc < 8; ++kc) {
            int ba = (wid * 16 + gid) * SQF + kc * 8 + tig;
            float2 p0 = sQ[ba],     p1 = sQ[ba + 8 * SQF];
            float2 p2 = sQ[ba + 4], p3 = sQ[ba + 8 * SQF + 4];
            uint32_t ah[4] = { __float_as_uint(p0.x), __float_as_uint(p1.x),
                               __float_as_uint(p2.x), __float_as_uint(p3.x) };
            uint32_t al[4] = { __float_as_uint(p0.y), __float_as_uint(p1.y),
                               __float_as_uint(p2.y), __float_as_uint(p3.y) };
#pragma unroll
            for (int j = 0; j < 8; ++j) {
                int bb = (j * 8 + gid) * SQF + kc * 8 + tig;
                float2 k0 = sK[bb], k1 = sK[bb + 4];
                uint32_t kh2[2] = { __float_as_uint(k0.x), __float_as_uint(k1.x) };
                uint32_t kl2[2] = { __float_as_uint(k0.y), __float_as_uint(k1.y) };
                mma8(s8[j], ah, kh2);
                mma8(s8[j], ah, kl2);
                mma8(s8[j], al, kh2);
            }
        }

        // online softmax (rows gid, gid+8)
        float mx0 = -1e30f, mx1 = -1e30f;
#pragma unroll
        for (int j = 0; j < 8; ++j) {
            mx0 = fmaxf(mx0, fmaxf(s8[j][0], s8[j][1]));
            mx1 = fmaxf(mx1, fmaxf(s8[j][2], s8[j][3]));
        }
        mx0 = fmaxf(mx0, __shfl_xor_sync(0xffffffffu, mx0, 1));
        mx0 = fmaxf(mx0, __shfl_xor_sync(0xffffffffu, mx0, 2));
        mx1 = fmaxf(mx1, __shfl_xor_sync(0xffffffffu, mx1, 1));
        mx1 = fmaxf(mx1, __shfl_xor_sync(0xffffffffu, mx1, 2));
        float mn0 = fmaxf(m0r, mx0), mn1 = fmaxf(m1r, mx1);
        float al0 = __expf(m0r - mn0), al1 = __expf(m1r - mn1);
        m0r = mn0; m1r = mn1;
        float sum0 = 0.f, sum1 = 0.f;
#pragma unroll
        for (int j = 0; j < 8; ++j) {
            s8[j][0] = __expf(s8[j][0] - mn0); sum0 += s8[j][0];
            s8[j][1] = __expf(s8[j][1] - mn0); sum0 += s8[j][1];
            s8[j][2] = __expf(s8[j][2] - mn1); sum1 += s8[j][2];
            s8[j][3] = __expf(s8[j][3] - mn1); sum1 += s8[j][3];
        }
        sum0 += __shfl_xor_sync(0xffffffffu, sum0, 1);
        sum0 += __shfl_xor_sync(0xffffffffu, sum0, 2);
        sum1 += __shfl_xor_sync(0xffffffffu, sum1, 1);
        sum1 += __shfl_xor_sync(0xffffffffu, sum1, 2);
        l0 = l0 * al0 + sum0;
        l1 = l1 * al1 + sum1;
#pragma unroll
        for (int j = 0; j < 8; ++j) {
            o[j][0] *= al0; o[j][1] *= al0;
            o[j][2] *= al1; o[j][3] *= al1;
        }

        // stash P (tf32-rounded)
#pragma unroll
        for (int j = 0; j < 8; ++j) {
            *(float2*)(wP + gid * SP + j * 8 + 2 * tig) =
                make_float2(tf32r(s8[j][0]), tf32r(s8[j][1]));
            *(float2*)(wP + (gid + 8) * SP + j * 8 + 2 * tig) =
                make_float2(tf32r(s8[j][2]), tf32r(s8[j][3]));
        }
        __syncwarp();

        // O += P V (single tf32)
#pragma unroll
        for (int kc = 0; kc < 8; ++kc) {
            uint32_t pa[4];
            int pb = gid * SP + kc * 8 + tig;
            pa[0] = uP[pb];     pa[1] = uP[pb + 8 * SP];
            pa[2] = uP[pb + 4]; pa[3] = uP[pb + 8 * SP + 4];
#pragma unroll
            for (int j = 0; j < 8; ++j) {
                int vb = (kc * 8 + tig) * SV + j * 8 + gid;
                uint32_t vv[2] = { uV[vb], uV[vb + 4 * SV] };
                mma8(o[j], pa, vv);
            }
        }
        __syncwarp();
    }

    const float linv0 = 1.f / l0, linv1 = 1.f / l1;
    const int b = bh >> 4, h = bh & 15;
    const int tok0 = q0 + wid * 16 + gid, tok1 = tok0 + 8;
    size_t base0 = ((size_t)(b * 2048 + tok0) * 16 + h) << 6;
    size_t base1 = ((size_t)(b * 2048 + tok1) * 16 + h) << 6;
    float* ga = (float*)g_aoi;
#pragma unroll
    for (int j = 0; j < 8; ++j) {
        int d = j * 8 + 2 * tig;
        store_split2(ga, base0 + d, o[j][0] * linv0, o[j][1] * linv0);
        store_split2(ga, base1 + d, o[j][2] * linv1, o[j][3] * linv1);
    }
}

// ---------------------------------------------------------------------------
extern "C" void kernel_launch(void* const* d_in, const int* in_sizes, int n_in,
                              void* d_out, int out_size)
{
    const float* x      = (const float*)d_in[0];
    const int*   pos    = (const int*)  d_in[1];
    const float* qkv_w  = (const float*)d_in[2];
    const float* proj_w = (const float*)d_in[3];
    const float* proj_b = (const float*)d_in[4];
    float*       out    = (float*)d_out;

    float2 *xi, *wqi, *wpi;
    cudaGetSymbolAddress((void**)&xi,  g_xi);
    cudaGetSymbolAddress((void**)&wqi, g_wqi);
    cudaGetSymbolAddress((void**)&wpi, g_wpi);

    // Pre-split (bandwidth-bound, ~15us total)
    split2_kernel<<<(M_*C_/4 + 255)/256, 256>>>((const float4*)x,      (float4*)xi,  M_*C_/4);
    split2_kernel<<<(3*C_*C_/4 + 255)/256, 256>>>((const float4*)qkv_w, (float4*)wqi, 3*C_*C_/4);
    split2_kernel<<<(C_*C_/4 + 255)/256, 256>>>((const float4*)proj_w, (float4*)wpi, C_*C_/4);

    cudaFuncSetAttribute(qkv_mma_kernel,
                         cudaFuncAttributeMaxDynamicSharedMemorySize, GEMM_SMEM);
    cudaFuncSetAttribute(proj_mma_kernel,
                         cudaFuncAttributeMaxDynamicSharedMemorySize, GEMM_SMEM);
    cudaFuncSetAttribute(attn_mma_kernel,
                         cudaFuncAttributeMaxDynamicSharedMemorySize, ATTN_SMEM);

    qkv_mma_kernel<<<dim3(24, 32), 256, GEMM_SMEM>>>(pos);
    attn_mma_kernel<<<dim3(32, 32), 128, ATTN_SMEM>>>();
    proj_mma_kernel<<<dim3(8, 32), 256, GEMM_SMEM>>>(proj_b, out);
}

// round 6
// speedup vs baseline: 1.0934x; 1.0934x over previous
#include <cuda_runtime.h>
#include <math.h>
#include <stdint.h>

#define B_  2
#define N_  2048
#define C_  1024
#define H_  16
#define DH_ 64
#define M_  (B_*N_)
#define BH_ (B_*H_)

__device__ float g_q [BH_ * N_ * DH_];   // rope'd q (raw f32)
__device__ float g_k [BH_ * N_ * DH_];   // rope'd k (raw f32)
__device__ float g_v [BH_ * N_ * DH_];   // v, tf32-rounded
__device__ float g_ao[M_ * C_];          // attention output (raw f32)

__constant__ float c_invf[16] = {
    1.0f, 0.7498942093324559f, 0.5623413251903491f, 0.4216965034285822f,
    0.31622776601683794f, 0.23713737056616552f, 0.1778279410038923f,
    0.13335214321633237f, 0.1f, 0.07498942093324558f, 0.05623413251903491f,
    0.04216965034285822f, 0.031622776601683794f, 0.023713737056616552f,
    0.01778279410038923f, 0.013335214321633237f
};

__device__ __forceinline__ float tf32r(float x) {
    uint32_t u;
    asm("cvt.rna.tf32.f32 %0, %1;" : "=r"(u) : "f"(x));
    return __uint_as_float(u);
}
__device__ __forceinline__ void mma8(float* d, const uint32_t* a, const uint32_t* b) {
    asm volatile(
        "mma.sync.aligned.m16n8k8.row.col.f32.tf32.tf32.f32 "
        "{%0,%1,%2,%3}, {%4,%5,%6,%7}, {%8,%9}, {%0,%1,%2,%3};"
        : "+f"(d[0]), "+f"(d[1]), "+f"(d[2]), "+f"(d[3])
        : "r"(a[0]), "r"(a[1]), "r"(a[2]), "r"(a[3]), "r"(b[0]), "r"(b[1]));
}
__device__ __forceinline__ uint32_t smem_u32(const void* p) {
    uint32_t a;
    asm("{ .reg .u64 t; cvta.to.shared.u64 t, %1; cvt.u32.u64 %0, t; }"
        : "=r"(a) : "l"(p));
    return a;
}
__device__ __forceinline__ void cpa16(uint32_t dst, const void* src) {
    asm volatile("cp.async.ca.shared.global [%0], [%1], 16;" :: "r"(dst), "l"(src));
}
#define CP_COMMIT() asm volatile("cp.async.commit_group;" ::: "memory")
#define CP_WAIT0()  asm volatile("cp.async.wait_group 0;" ::: "memory")
#define CP_WAIT1()  asm volatile("cp.async.wait_group 1;" ::: "memory")

// ===========================================================================
// GEMM mainloop: warp 64x32 tile of D[128x128] = A[m0:128,:1024] @ B[n0:128,:1024]^T
// Raw f32 staged by cp.async (self-staged, double-buffered), split hi/lo at the
// smem boundary once per CTA. tf32x2 (3 mma passes). 256 thr = 8 warps (2m x 4n).
// ===========================================================================
#define SA 20
#define GEMM_SMEM ((4 * 128 * SA + 2 * 2048 * 2) * (int)sizeof(float))  // 73728

__device__ __forceinline__ void gemm_ml(
    const float* __restrict__ A, const float* __restrict__ Bw,
    int m0, int n0, float* smf, float acc[4][4][4])
{
    float* sAh  = smf;
    float* sAl  = sAh + 128 * SA;
    float* sBh  = sAl + 128 * SA;
    float* sBl  = sBh + 128 * SA;
    float* rawA = sBl + 128 * SA;         // 2 stages x 128x16
    float* rawB = rawA + 2 * 2048;
    const uint32_t rawAu = smem_u32(rawA), rawBu = smem_u32(rawB);

    const int tid = threadIdx.x, lane = tid & 31, wid = tid >> 5;
    const int gid = lane >> 2, tig = lane & 3;
    const int wm = (wid >> 2) * 64, wn = (wid & 3) * 32;
    const int r0 = tid >> 2, r1 = r0 + 64, q0f = (tid & 3) * 4;
    const uint32_t *uAh = (const uint32_t*)sAh, *uAl = (const uint32_t*)sAl;
    const uint32_t *uBh = (const uint32_t*)sBh, *uBl = (const uint32_t*)sBl;

#define GPREF(IT, ST) do {                                                      \
    int _k0 = (IT) * 16;                                                        \
    cpa16(rawAu + (((ST)*2048) + r0*16 + q0f)*4, A  + (size_t)(m0+r0)*1024 + _k0 + q0f); \
    cpa16(rawAu + (((ST)*2048) + r1*16 + q0f)*4, A  + (size_t)(m0+r1)*1024 + _k0 + q0f); \
    cpa16(rawBu + (((ST)*2048) + r0*16 + q0f)*4, Bw + (size_t)(n0+r0)*1024 + _k0 + q0f); \
    cpa16(rawBu + (((ST)*2048) + r1*16 + q0f)*4, Bw + (size_t)(n0+r1)*1024 + _k0 + q0f); \
} while (0)

    GPREF(0, 0); CP_COMMIT();

    for (int it = 0; it < 64; ++it) {
        const int st = it & 1;
        CP_WAIT0();                 // own staged chunks for tile `it` arrived
        if (it) __syncthreads();    // all warps done computing previous tile

        // split raw -> (hi,lo) smem; each thread handles exactly what it staged
        const float* cRA = rawA + st * 2048;
        const float* cRB = rawB + st * 2048;
#pragma unroll
        for (int s = 0; s < 2; ++s) {
            int row = s ? r1 : r0;
            float4 v = *(const float4*)(cRA + row * 16 + q0f);
            float4 vh, vl;
            vh.x = tf32r(v.x); vl.x = tf32r(v.x - vh.x);
            vh.y = tf32r(v.y); vl.y = tf32r(v.y - vh.y);
            vh.z = tf32r(v.z); vl.z = tf32r(v.z - vh.z);
            vh.w = tf32r(v.w); vl.w = tf32r(v.w - vh.w);
            *(float4*)(sAh + row * SA + q0f) = vh;
            *(float4*)(sAl + row * SA + q0f) = vl;
            v = *(const float4*)(cRB + row * 16 + q0f);
            vh.x = tf32r(v.x); vl.x = tf32r(v.x - vh.x);
            vh.y = tf32r(v.y); vl.y = tf32r(v.y - vh.y);
            vh.z = tf32r(v.z); vl.z = tf32r(v.z - vh.z);
            vh.w = tf32r(v.w); vl.w = tf32r(v.w - vh.w);
            *(float4*)(sBh + row * SA + q0f) = vh;
            *(float4*)(sBl + row * SA + q0f) = vl;
        }
        __syncthreads();
        if (it + 1 < 64) GPREF(it + 1, st ^ 1);   // issue BEFORE compute
        CP_COMMIT();

#pragma unroll
        for (int ks = 0; ks < 2; ++ks) {
            uint32_t ah[4][4], al[4][4], bh[4][2], bl[4][2];
#pragma unroll
            for (int i = 0; i < 4; ++i) {
                int ba = (wm + i * 16 + gid) * SA + ks * 8 + tig;
                ah[i][0] = uAh[ba];            ah[i][1] = uAh[ba + 8 * SA];
                ah[i][2] = uAh[ba + 4];        ah[i][3] = uAh[ba + 8 * SA + 4];
                al[i][0] = uAl[ba];            al[i][1] = uAl[ba + 8 * SA];
                al[i][2] = uAl[ba + 4];        al[i][3] = uAl[ba + 8 * SA + 4];
            }
#pragma unroll
            for (int j = 0; j < 4; ++j) {
                int bb = (wn + j * 8 + gid) * SA + ks * 8 + tig;
                bh[j][0] = uBh[bb]; bh[j][1] = uBh[bb + 4];
                bl[j][0] = uBl[bb]; bl[j][1] = uBl[bb + 4];
            }
#pragma unroll
            for (int i = 0; i < 4; ++i)
#pragma unroll
                for (int j = 0; j < 4; ++j) {
                    mma8(acc[i][j], ah[i], bh[j]);
                    mma8(acc[i][j], ah[i], bl[j]);
                    mma8(acc[i][j], al[i], bh[j]);
                }
        }
    }
#undef GPREF
}

// ---------------------------------------------------------------------------
// Kernel A: qkv GEMM + RoPE; v stored tf32-rounded. Grid (24, 32), 256 thr.
// ---------------------------------------------------------------------------
__global__ __launch_bounds__(256) void qkv_mma_kernel(
    const float* __restrict__ x, const float* __restrict__ w,
    const int* __restrict__ pos)
{
    extern __shared__ float smf[];
    const int tid = threadIdx.x, lane = tid & 31, wid = tid >> 5;
    const int gid = lane >> 2, tig = lane & 3;
    const int wm = (wid >> 2) * 64, wn = (wid & 3) * 32;
    const int m0 = blockIdx.y * 128, n0 = blockIdx.x * 128;

    float acc[4][4][4];
#pragma unroll
    for (int i = 0; i < 4; ++i)
#pragma unroll
        for (int j = 0; j < 4; ++j)
#pragma unroll
            for (int c = 0; c < 4; ++c) acc[i][j][c] = 0.f;

    gemm_ml(x, w, m0, n0, smf, acc);

    const int which = n0 >> 10;                       // 0=q 1=k 2=v
    const int h  = (((n0 & 1023) + wn) >> 6);
    const int db = wn & 32;
    float* dst = (which == 0) ? g_q : (which == 1) ? g_k : g_v;

#pragma unroll
    for (int i = 0; i < 4; ++i) {
        int mA = m0 + wm + i * 16 + gid;
        int mB = mA + 8;
        float* oA = dst + (((size_t)((mA >> 11) * 16 + h) * 2048 + (mA & 2047)) << 6);
        float* oB = dst + (((size_t)((mB >> 11) * 16 + h) * 2048 + (mB & 2047)) << 6);
        if (which == 2) {
#pragma unroll
            for (int j = 0; j < 4; ++j) {
                int d = db + j * 8 + 2 * tig;
                *(float2*)(oA + d) = make_float2(tf32r(acc[i][j][0]), tf32r(acc[i][j][1]));
                *(float2*)(oB + d) = make_float2(tf32r(acc[i][j][2]), tf32r(acc[i][j][3]));
            }
        } else {
            int2 pA = ((const int2*)pos)[mA];
            int2 pB = ((const int2*)pos)[mB];
            float pa = db ? (float)pA.y : (float)pA.x;
            float pb = db ? (float)pB.y : (float)pB.x;
#pragma unroll
            for (int j = 0; j < 2; ++j) {
                int dd = j * 8 + 2 * tig;
                float s0a,c0a,s1a,c1a,s0b,c0b,s1b,c1b;
                sincosf(pa * c_invf[dd],     &s0a, &c0a);
                sincosf(pa * c_invf[dd + 1], &s1a, &c1a);
                sincosf(pb * c_invf[dd],     &s0b, &c0b);
                sincosf(pb * c_invf[dd + 1], &s1b, &c1b);
                float y10 = acc[i][j][0], y20 = acc[i][j+2][0];
                float y11 = acc[i][j][1], y21 = acc[i][j+2][1];
                *(float2*)(oA + db + dd)      = make_float2(y10*c0a - y20*s0a, y11*c1a - y21*s1a);
                *(float2*)(oA + db + dd + 16) = make_float2(y10*s0a + y20*c0a, y11*s1a + y21*c1a);
                float z10 = acc[i][j][2], z20 = acc[i][j+2][2];
                float z11 = acc[i][j][3], z21 = acc[i][j+2][3];
                *(float2*)(oB + db + dd)      = make_float2(z10*c0b - z20*s0b, z11*c1b - z21*s1b);
                *(float2*)(oB + db + dd + 16) = make_float2(z10*s0b + z20*c0b, z11*s1b + z21*c1b);
            }
        }
    }
}

// ---------------------------------------------------------------------------
// Kernel C: out = g_ao @ proj_w^T + bias. Grid (8, 32), 256 thr.
// ---------------------------------------------------------------------------
__global__ __launch_bounds__(256) void proj_mma_kernel(
    const float* __restrict__ w, const float* __restrict__ bias,
    float* __restrict__ out)
{
    extern __shared__ float smf[];
    const int tid = threadIdx.x, lane = tid & 31, wid = tid >> 5;
    const int gid = lane >> 2, tig = lane & 3;
    const int wm = (wid >> 2) * 64, wn = (wid & 3) * 32;
    const int m0 = blockIdx.y * 128, n0 = blockIdx.x * 128;

    float acc[4][4][4];
#pragma unroll
    for (int i = 0; i < 4; ++i)
#pragma unroll
        for (int j = 0; j < 4; ++j)
#pragma unroll
            for (int c = 0; c < 4; ++c) acc[i][j][c] = 0.f;

    gemm_ml(g_ao, w, m0, n0, smf, acc);

#pragma unroll
    for (int i = 0; i < 4; ++i) {
        int mA = m0 + wm + i * 16 + gid;
#pragma unroll
        for (int j = 0; j < 4; ++j) {
            int n = n0 + wn + j * 8 + 2 * tig;
            float b0 = bias[n], b1 = bias[n + 1];
            *(float2*)(out + (size_t)mA * 1024 + n) =
                make_float2(acc[i][j][0] + b0, acc[i][j][1] + b1);
            *(float2*)(out + (size_t)(mA + 8) * 1024 + n) =
                make_float2(acc[i][j][2] + b0, acc[i][j][3] + b1);
        }
    }
}

// ---------------------------------------------------------------------------
// Kernel B: flash attention. Q fragments in registers; K self-staged cp.async
// double-buffer + hi/lo split; V cp.async direct into sV (issued before QK^T).
// 128 threads, Tq=Tkv=64. QK tf32x2, PV tf32 (V pre-rounded in gmem).
// ---------------------------------------------------------------------------
#define SKS 68
#define SVS 72
#define SPS 68
// rawK[2][4096] | sKh[64*68] | sKl[64*68] | sV[64*72] | sP[4*16*68]
#define ATTN_SMEM ((2*4096 + 2*64*SKS + 64*SVS + 4*16*SPS) * (int)sizeof(float))

__global__ __launch_bounds__(128) void attn_mma_kernel()
{
    extern __shared__ float smf[];
    float* rawK = smf;
    float* sKh  = rawK + 2 * 4096;
    float* sKl  = sKh + 64 * SKS;
    float* sV   = sKl + 64 * SKS;
    float* sP   = sV + 64 * SVS;             // also Q staging before the loop
    const uint32_t rawKu = smem_u32(rawK), sVu = smem_u32(sV);

    const int tid = threadIdx.x, lane = tid & 31, wid = tid >> 5;
    const int gid = lane >> 2, tig = lane & 3;
    const int bh = blockIdx.y, q0 = blockIdx.x * 64;

    const float* Qg = g_q + ((size_t)bh * N_ + q0) * DH_;
    const float* Kg = g_k + (size_t)bh * N_ * DH_;
    const float* Vg = g_v + (size_t)bh * N_ * DH_;

    // ---- stage Q into sP, extract scaled+split fragments to registers ----
#pragma unroll
    for (int s = 0; s < 8; ++s) {
        int c = tid + s * 128, row = c >> 4, q = (c & 15) * 4;
        *(float4*)(sP + row * SPS + q) = *(const float4*)(Qg + (size_t)row * 64 + q);
    }
    __syncthreads();
    uint32_t qh[8][4], ql[8][4];
#pragma unroll
    for (int kc = 0; kc < 8; ++kc)
#pragma unroll
        for (int e = 0; e < 4; ++e) {
            int row = wid * 16 + gid + ((e & 1) ? 8 : 0);
            int col = kc * 8 + tig + ((e & 2) ? 4 : 0);
            float v = sP[row * SPS + col] * 0.125f;
            float hh = tf32r(v);
            qh[kc][e] = __float_as_uint(hh);
            ql[kc][e] = __float_as_uint(tf32r(v - hh));
        }
    __syncthreads();    // sP free for P use; rawK free for K staging

#define KPREF(KV0, ST) do {                                                     \
    _Pragma("unroll")                                                           \
    for (int s = 0; s < 8; ++s) {                                               \
        int c = tid + s * 128, row = c >> 4, q = (c & 15) * 4;                  \
        cpa16(rawKu + (((ST)*4096) + row*64 + q)*4,                             \
              Kg + (size_t)((KV0) + row) * 64 + q);                             \
    }                                                                           \
} while (0)

    KPREF(0, 0); CP_COMMIT();

    float o[8][4];
#pragma unroll
    for (int j = 0; j < 8; ++j)
#pragma unroll
        for (int c = 0; c < 4; ++c) o[j][c] = 0.f;
    float m0r = -1e30f, m1r = -1e30f, l0 = 0.f, l1 = 0.f;

    float* wP = sP + wid * 16 * SPS;
    const uint32_t* uP  = (const uint32_t*)wP;
    const uint32_t* uV  = (const uint32_t*)sV;
    const uint32_t* uKh = (const uint32_t*)sKh;
    const uint32_t* uKl = (const uint32_t*)sKl;

    for (int it = 0; it < 32; ++it) {
        const int kv0 = it * 64, st = it & 1;
        CP_WAIT0();              // K(it) staged (own chunks); drains everything prior
        __syncthreads();         // all warps done with previous iteration (sV/sP/sK free)

        // V(it): direct cp.async into sV — lands during QK compute
#pragma unroll
        for (int s = 0; s < 8; ++s) {
            int c = tid + s * 128, row = c >> 4, q = (c & 15) * 4;
            cpa16(sVu + (row * SVS + q) * 4, Vg + (size_t)(kv0 + row) * 64 + q);
        }
        CP_COMMIT();             // group V_it  (committed BEFORE K_{it+1})

        // split K(it) raw -> (hi,lo)
        const float* cRK = rawK + st * 4096;
#pragma unroll
        for (int s = 0; s < 8; ++s) {
            int c = tid + s * 128, row = c >> 4, q = (c & 15) * 4;
            float4 v = *(const float4*)(cRK + row * 64 + q);
            float4 vh, vl;
            vh.x = tf32r(v.x); vl.x = tf32r(v.x - vh.x);
            vh.y = tf32r(v.y); vl.y = tf32r(v.y - vh.y);
            vh.z = tf32r(v.z); vl.z = tf32r(v.z - vh.z);
            vh.w = tf32r(v.w); vl.w = tf32r(v.w - vh.w);
            *(float4*)(sKh + row * SKS + q) = vh;
            *(float4*)(sKl + row * SKS + q) = vl;
        }
        if (it + 1 < 32) KPREF(kv0 + 64, st ^ 1);
        CP_COMMIT();             // group K_{it+1} (possibly empty)
        __syncthreads();         // sKh/sKl visible

        // S = (Q/8) K^T, tf32x2
        float s8[8][4];
#pragma unroll
        for (int j = 0; j < 8; ++j)
#pragma unroll
            for (int c = 0; c < 4; ++c) s8[j][c] = 0.f;
#pragma unroll
        for (int kc = 0; kc < 8; ++kc) {
#pragma unroll
            for (int j = 0; j < 8; ++j) {
                int bb = (j * 8 + gid) * SKS + kc * 8 + tig;
                uint32_t kh2[2] = { uKh[bb], uKh[bb + 4] };
                uint32_t kl2[2] = { uKl[bb], uKl[bb + 4] };
                mma8(s8[j], qh[kc], kh2);
                mma8(s8[j], qh[kc], kl2);
                mma8(s8[j], ql[kc], kh2);
            }
        }

        CP_WAIT1();              // V_it complete (K_{it+1} may stay in flight)
        __syncthreads();         // everyone's V chunks visible

        // online softmax (rows gid, gid+8)
        float mx0 = -1e30f, mx1 = -1e30f;
#pragma unroll
        for (int j = 0; j < 8; ++j) {
            mx0 = fmaxf(mx0, fmaxf(s8[j][0], s8[j][1]));
            mx1 = fmaxf(mx1, fmaxf(s8[j][2], s8[j][3]));
        }
        mx0 = fmaxf(mx0, __shfl_xor_sync(0xffffffffu, mx0, 1));
        mx0 = fmaxf(mx0, __shfl_xor_sync(0xffffffffu, mx0, 2));
        mx1 = fmaxf(mx1, __shfl_xor_sync(0xffffffffu, mx1, 1));
        mx1 = fmaxf(mx1, __shfl_xor_sync(0xffffffffu, mx1, 2));
        float mn0 = fmaxf(m0r, mx0), mn1 = fmaxf(m1r, mx1);
        float al0 = __expf(m0r - mn0), al1 = __expf(m1r - mn1);
        m0r = mn0; m1r = mn1;
        float sum0 = 0.f, sum1 = 0.f;
#pragma unroll
        for (int j = 0; j < 8; ++j) {
            s8[j][0] = __expf(s8[j][0] - mn0); sum0 += s8[j][0];
            s8[j][1] = __expf(s8[j][1] - mn0); sum0 += s8[j][1];
            s8[j][2] = __expf(s8[j][2] - mn1); sum1 += s8[j][2];
            s8[j][3] = __expf(s8[j][3] - mn1); sum1 += s8[j][3];
        }
        sum0 += __shfl_xor_sync(0xffffffffu, sum0, 1);
        sum0 += __shfl_xor_sync(0xffffffffu, sum0, 2);
        sum1 += __shfl_xor_sync(0xffffffffu, sum1, 1);
        sum1 += __shfl_xor_sync(0xffffffffu, sum1, 2);
        l0 = l0 * al0 + sum0;
        l1 = l1 * al1 + sum1;
#pragma unroll
        for (int j = 0; j < 8; ++j) {
            o[j][0] *= al0; o[j][1] *= al0;
            o[j][2] *= al1; o[j][3] *= al1;
        }

        // stash P (tf32-rounded) in per-warp smem
#pragma unroll
        for (int j = 0; j < 8; ++j) {
            *(float2*)(wP + gid * SPS + j * 8 + 2 * tig) =
                make_float2(tf32r(s8[j][0]), tf32r(s8[j][1]));
            *(float2*)(wP + (gid + 8) * SPS + j * 8 + 2 * tig) =
                make_float2(tf32r(s8[j][2]), tf32r(s8[j][3]));
        }
        __syncwarp();

        // O += P V (single tf32; V pre-rounded)
#pragma unroll
        for (int kc = 0; kc < 8; ++kc) {
            uint32_t pa[4];
            int pb = gid * SPS + kc * 8 + tig;
            pa[0] = uP[pb];     pa[1] = uP[pb + 8 * SPS];
            pa[2] = uP[pb + 4]; pa[3] = uP[pb + 8 * SPS + 4];
#pragma unroll
            for (int j = 0; j < 8; ++j) {
                int vb = (kc * 8 + tig) * SVS + j * 8 + gid;
                uint32_t vv[2] = { uV[vb], uV[vb + 4 * SVS] };
                mma8(o[j], pa, vv);
            }
        }
        __syncwarp();
    }
#undef KPREF

    const float linv0 = 1.f / l0, linv1 = 1.f / l1;
    const int b = bh >> 4, h = bh & 15;
    const int tok0 = q0 + wid * 16 + gid, tok1 = tok0 + 8;
    float* oA = g_ao + (((size_t)(b * 2048 + tok0) * 16 + h) << 6);
    float* oB = g_ao + (((size_t)(b * 2048 + tok1) * 16 + h) << 6);
#pragma unroll
    for (int j = 0; j < 8; ++j) {
        int d = j * 8 + 2 * tig;
        *(float2*)(oA + d) = make_float2(o[j][0] * linv0, o[j][1] * linv0);
        *(float2*)(oB + d) = make_float2(o[j][2] * linv1, o[j][3] * linv1);
    }
}

// ---------------------------------------------------------------------------
extern "C" void kernel_launch(void* const* d_in, const int* in_sizes, int n_in,
                              void* d_out, int out_size)
{
    const float* x      = (const float*)d_in[0];
    const int*   pos    = (const int*)  d_in[1];
    const float* qkv_w  = (const float*)d_in[2];
    const float* proj_w = (const float*)d_in[3];
    const float* proj_b = (const float*)d_in[4];
    float*       out    = (float*)d_out;

    cudaFuncSetAttribute(qkv_mma_kernel,
                         cudaFuncAttributeMaxDynamicSharedMemorySize, GEMM_SMEM);
    cudaFuncSetAttribute(proj_mma_kernel,
                         cudaFuncAttributeMaxDynamicSharedMemorySize, GEMM_SMEM);
    cudaFuncSetAttribute(attn_mma_kernel,
                         cudaFuncAttributeMaxDynamicSharedMemorySize, ATTN_SMEM);

    qkv_mma_kernel<<<dim3(24, 32), 256, GEMM_SMEM>>>(x, qkv_w, pos);
    attn_mma_kernel<<<dim3(32, 32), 128, ATTN_SMEM>>>();
    proj_mma_kernel<<<dim3(8, 32), 256, GEMM_SMEM>>>(proj_b ? proj_w : proj_w, proj_b, out);
}

// round 7
// speedup vs baseline: 1.9350x; 1.7698x over previous
#include <cuda_runtime.h>
#include <math.h>
#include <stdint.h>

#define B_  2
#define N_  2048
#define C_  1024
#define H_  16
#define DH_ 64
#define M_  (B_*N_)
#define BH_ (B_*H_)

// Packed bf16 (hi,lo) planes. u32 = {bf16 k_even | bf16 k_odd<<16}.
__device__ uint32_t g_xh [M_ * 512],      g_xl [M_ * 512];       // x
__device__ uint32_t g_wqh[3 * C_ * 512],  g_wql[3 * C_ * 512];   // qkv_w
__device__ uint32_t g_wph[C_ * 512],      g_wpl[C_ * 512];       // proj_w
__device__ uint32_t g_qh [BH_ * N_ * 32], g_ql [BH_ * N_ * 32];  // q (rope'd, /8)
__device__ uint32_t g_kh [BH_ * N_ * 32], g_kl [BH_ * N_ * 32];  // k (rope'd)
__device__ uint32_t g_aoh[M_ * 512],      g_aol[M_ * 512];       // attn out
__device__ float    g_v  [BH_ * N_ * DH_];                       // v (tf32-rounded)

__constant__ float c_invf[16] = {
    1.0f, 0.7498942093324559f, 0.5623413251903491f, 0.4216965034285822f,
    0.31622776601683794f, 0.23713737056616552f, 0.1778279410038923f,
    0.13335214321633237f, 0.1f, 0.07498942093324558f, 0.05623413251903491f,
    0.04216965034285822f, 0.031622776601683794f, 0.023713737056616552f,
    0.01778279410038923f, 0.013335214321633237f
};

__device__ __forceinline__ float tf32r(float x) {
    uint32_t u;
    asm("cvt.rna.tf32.f32 %0, %1;" : "=r"(u) : "f"(x));
    return __uint_as_float(u);
}
// pack (x0 -> low bf16, x1 -> high bf16); lo plane = residual
__device__ __forceinline__ uint2 split_bf16x2(float x0, float x1) {
    uint32_t hp, lp;
    asm("cvt.rn.bf16x2.f32 %0, %1, %2;" : "=r"(hp) : "f"(x1), "f"(x0));
    float h0 = __uint_as_float(hp << 16);
    float h1 = __uint_as_float(hp & 0xffff0000u);
    float l0 = x0 - h0, l1 = x1 - h1;
    asm("cvt.rn.bf16x2.f32 %0, %1, %2;" : "=r"(lp) : "f"(l1), "f"(l0));
    return make_uint2(hp, lp);
}
__device__ __forceinline__ void mma16(float* d, const uint32_t* a, const uint32_t* b) {
    asm volatile(
        "mma.sync.aligned.m16n8k16.row.col.f32.bf16.bf16.f32 "
        "{%0,%1,%2,%3}, {%4,%5,%6,%7}, {%8,%9}, {%0,%1,%2,%3};"
        : "+f"(d[0]), "+f"(d[1]), "+f"(d[2]), "+f"(d[3])
        : "r"(a[0]), "r"(a[1]), "r"(a[2]), "r"(a[3]), "r"(b[0]), "r"(b[1]));
}
__device__ __forceinline__ void mma8t(float* d, const uint32_t* a, const uint32_t* b) {
    asm volatile(
        "mma.sync.aligned.m16n8k8.row.col.f32.tf32.tf32.f32 "
        "{%0,%1,%2,%3}, {%4,%5,%6,%7}, {%8,%9}, {%0,%1,%2,%3};"
        : "+f"(d[0]), "+f"(d[1]), "+f"(d[2]), "+f"(d[3])
        : "r"(a[0]), "r"(a[1]), "r"(a[2]), "r"(a[3]), "r"(b[0]), "r"(b[1]));
}
__device__ __forceinline__ uint32_t smem_u32(const void* p) {
    uint32_t a;
    asm("{ .reg .u64 t; cvta.to.shared.u64 t, %1; cvt.u32.u64 %0, t; }"
        : "=r"(a) : "l"(p));
    return a;
}
__device__ __forceinline__ void cpa16(uint32_t dst, const void* src) {
    asm volatile("cp.async.ca.shared.global [%0], [%1], 16;" :: "r"(dst), "l"(src));
}
#define CP_COMMIT() asm volatile("cp.async.commit_group;" ::: "memory")
#define CP_WAIT0()  asm volatile("cp.async.wait_group 0;" ::: "memory")
#define CP_WAIT1()  asm volatile("cp.async.wait_group 1;" ::: "memory")

// ---------------------------------------------------------------------------
// Split kernel: f32 row-major -> packed bf16 hi/lo planes
// ---------------------------------------------------------------------------
__global__ __launch_bounds__(256) void splitb_kernel(
    const float4* __restrict__ src, uint32_t* __restrict__ dh,
    uint32_t* __restrict__ dl, int n4)
{
    int i = blockIdx.x * blockDim.x + threadIdx.x;
    if (i < n4) {
        float4 v = src[i];
        uint2 p0 = split_bf16x2(v.x, v.y);
        uint2 p1 = split_bf16x2(v.z, v.w);
        *(uint2*)(dh + 2 * i) = make_uint2(p0.x, p1.x);
        *(uint2*)(dl + 2 * i) = make_uint2(p0.y, p1.y);
    }
}

// ===========================================================================
// GEMM mainloop: warp 64x32 of D[128x128] = A[m0:128,:1024] @ B[n0:128,:1024]^T
// Packed bf16 planes via cp.async, 2-stage (proper WAIT1). BK=32 (16 u32).
// 3-pass bf16: ah*bh + ah*bl + al*bh. 256 thr = 8 warps (2m x 4n).
// ===========================================================================
#define SG 20                                        // u32 stride per row
#define GEMM_SMEM (4 * 2 * 128 * SG * 4)             // 81920 B

__device__ __forceinline__ void gemm_ml(
    const uint32_t* __restrict__ Ah, const uint32_t* __restrict__ Al,
    const uint32_t* __restrict__ Bh, const uint32_t* __restrict__ Bl,
    int m0, int n0, uint32_t* smu, float acc[4][4][4])
{
    uint32_t* sAh = smu;
    uint32_t* sAl = sAh + 2 * 128 * SG;
    uint32_t* sBh = sAl + 2 * 128 * SG;
    uint32_t* sBl = sBh + 2 * 128 * SG;
    const uint32_t uAh = smem_u32(sAh), uAl = smem_u32(sAl);
    const uint32_t uBh = smem_u32(sBh), uBl = smem_u32(sBl);

    const int tid = threadIdx.x, lane = tid & 31, wid = tid >> 5;
    const int gid = lane >> 2, tig = lane & 3;
    const int wm = (wid >> 2) * 64, wn = (wid & 3) * 32;

#define GPREF(IT, ST) do {                                                      \
    int _ko = (IT) * 16;                                                        \
    _Pragma("unroll")                                                           \
    for (int s = 0; s < 2; ++s) {                                               \
        int c = tid + s * 256, row = c >> 2, q = (c & 3) * 4;                   \
        cpa16(uAh + (((ST)*128*SG) + row*SG + q)*4, Ah + (size_t)(m0+row)*512 + _ko + q); \
        cpa16(uAl + (((ST)*128*SG) + row*SG + q)*4, Al + (size_t)(m0+row)*512 + _ko + q); \
        cpa16(uBh + (((ST)*128*SG) + row*SG + q)*4, Bh + (size_t)(n0+row)*512 + _ko + q); \
        cpa16(uBl + (((ST)*128*SG) + row*SG + q)*4, Bl + (size_t)(n0+row)*512 + _ko + q); \
    }                                                                           \
} while (0)

    GPREF(0, 0); CP_COMMIT();
    GPREF(1, 1); CP_COMMIT();

    for (int it = 0; it < 32; ++it) {
        const int st = it & 1;
        CP_WAIT1();                 // tile `it` landed; tile it+1 still in flight
        __syncthreads();

        const uint32_t* cAh = sAh + st * 128 * SG;
        const uint32_t* cAl = sAl + st * 128 * SG;
        const uint32_t* cBh = sBh + st * 128 * SG;
        const uint32_t* cBl = sBl + st * 128 * SG;
#pragma unroll
        for (int kc = 0; kc < 2; ++kc) {
            uint32_t bh[4][2], bl[4][2];
#pragma unroll
            for (int j = 0; j < 4; ++j) {
                int bb = (wn + j * 8 + gid) * SG + kc * 8 + tig;
                bh[j][0] = cBh[bb]; bh[j][1] = cBh[bb + 4];
                bl[j][0] = cBl[bb]; bl[j][1] = cBl[bb + 4];
            }
#pragma unroll
            for (int i = 0; i < 4; ++i) {
                int ba = (wm + i * 16 + gid) * SG + kc * 8 + tig;
                uint32_t ah[4] = { cAh[ba], cAh[ba + 8*SG], cAh[ba + 4], cAh[ba + 8*SG + 4] };
                uint32_t al[4] = { cAl[ba], cAl[ba + 8*SG], cAl[ba + 4], cAl[ba + 8*SG + 4] };
#pragma unroll
                for (int j = 0; j < 4; ++j) {
                    mma16(acc[i][j], ah, bh[j]);
                    mma16(acc[i][j], ah, bl[j]);
                    mma16(acc[i][j], al, bh[j]);
                }
            }
        }
        __syncthreads();            // all warps done reading stage st
        if (it + 2 < 32) GPREF(it + 2, st);
        CP_COMMIT();
    }
#undef GPREF
}

// ---------------------------------------------------------------------------
// Kernel A: qkv GEMM + RoPE; q/k packed bf16 planes, v tf32 f32. Grid (24,32).
// ---------------------------------------------------------------------------
__global__ __launch_bounds__(256) void qkv_mma_kernel(const int* __restrict__ pos)
{
    extern __shared__ uint32_t smu[];
    const int tid = threadIdx.x, lane = tid & 31, wid = tid >> 5;
    const int gid = lane >> 2, tig = lane & 3;
    const int wm = (wid >> 2) * 64, wn = (wid & 3) * 32;
    const int m0 = blockIdx.y * 128, n0 = blockIdx.x * 128;

    float acc[4][4][4];
#pragma unroll
    for (int i = 0; i < 4; ++i)
#pragma unroll
        for (int j = 0; j < 4; ++j)
#pragma unroll
            for (int c = 0; c < 4; ++c) acc[i][j][c] = 0.f;

    gemm_ml(g_xh, g_xl, g_wqh, g_wql, m0, n0, smu, acc);

    const int which = n0 >> 10;                    // 0=q 1=k 2=v
    const int h  = (((n0 & 1023) + wn) >> 6);
    const int db = wn & 32;
    const float sc = (which == 0) ? 0.125f : 1.f;
    uint32_t* dh = (which == 0) ? g_qh : g_kh;
    uint32_t* dl = (which == 0) ? g_ql : g_kl;

#pragma unroll
    for (int i = 0; i < 4; ++i) {
        int mA = m0 + wm + i * 16 + gid;
        int mB = mA + 8;
        int rowA = ((mA >> 11) * 16 + h) * 2048 + (mA & 2047);
        int rowB = ((mB >> 11) * 16 + h) * 2048 + (mB & 2047);
        if (which == 2) {
            float* oA = g_v + ((size_t)rowA << 6);
            float* oB = g_v + ((size_t)rowB << 6);
#pragma unroll
            for (int j = 0; j < 4; ++j) {
                int d = db + j * 8 + 2 * tig;
                *(float2*)(oA + d) = make_float2(tf32r(acc[i][j][0]), tf32r(acc[i][j][1]));
                *(float2*)(oB + d) = make_float2(tf32r(acc[i][j][2]), tf32r(acc[i][j][3]));
            }
        } else {
            size_t bAu = (size_t)rowA * 32 + (db >> 1);
            size_t bBu = (size_t)rowB * 32 + (db >> 1);
            int2 pA = ((const int2*)pos)[mA];
            int2 pB = ((const int2*)pos)[mB];
            float pa = db ? (float)pA.y : (float)pA.x;
            float pb = db ? (float)pB.y : (float)pB.x;
#pragma unroll
            for (int j = 0; j < 2; ++j) {
                int dd = j * 8 + 2 * tig;          // even
                int ui = j * 4 + tig;              // u32 index within half
                float s0a,c0a,s1a,c1a,s0b,c0b,s1b,c1b;
                sincosf(pa * c_invf[dd],     &s0a, &c0a);
                sincosf(pa * c_invf[dd + 1], &s1a, &c1a);
                sincosf(pb * c_invf[dd],     &s0b, &c0b);
                sincosf(pb * c_invf[dd + 1], &s1b, &c1b);
                float y10 = acc[i][j][0], y20 = acc[i][j+2][0];
                float y11 = acc[i][j][1], y21 = acc[i][j+2][1];
                uint2 u;
                u = split_bf16x2((y10*c0a - y20*s0a)*sc, (y11*c1a - y21*s1a)*sc);
                dh[bAu + ui] = u.x;     dl[bAu + ui] = u.y;
                u = split_bf16x2((y10*s0a + y20*c0a)*sc, (y11*s1a + y21*c1a)*sc);
                dh[bAu + ui + 8] = u.x; dl[bAu + ui + 8] = u.y;
                float z10 = acc[i][j][2], z20 = acc[i][j+2][2];
                float z11 = acc[i][j][3], z21 = acc[i][j+2][3];
                u = split_bf16x2((z10*c0b - z20*s0b)*sc, (z11*c1b - z21*s1b)*sc);
                dh[bBu + ui] = u.x;     dl[bBu + ui] = u.y;
                u = split_bf16x2((z10*s0b + z20*c0b)*sc, (z11*s1b + z21*c1b)*sc);
                dh[bBu + ui + 8] = u.x; dl[bBu + ui + 8] = u.y;
            }
        }
    }
}

// ---------------------------------------------------------------------------
// Kernel C: out = ao @ proj_w^T + bias. Grid (8, 32).
// ---------------------------------------------------------------------------
__global__ __launch_bounds__(256) void proj_mma_kernel(
    const float* __restrict__ bias, float* __restrict__ out)
{
    extern __shared__ uint32_t smu[];
    const int tid = threadIdx.x, lane = tid & 31, wid = tid >> 5;
    const int gid = lane >> 2, tig = lane & 3;
    const int wm = (wid >> 2) * 64, wn = (wid & 3) * 32;
    const int m0 = blockIdx.y * 128, n0 = blockIdx.x * 128;

    float acc[4][4][4];
#pragma unroll
    for (int i = 0; i < 4; ++i)
#pragma unroll
        for (int j = 0; j < 4; ++j)
#pragma unroll
            for (int c = 0; c < 4; ++c) acc[i][j][c] = 0.f;

    gemm_ml(g_aoh, g_aol, g_wph, g_wpl, m0, n0, smu, acc);

#pragma unroll
    for (int i = 0; i < 4; ++i) {
        int mA = m0 + wm + i * 16 + gid;
#pragma unroll
        for (int j = 0; j < 4; ++j) {
            int n = n0 + wn + j * 8 + 2 * tig;
            float b0 = bias[n], b1 = bias[n + 1];
            *(float2*)(out + (size_t)mA * 1024 + n) =
                make_float2(acc[i][j][0] + b0, acc[i][j][1] + b1);
            *(float2*)(out + (size_t)(mA + 8) * 1024 + n) =
                make_float2(acc[i][j][2] + b0, acc[i][j][3] + b1);
        }
    }
}

// ---------------------------------------------------------------------------
// Kernel B: flash attention. Q bf16 frags in regs; K packed planes cp.async
// double-buffered (no in-kernel split); QK bf16 3-pass; PV single tf32.
// 128 threads, Tq=Tkv=64. Output written as packed bf16 planes for proj.
// ---------------------------------------------------------------------------
#define SKU 36    // u32 stride for K plane rows
#define SVS 72
#define SPS 68
#define ATTN_SMEM ((2*2*64*SKU)*4 + (64*SVS)*4 + (4*16*SPS)*4)   // 72704 B

__global__ __launch_bounds__(128) void attn_mma_kernel()
{
    extern __shared__ uint32_t smu[];
    uint32_t* sKh = smu;                      // [2][64*SKU]
    uint32_t* sKl = sKh + 2 * 64 * SKU;       // [2][64*SKU]
    float*    sV  = (float*)(sKl + 2 * 64 * SKU);   // [64][SVS]
    float*    sP  = sV + 64 * SVS;            // [4][16][SPS]
    const uint32_t uKh = smem_u32(sKh), uKl = smem_u32(sKl), uV = smem_u32(sV);

    const int tid = threadIdx.x, lane = tid & 31, wid = tid >> 5;
    const int gid = lane >> 2, tig = lane & 3;
    const int bh = blockIdx.y, q0 = blockIdx.x * 64;

    const uint32_t* Qh = g_qh + (size_t)(bh * 2048 + q0) * 32;
    const uint32_t* Ql = g_ql + (size_t)(bh * 2048 + q0) * 32;
    const uint32_t* Kh = g_kh + (size_t)bh * 2048 * 32;
    const uint32_t* Kl = g_kl + (size_t)bh * 2048 * 32;
    const float*    Vg = g_v  + (size_t)bh * 2048 * 64;

    // Q fragments straight from gmem planes (a0,a1,a2,a3 layout)
    uint32_t qh[4][4], ql[4][4];
#pragma unroll
    for (int kc = 0; kc < 4; ++kc) {
#pragma unroll
        for (int e = 0; e < 4; ++e) {
            size_t a = (size_t)(wid * 16 + gid + ((e & 1) ? 8 : 0)) * 32
                     + kc * 8 + tig + ((e & 2) ? 4 : 0);
            qh[kc][e] = Qh[a];
            ql[kc][e] = Ql[a];
        }
    }

#define KPREF(KV0, ST) do {                                                     \
    _Pragma("unroll")                                                           \
    for (int s = 0; s < 4; ++s) {                                               \
        int c = tid + s * 128, row = c >> 3, q = (c & 7) * 4;                   \
        cpa16(uKh + (((ST)*64*SKU) + row*SKU + q)*4, Kh + (size_t)((KV0)+row)*32 + q); \
        cpa16(uKl + (((ST)*64*SKU) + row*SKU + q)*4, Kl + (size_t)((KV0)+row)*32 + q); \
    }                                                                           \
} while (0)

    KPREF(0, 0); CP_COMMIT();

    float o[8][4];
#pragma unroll
    for (int j = 0; j < 8; ++j)
#pragma unroll
        for (int c = 0; c < 4; ++c) o[j][c] = 0.f;
    float m0r = -1e30f, m1r = -1e30f, l0 = 0.f, l1 = 0.f;

    float* wP = sP + wid * 16 * SPS;
    const uint32_t* uPp = (const uint32_t*)wP;
    const uint32_t* uVp = (const uint32_t*)sV;

    for (int it = 0; it < 32; ++it) {
        const int kv0 = it * 64, st = it & 1;
        CP_WAIT0();              // K(it) landed (first iter) / no-op later
        __syncthreads();         // prev iteration fully done with sV/sP

        // V(it) direct into sV + prefetch K(it+1) into other stage
#pragma unroll
        for (int s = 0; s < 8; ++s) {
            int c = tid + s * 128, row = c >> 4, q = (c & 15) * 4;
            cpa16(uV + (row * SVS + q) * 4, Vg + (size_t)(kv0 + row) * 64 + q);
        }
        if (it + 1 < 32) KPREF(kv0 + 64, st ^ 1);
        CP_COMMIT();

        // S = (Q/8) K^T, bf16 3-pass
        const uint32_t* cKh = sKh + st * 64 * SKU;
        const uint32_t* cKl = sKl + st * 64 * SKU;
        float s8[8][4];
#pragma unroll
        for (int j = 0; j < 8; ++j)
#pragma unroll
            for (int c = 0; c < 4; ++c) s8[j][c] = 0.f;
#pragma unroll
        for (int kc = 0; kc < 4; ++kc) {
#pragma unroll
            for (int j = 0; j < 8; ++j) {
                int bb = (j * 8 + gid) * SKU + kc * 8 + tig;
                uint32_t kh2[2] = { cKh[bb], cKh[bb + 4] };
                uint32_t kl2[2] = { cKl[bb], cKl[bb + 4] };
                mma16(s8[j], qh[kc], kh2);
                mma16(s8[j], qh[kc], kl2);
                mma16(s8[j], ql[kc], kh2);
            }
        }

        CP_WAIT0();              // V(it) + K(it+1) landed (hidden behind QK)
        __syncthreads();

        // online softmax (rows gid, gid+8)
        float mx0 = -1e30f, mx1 = -1e30f;
#pragma unroll
        for (int j = 0; j < 8; ++j) {
            mx0 = fmaxf(mx0, fmaxf(s8[j][0], s8[j][1]));
            mx1 = fmaxf(mx1, fmaxf(s8[j][2], s8[j][3]));
        }
        mx0 = fmaxf(mx0, __shfl_xor_sync(0xffffffffu, mx0, 1));
        mx0 = fmaxf(mx0, __shfl_xor_sync(0xffffffffu, mx0, 2));
        mx1 = fmaxf(mx1, __shfl_xor_sync(0xffffffffu, mx1, 1));
        mx1 = fmaxf(mx1, __shfl_xor_sync(0xffffffffu, mx1, 2));
        float mn0 = fmaxf(m0r, mx0), mn1 = fmaxf(m1r, mx1);
        float al0 = __expf(m0r - mn0), al1 = __expf(m1r - mn1);
        m0r = mn0; m1r = mn1;
        float sum0 = 0.f, sum1 = 0.f;
#pragma unroll
        for (int j = 0; j < 8; ++j) {
            s8[j][0] = __expf(s8[j][0] - mn0); sum0 += s8[j][0];
            s8[j][1] = __expf(s8[j][1] - mn0); sum0 += s8[j][1];
            s8[j][2] = __expf(s8[j][2] - mn1); sum1 += s8[j][2];
            s8[j][3] = __expf(s8[j][3] - mn1); sum1 += s8[j][3];
        }
        sum0 += __shfl_xor_sync(0xffffffffu, sum0, 1);
        sum0 += __shfl_xor_sync(0xffffffffu, sum0, 2);
        sum1 += __shfl_xor_sync(0xffffffffu, sum1, 1);
        sum1 += __shfl_xor_sync(0xffffffffu, sum1, 2);
        l0 = l0 * al0 + sum0;
        l1 = l1 * al1 + sum1;
#pragma unroll
        for (int j = 0; j < 8; ++j) {
            o[j][0] *= al0; o[j][1] *= al0;
            o[j][2] *= al1; o[j][3] *= al1;
        }

        // stash P (tf32-rounded)
#pragma unroll
        for (int j = 0; j < 8; ++j) {
            *(float2*)(wP + gid * SPS + j * 8 + 2 * tig) =
                make_float2(tf32r(s8[j][0]), tf32r(s8[j][1]));
            *(float2*)(wP + (gid + 8) * SPS + j * 8 + 2 * tig) =
                make_float2(tf32r(s8[j][2]), tf32r(s8[j][3]));
        }
        __syncwarp();

        // O += P V (single tf32; V pre-rounded)
#pragma unroll
        for (int kc = 0; kc < 8; ++kc) {
            uint32_t pa[4];
            int pb = gid * SPS + kc * 8 + tig;
            pa[0] = uPp[pb];     pa[1] = uPp[pb + 8 * SPS];
            pa[2] = uPp[pb + 4]; pa[3] = uPp[pb + 8 * SPS + 4];
#pragma unroll
            for (int j = 0; j < 8; ++j) {
                int vb = (kc * 8 + tig) * SVS + j * 8 + gid;
                uint32_t vv[2] = { uVp[vb], uVp[vb + 4 * SVS] };
                mma8t(o[j], pa, vv);
            }
        }
        __syncwarp();
    }
#undef KPREF

    const float linv0 = 1.f / l0, linv1 = 1.f / l1;
    const int b = bh >> 4, h = bh & 15;
    const int tok0 = q0 + wid * 16 + gid, tok1 = tok0 + 8;
    size_t b0u = (size_t)(b * 2048 + tok0) * 512 + h * 32;
    size_t b1u = (size_t)(b * 2048 + tok1) * 512 + h * 32;
#pragma unroll
    for (int j = 0; j < 8; ++j) {
        int ui = j * 4 + tig;
        uint2 u0 = split_bf16x2(o[j][0] * linv0, o[j][1] * linv0);
        g_aoh[b0u + ui] = u0.x; g_aol[b0u + ui] = u0.y;
        uint2 u1 = split_bf16x2(o[j][2] * linv1, o[j][3] * linv1);
        g_aoh[b1u + ui] = u1.x; g_aol[b1u + ui] = u1.y;
    }
}

// ---------------------------------------------------------------------------
extern "C" void kernel_launch(void* const* d_in, const int* in_sizes, int n_in,
                              void* d_out, int out_size)
{
    const float* x      = (const float*)d_in[0];
    const int*   pos    = (const int*)  d_in[1];
    const float* qkv_w  = (const float*)d_in[2];
    const float* proj_w = (const float*)d_in[3];
    const float* proj_b = (const float*)d_in[4];
    float*       out    = (float*)d_out;

    uint32_t *xh, *xl, *wqh, *wql, *wph, *wpl;
    cudaGetSymbolAddress((void**)&xh,  g_xh);
    cudaGetSymbolAddress((void**)&xl,  g_xl);
    cudaGetSymbolAddress((void**)&wqh, g_wqh);
    cudaGetSymbolAddress((void**)&wql, g_wql);
    cudaGetSymbolAddress((void**)&wph, g_wph);
    cudaGetSymbolAddress((void**)&wpl, g_wpl);

    splitb_kernel<<<(M_*C_/4 + 255)/256, 256>>>((const float4*)x, xh, xl, M_*C_/4);
    splitb_kernel<<<(3*C_*C_/4 + 255)/256, 256>>>((const float4*)qkv_w, wqh, wql, 3*C_*C_/4);
    splitb_kernel<<<(C_*C_/4 + 255)/256, 256>>>((const float4*)proj_w, wph, wpl, C_*C_/4);

    cudaFuncSetAttribute(qkv_mma_kernel,
                         cudaFuncAttributeMaxDynamicSharedMemorySize, GEMM_SMEM);
    cudaFuncSetAttribute(proj_mma_kernel,
                         cudaFuncAttributeMaxDynamicSharedMemorySize, GEMM_SMEM);
    cudaFuncSetAttribute(attn_mma_kernel,
                         cudaFuncAttributeMaxDynamicSharedMemorySize, ATTN_SMEM);

    qkv_mma_kernel<<<dim3(24, 32), 256, GEMM_SMEM>>>(pos);
    attn_mma_kernel<<<dim3(32, 32), 128, ATTN_SMEM>>>();
    proj_mma_kernel<<<dim3(8, 32), 256, GEMM_SMEM>>>(proj_b, out);
}

// round 8
// speedup vs baseline: 2.0699x; 1.0697x over previous
#include <cuda_runtime.h>
#include <math.h>
#include <stdint.h>

#define B_  2
#define N_  2048
#define C_  1024
#define H_  16
#define DH_ 64
#define M_  (B_*N_)
#define BH_ (B_*H_)

// Packed bf16 (hi,lo) planes. u32 = {bf16 k_even | bf16 k_odd<<16}.
__device__ uint32_t g_xh [M_ * 512],      g_xl [M_ * 512];       // x
__device__ uint32_t g_wqh[3 * C_ * 512],  g_wql[3 * C_ * 512];   // qkv_w
__device__ uint32_t g_wph[C_ * 512],      g_wpl[C_ * 512];       // proj_w
__device__ uint32_t g_qh [BH_ * N_ * 32], g_ql [BH_ * N_ * 32];  // q (rope'd, /8)
__device__ uint32_t g_kh [BH_ * N_ * 32], g_kl [BH_ * N_ * 32];  // k (rope'd)
__device__ uint32_t g_aoh[M_ * 512],      g_aol[M_ * 512];       // attn out
__device__ float    g_v  [BH_ * N_ * DH_];                       // v (tf32-rounded)

__constant__ float c_invf[16] = {
    1.0f, 0.7498942093324559f, 0.5623413251903491f, 0.4216965034285822f,
    0.31622776601683794f, 0.23713737056616552f, 0.1778279410038923f,
    0.13335214321633237f, 0.1f, 0.07498942093324558f, 0.05623413251903491f,
    0.04216965034285822f, 0.031622776601683794f, 0.023713737056616552f,
    0.01778279410038923f, 0.013335214321633237f
};

__device__ __forceinline__ float tf32r(float x) {
    uint32_t u;
    asm("cvt.rna.tf32.f32 %0, %1;" : "=r"(u) : "f"(x));
    return __uint_as_float(u);
}
__device__ __forceinline__ uint2 split_bf16x2(float x0, float x1) {
    uint32_t hp, lp;
    asm("cvt.rn.bf16x2.f32 %0, %1, %2;" : "=r"(hp) : "f"(x1), "f"(x0));
    float h0 = __uint_as_float(hp << 16);
    float h1 = __uint_as_float(hp & 0xffff0000u);
    float l0 = x0 - h0, l1 = x1 - h1;
    asm("cvt.rn.bf16x2.f32 %0, %1, %2;" : "=r"(lp) : "f"(l1), "f"(l0));
    return make_uint2(hp, lp);
}
__device__ __forceinline__ void mma16(float* d, const uint32_t* a, const uint32_t* b) {
    asm volatile(
        "mma.sync.aligned.m16n8k16.row.col.f32.bf16.bf16.f32 "
        "{%0,%1,%2,%3}, {%4,%5,%6,%7}, {%8,%9}, {%0,%1,%2,%3};"
        : "+f"(d[0]), "+f"(d[1]), "+f"(d[2]), "+f"(d[3])
        : "r"(a[0]), "r"(a[1]), "r"(a[2]), "r"(a[3]), "r"(b[0]), "r"(b[1]));
}
__device__ __forceinline__ void mma8t(float* d, const uint32_t* a, const uint32_t* b) {
    asm volatile(
        "mma.sync.aligned.m16n8k8.row.col.f32.tf32.tf32.f32 "
        "{%0,%1,%2,%3}, {%4,%5,%6,%7}, {%8,%9}, {%0,%1,%2,%3};"
        : "+f"(d[0]), "+f"(d[1]), "+f"(d[2]), "+f"(d[3])
        : "r"(a[0]), "r"(a[1]), "r"(a[2]), "r"(a[3]), "r"(b[0]), "r"(b[1]));
}
__device__ __forceinline__ void ldsm4(uint32_t* d, uint32_t a) {
    asm volatile("ldmatrix.sync.aligned.m8n8.x4.shared.b16 {%0,%1,%2,%3}, [%4];"
        : "=r"(d[0]), "=r"(d[1]), "=r"(d[2]), "=r"(d[3]) : "r"(a));
}
__device__ __forceinline__ uint32_t smem_u32(const void* p) {
    uint32_t a;
    asm("{ .reg .u64 t; cvta.to.shared.u64 t, %1; cvt.u32.u64 %0, t; }"
        : "=r"(a) : "l"(p));
    return a;
}
__device__ __forceinline__ void cpa16(uint32_t dst, const void* src) {
    asm volatile("cp.async.ca.shared.global [%0], [%1], 16;" :: "r"(dst), "l"(src));
}
#define CP_COMMIT() asm volatile("cp.async.commit_group;" ::: "memory")
#define CP_WAIT0()  asm volatile("cp.async.wait_group 0;" ::: "memory")
#define CP_WAIT1()  asm volatile("cp.async.wait_group 1;" ::: "memory")

// ---------------------------------------------------------------------------
__global__ __launch_bounds__(256) void splitb_kernel(
    const float4* __restrict__ src, uint32_t* __restrict__ dh,
    uint32_t* __restrict__ dl, int n4)
{
    int i = blockIdx.x * blockDim.x + threadIdx.x;
    if (i < n4) {
        float4 v = src[i];
        uint2 p0 = split_bf16x2(v.x, v.y);
        uint2 p1 = split_bf16x2(v.z, v.w);
        *(uint2*)(dh + 2 * i) = make_uint2(p0.x, p1.x);
        *(uint2*)(dl + 2 * i) = make_uint2(p0.y, p1.y);
    }
}

// ===========================================================================
// GEMM mainloop: warp 64x32 of D[128x128] = A[m0:128,:1024] @ B[n0:128,:1024]^T
// Packed bf16 planes, cp.async 2-stage (one barrier/iter), ldmatrix fragments.
// BK=32 (16 u32). 3-pass bf16. 256 thr = 8 warps (2m x 4n).
// ===========================================================================
#define SG 20
#define GEMM_SMEM (4 * 2 * 128 * SG * 4)             // 81920 B

__device__ __forceinline__ void gemm_ml(
    const uint32_t* __restrict__ Ah, const uint32_t* __restrict__ Al,
    const uint32_t* __restrict__ Bh, const uint32_t* __restrict__ Bl,
    int m0, int n0, uint32_t* smu, float acc[4][4][4])
{
    uint32_t* sAh = smu;
    uint32_t* sAl = sAh + 2 * 128 * SG;
    uint32_t* sBh = sAl + 2 * 128 * SG;
    uint32_t* sBl = sBh + 2 * 128 * SG;
    const uint32_t uAh = smem_u32(sAh), uAl = smem_u32(sAl);
    const uint32_t uBh = smem_u32(sBh), uBl = smem_u32(sBl);

    const int tid = threadIdx.x, lane = tid & 31, wid = tid >> 5;
    const int wm = (wid >> 2) * 64, wn = (wid & 3) * 32;
    const int mq = lane >> 3, r = lane & 7;
    // ldmatrix byte offsets (per-lane row addresses)
    const uint32_t aOff = ((wm + (mq & 1) * 8 + r) * SG + (mq >> 1) * 4) * 4;
    const uint32_t bOff = ((wn + (mq >> 1) * 8 + r) * SG + (mq & 1) * 4) * 4;

#define GPREF(IT, ST) do {                                                      \
    int _ko = (IT) * 16;                                                        \
    _Pragma("unroll")                                                           \
    for (int s = 0; s < 2; ++s) {                                               \
        int c = tid + s * 256, row = c >> 2, q = (c & 3) * 4;                   \
        cpa16(uAh + (((ST)*128*SG) + row*SG + q)*4, Ah + (size_t)(m0+row)*512 + _ko + q); \
        cpa16(uAl + (((ST)*128*SG) + row*SG + q)*4, Al + (size_t)(m0+row)*512 + _ko + q); \
        cpa16(uBh + (((ST)*128*SG) + row*SG + q)*4, Bh + (size_t)(n0+row)*512 + _ko + q); \
        cpa16(uBl + (((ST)*128*SG) + row*SG + q)*4, Bl + (size_t)(n0+row)*512 + _ko + q); \
    }                                                                           \
} while (0)

    GPREF(0, 0); CP_COMMIT();

    for (int it = 0; it < 32; ++it) {
        const int st = it & 1;
        CP_WAIT0();                 // tile `it` landed
        __syncthreads();            // everyone done with stage st (prev use)
        if (it + 1 < 32) { GPREF(it + 1, st ^ 1); CP_COMMIT(); }

        const uint32_t so = st * 128 * SG * 4;
#pragma unroll
        for (int kc = 0; kc < 2; ++kc) {
            uint32_t bh[4][2], bl[4][2];
#pragma unroll
            for (int jp = 0; jp < 2; ++jp) {
                uint32_t t[4];
                ldsm4(t, uBh + so + bOff + (jp * 16 * SG + kc * 8) * 4);
                bh[2*jp][0] = t[0]; bh[2*jp][1] = t[1];
                bh[2*jp+1][0] = t[2]; bh[2*jp+1][1] = t[3];
                ldsm4(t, uBl + so + bOff + (jp * 16 * SG + kc * 8) * 4);
                bl[2*jp][0] = t[0]; bl[2*jp][1] = t[1];
                bl[2*jp+1][0] = t[2]; bl[2*jp+1][1] = t[3];
            }
#pragma unroll
            for (int i = 0; i < 4; ++i) {
                uint32_t ah[4], al[4];
                ldsm4(ah, uAh + so + aOff + (i * 16 * SG + kc * 8) * 4);
                ldsm4(al, uAl + so + aOff + (i * 16 * SG + kc * 8) * 4);
#pragma unroll
                for (int j = 0; j < 4; ++j) {
                    mma16(acc[i][j], ah, bh[j]);
                    mma16(acc[i][j], ah, bl[j]);
                    mma16(acc[i][j], al, bh[j]);
                }
            }
        }
    }
#undef GPREF
}

// ---------------------------------------------------------------------------
// Kernel A: qkv GEMM + RoPE; q/k packed bf16 planes, v tf32 f32. Grid (24,32).
// ---------------------------------------------------------------------------
__global__ __launch_bounds__(256) void qkv_mma_kernel(const int* __restrict__ pos)
{
    extern __shared__ uint32_t smu[];
    const int tid = threadIdx.x, lane = tid & 31, wid = tid >> 5;
    const int gid = lane >> 2, tig = lane & 3;
    const int wm = (wid >> 2) * 64, wn = (wid & 3) * 32;
    const int m0 = blockIdx.y * 128, n0 = blockIdx.x * 128;

    float acc[4][4][4];
#pragma unroll
    for (int i = 0; i < 4; ++i)
#pragma unroll
        for (int j = 0; j < 4; ++j)
#pragma unroll
            for (int c = 0; c < 4; ++c) acc[i][j][c] = 0.f;

    gemm_ml(g_xh, g_xl, g_wqh, g_wql, m0, n0, smu, acc);

    const int which = n0 >> 10;                    // 0=q 1=k 2=v
    const int h  = (((n0 & 1023) + wn) >> 6);
    const int db = wn & 32;
    const float sc = (which == 0) ? 0.125f : 1.f;
    uint32_t* dh = (which == 0) ? g_qh : g_kh;
    uint32_t* dl = (which == 0) ? g_ql : g_kl;

#pragma unroll
    for (int i = 0; i < 4; ++i) {
        int mA = m0 + wm + i * 16 + gid;
        int mB = mA + 8;
        int rowA = ((mA >> 11) * 16 + h) * 2048 + (mA & 2047);
        int rowB = ((mB >> 11) * 16 + h) * 2048 + (mB & 2047);
        if (which == 2) {
            float* oA = g_v + ((size_t)rowA << 6);
            float* oB = g_v + ((size_t)rowB << 6);
#pragma unroll
            for (int j = 0; j < 4; ++j) {
                int d = db + j * 8 + 2 * tig;
                *(float2*)(oA + d) = make_float2(tf32r(acc[i][j][0]), tf32r(acc[i][j][1]));
                *(float2*)(oB + d) = make_float2(tf32r(acc[i][j][2]), tf32r(acc[i][j][3]));
            }
        } else {
            size_t bAu = (size_t)rowA * 32 + (db >> 1);
            size_t bBu = (size_t)rowB * 32 + (db >> 1);
            int2 pA = ((const int2*)pos)[mA];
            int2 pB = ((const int2*)pos)[mB];
            float pa = db ? (float)pA.y : (float)pA.x;
            float pb = db ? (float)pB.y : (float)pB.x;
#pragma unroll
            for (int j = 0; j < 2; ++j) {
                int dd = j * 8 + 2 * tig;
                int ui = j * 4 + tig;
                float s0a,c0a,s1a,c1a,s0b,c0b,s1b,c1b;
                sincosf(pa * c_invf[dd],     &s0a, &c0a);
                sincosf(pa * c_invf[dd + 1], &s1a, &c1a);
                sincosf(pb * c_invf[dd],     &s0b, &c0b);
                sincosf(pb * c_invf[dd + 1], &s1b, &c1b);
                float y10 = acc[i][j][0], y20 = acc[i][j+2][0];
                float y11 = acc[i][j][1], y21 = acc[i][j+2][1];
                uint2 u;
                u = split_bf16x2((y10*c0a - y20*s0a)*sc, (y11*c1a - y21*s1a)*sc);
                dh[bAu + ui] = u.x;     dl[bAu + ui] = u.y;
                u = split_bf16x2((y10*s0a + y20*c0a)*sc, (y11*s1a + y21*c1a)*sc);
                dh[bAu + ui + 8] = u.x; dl[bAu + ui + 8] = u.y;
                float z10 = acc[i][j][2], z20 = acc[i][j+2][2];
                float z11 = acc[i][j][3], z21 = acc[i][j+2][3];
                u = split_bf16x2((z10*c0b - z20*s0b)*sc, (z11*c1b - z21*s1b)*sc);
                dh[bBu + ui] = u.x;     dl[bBu + ui] = u.y;
                u = split_bf16x2((z10*s0b + z20*c0b)*sc, (z11*s1b + z21*c1b)*sc);
                dh[bBu + ui + 8] = u.x; dl[bBu + ui + 8] = u.y;
            }
        }
    }
}

// ---------------------------------------------------------------------------
// Kernel C: out = ao @ proj_w^T + bias. Grid (8, 32).
// ---------------------------------------------------------------------------
__global__ __launch_bounds__(256) void proj_mma_kernel(
    const float* __restrict__ bias, float* __restrict__ out)
{
    extern __shared__ uint32_t smu[];
    const int tid = threadIdx.x, lane = tid & 31, wid = tid >> 5;
    const int gid = lane >> 2, tig = lane & 3;
    const int wm = (wid >> 2) * 64, wn = (wid & 3) * 32;
    const int m0 = blockIdx.y * 128, n0 = blockIdx.x * 128;

    float acc[4][4][4];
#pragma unroll
    for (int i = 0; i < 4; ++i)
#pragma unroll
        for (int j = 0; j < 4; ++j)
#pragma unroll
            for (int c = 0; c < 4; ++c) acc[i][j][c] = 0.f;

    gemm_ml(g_aoh, g_aol, g_wph, g_wpl, m0, n0, smu, acc);

#pragma unroll
    for (int i = 0; i < 4; ++i) {
        int mA = m0 + wm + i * 16 + gid;
#pragma unroll
        for (int j = 0; j < 4; ++j) {
            int n = n0 + wn + j * 8 + 2 * tig;
            float b0 = bias[n], b1 = bias[n + 1];
            *(float2*)(out + (size_t)mA * 1024 + n) =
                make_float2(acc[i][j][0] + b0, acc[i][j][1] + b1);
            *(float2*)(out + (size_t)(mA + 8) * 1024 + n) =
                make_float2(acc[i][j][2] + b0, acc[i][j][3] + b1);
        }
    }
}

// ---------------------------------------------------------------------------
// Kernel B: flash attention. Q bf16 frags in regs; K planes via ldmatrix,
// double-buffered with separate V/K commit groups; QK bf16 3-pass; PV tf32.
// ---------------------------------------------------------------------------
#define SKU 36
#define SVS 72
#define SPS 68
#define ATTN_SMEM ((2*2*64*SKU)*4 + (64*SVS)*4 + (4*16*SPS)*4)   // 72704 B

__global__ __launch_bounds__(128) void attn_mma_kernel()
{
    extern __shared__ uint32_t smu[];
    uint32_t* sKh = smu;                      // [2][64*SKU]
    uint32_t* sKl = sKh + 2 * 64 * SKU;       // [2][64*SKU]
    float*    sV  = (float*)(sKl + 2 * 64 * SKU);   // [64][SVS]
    float*    sP  = sV + 64 * SVS;            // [4][16][SPS]
    const uint32_t uKh = smem_u32(sKh), uKl = smem_u32(sKl), uV = smem_u32(sV);

    const int tid = threadIdx.x, lane = tid & 31, wid = tid >> 5;
    const int gid = lane >> 2, tig = lane & 3;
    const int mq = lane >> 3, r = lane & 7;
    const int bh = blockIdx.y, q0 = blockIdx.x * 64;
    // ldmatrix (B-pattern) per-lane byte offset into a K stage
    const uint32_t kOff = (((mq >> 1) * 8 + r) * SKU + (mq & 1) * 4) * 4;

    const uint32_t* Qh = g_qh + (size_t)(bh * 2048 + q0) * 32;
    const uint32_t* Ql = g_ql + (size_t)(bh * 2048 + q0) * 32;
    const uint32_t* Kh = g_kh + (size_t)bh * 2048 * 32;
    const uint32_t* Kl = g_kl + (size_t)bh * 2048 * 32;
    const float*    Vg = g_v  + (size_t)bh * 2048 * 64;

    uint32_t qh[4][4], ql[4][4];
#pragma unroll
    for (int kc = 0; kc < 4; ++kc) {
#pragma unroll
        for (int e = 0; e < 4; ++e) {
            size_t a = (size_t)(wid * 16 + gid + ((e & 1) ? 8 : 0)) * 32
                     + kc * 8 + tig + ((e & 2) ? 4 : 0);
            qh[kc][e] = Qh[a];
            ql[kc][e] = Ql[a];
        }
    }

#define KPREF(KV0, ST) do {                                                     \
    _Pragma("unroll")                                                           \
    for (int s = 0; s < 4; ++s) {                                               \
        int c = tid + s * 128, row = c >> 3, q = (c & 7) * 4;                   \
        cpa16(uKh + (((ST)*64*SKU) + row*SKU + q)*4, Kh + (size_t)((KV0)+row)*32 + q); \
        cpa16(uKl + (((ST)*64*SKU) + row*SKU + q)*4, Kl + (size_t)((KV0)+row)*32 + q); \
    }                                                                           \
} while (0)

    KPREF(0, 0); CP_COMMIT();

    float o[8][4];
#pragma unroll
    for (int j = 0; j < 8; ++j)
#pragma unroll
        for (int c = 0; c < 4; ++c) o[j][c] = 0.f;
    float m0r = -1e30f, m1r = -1e30f, l0 = 0.f, l1 = 0.f;

    float* wP = sP + wid * 16 * SPS;
    const uint32_t* uPp = (const uint32_t*)wP;
    const uint32_t* uVp = (const uint32_t*)sV;

    for (int it = 0; it < 32; ++it) {
        const int kv0 = it * 64, st = it & 1;
        CP_WAIT0();              // K(it) landed
        __syncthreads();         // prev iteration fully done with sV/sP/stage st

        // V(it) into sV: its own commit group
#pragma unroll
        for (int s = 0; s < 8; ++s) {
            int c = tid + s * 128, row = c >> 4, q = (c & 15) * 4;
            cpa16(uV + (row * SVS + q) * 4, Vg + (size_t)(kv0 + row) * 64 + q);
        }
        CP_COMMIT();
        // K(it+1) prefetch: separate group, stays in flight through softmax/PV
        if (it + 1 < 32) { KPREF(kv0 + 64, st ^ 1); }
        CP_COMMIT();

        // S = (Q/8) K^T, bf16 3-pass, K frags via ldmatrix
        const uint32_t so = st * 64 * SKU * 4;
        float s8[8][4];
#pragma unroll
        for (int j = 0; j < 8; ++j)
#pragma unroll
            for (int c = 0; c < 4; ++c) s8[j][c] = 0.f;
#pragma unroll
        for (int kc = 0; kc < 4; ++kc) {
#pragma unroll
            for (int jp = 0; jp < 4; ++jp) {
                uint32_t th[4], tl[4];
                ldsm4(th, uKh + so + kOff + (jp * 16 * SKU + kc * 8) * 4);
                ldsm4(tl, uKl + so + kOff + (jp * 16 * SKU + kc * 8) * 4);
                mma16(s8[2*jp],   qh[kc], th);
                mma16(s8[2*jp],   qh[kc], tl);
                mma16(s8[2*jp],   ql[kc], th);
                mma16(s8[2*jp+1], qh[kc], th + 2);
                mma16(s8[2*jp+1], qh[kc], tl + 2);
                mma16(s8[2*jp+1], ql[kc], th + 2);
            }
        }

        CP_WAIT1();              // V(it) landed; K(it+1) still in flight
        __syncthreads();

        // online softmax (rows gid, gid+8)
        float mx0 = -1e30f, mx1 = -1e30f;
#pragma unroll
        for (int j = 0; j < 8; ++j) {
            mx0 = fmaxf(mx0, fmaxf(s8[j][0], s8[j][1]));
            mx1 = fmaxf(mx1, fmaxf(s8[j][2], s8[j][3]));
        }
        mx0 = fmaxf(mx0, __shfl_xor_sync(0xffffffffu, mx0, 1));
        mx0 = fmaxf(mx0, __shfl_xor_sync(0xffffffffu, mx0, 2));
        mx1 = fmaxf(mx1, __shfl_xor_sync(0xffffffffu, mx1, 1));
        mx1 = fmaxf(mx1, __shfl_xor_sync(0xffffffffu, mx1, 2));
        float mn0 = fmaxf(m0r, mx0), mn1 = fmaxf(m1r, mx1);
        float al0 = __expf(m0r - mn0), al1 = __expf(m1r - mn1);
        m0r = mn0; m1r = mn1;
        float sum0 = 0.f, sum1 = 0.f;
#pragma unroll
        for (int j = 0; j < 8; ++j) {
            s8[j][0] = __expf(s8[j][0] - mn0); sum0 += s8[j][0];
            s8[j][1] = __expf(s8[j][1] - mn0); sum0 += s8[j][1];
            s8[j][2] = __expf(s8[j][2] - mn1); sum1 += s8[j][2];
            s8[j][3] = __expf(s8[j][3] - mn1); sum1 += s8[j][3];
        }
        sum0 += __shfl_xor_sync(0xffffffffu, sum0, 1);
        sum0 += __shfl_xor_sync(0xffffffffu, sum0, 2);
        sum1 += __shfl_xor_sync(0xffffffffu, sum1, 1);
        sum1 += __shfl_xor_sync(0xffffffffu, sum1, 2);
        l0 = l0 * al0 + sum0;
        l1 = l1 * al1 + sum1;
#pragma unroll
        for (int j = 0; j < 8; ++j) {
            o[j][0] *= al0; o[j][1] *= al0;
            o[j][2] *= al1; o[j][3] *= al1;
        }

        // stash P (tf32-rounded)
#pragma unroll
        for (int j = 0; j < 8; ++j) {
            *(float2*)(wP + gid * SPS + j * 8 + 2 * tig) =
                make_float2(tf32r(s8[j][0]), tf32r(s8[j][1]));
            *(float2*)(wP + (gid + 8) * SPS + j * 8 + 2 * tig) =
                make_float2(tf32r(s8[j][2]), tf32r(s8[j][3]));
        }
        __syncwarp();

        // O += P V (single tf32; V pre-rounded)
#pragma unroll
        for (int kc = 0; kc < 8; ++kc) {
            uint32_t pa[4];
            int pb = gid * SPS + kc * 8 + tig;
            pa[0] = uPp[pb];     pa[1] = uPp[pb + 8 * SPS];
            pa[2] = uPp[pb + 4]; pa[3] = uPp[pb + 8 * SPS + 4];
#pragma unroll
            for (int j = 0; j < 8; ++j) {
                int vb = (kc * 8 + tig) * SVS + j * 8 + gid;
                uint32_t vv[2] = { uVp[vb], uVp[vb + 4 * SVS] };
                mma8t(o[j], pa, vv);
            }
        }
        __syncwarp();
    }
#undef KPREF

    const float linv0 = 1.f / l0, linv1 = 1.f / l1;
    const int b = bh >> 4, h = bh & 15;
    const int tok0 = q0 + wid * 16 + gid, tok1 = tok0 + 8;
    size_t b0u = (size_t)(b * 2048 + tok0) * 512 + h * 32;
    size_t b1u = (size_t)(b * 2048 + tok1) * 512 + h * 32;
#pragma unroll
    for (int j = 0; j < 8; ++j) {
        int ui = j * 4 + tig;
        uint2 u0 = split_bf16x2(o[j][0] * linv0, o[j][1] * linv0);
        g_aoh[b0u + ui] = u0.x; g_aol[b0u + ui] = u0.y;
        uint2 u1 = split_bf16x2(o[j][2] * linv1, o[j][3] * linv1);
        g_aoh[b1u + ui] = u1.x; g_aol[b1u + ui] = u1.y;
    }
}

// ---------------------------------------------------------------------------
extern "C" void kernel_launch(void* const* d_in, const int* in_sizes, int n_in,
                              void* d_out, int out_size)
{
    const float* x      = (const float*)d_in[0];
    const int*   pos    = (const int*)  d_in[1];
    const float* qkv_w  = (const float*)d_in[2];
    const float* proj_w = (const float*)d_in[3];
    const float* proj_b = (const float*)d_in[4];
    float*       out    = (float*)d_out;

    uint32_t *xh, *xl, *wqh, *wql, *wph, *wpl;
    cudaGetSymbolAddress((void**)&xh,  g_xh);
    cudaGetSymbolAddress((void**)&xl,  g_xl);
    cudaGetSymbolAddress((void**)&wqh, g_wqh);
    cudaGetSymbolAddress((void**)&wql, g_wql);
    cudaGetSymbolAddress((void**)&wph, g_wph);
    cudaGetSymbolAddress((void**)&wpl, g_wpl);

    splitb_kernel<<<(M_*C_/4 + 255)/256, 256>>>((const float4*)x, xh, xl, M_*C_/4);
    splitb_kernel<<<(3*C_*C_/4 + 255)/256, 256>>>((const float4*)qkv_w, wqh, wql, 3*C_*C_/4);
    splitb_kernel<<<(C_*C_/4 + 255)/256, 256>>>((const float4*)proj_w, wph, wpl, C_*C_/4);

    cudaFuncSetAttribute(qkv_mma_kernel,
                         cudaFuncAttributeMaxDynamicSharedMemorySize, GEMM_SMEM);
    cudaFuncSetAttribute(proj_mma_kernel,
                         cudaFuncAttributeMaxDynamicSharedMemorySize, GEMM_SMEM);
    cudaFuncSetAttribute(attn_mma_kernel,
                         cudaFuncAttributeMaxDynamicSharedMemorySize, ATTN_SMEM);

    qkv_mma_kernel<<<dim3(24, 32), 256, GEMM_SMEM>>>(pos);
    attn_mma_kernel<<<dim3(32, 32), 128, ATTN_SMEM>>>();
    proj_mma_kernel<<<dim3(8, 32), 256, GEMM_SMEM>>>(proj_b, out);
}

// round 9
// speedup vs baseline: 2.1349x; 1.0314x over previous
#include <cuda_runtime.h>
#include <math.h>
#include <stdint.h>

#define B_  2
#define N_  2048
#define C_  1024
#define H_  16
#define DH_ 64
#define M_  (B_*N_)
#define BH_ (B_*H_)

// Packed bf16 (hi,lo) planes. u32 = {bf16 k_even | bf16 k_odd<<16}.
__device__ uint32_t g_xh [M_ * 512],      g_xl [M_ * 512];       // x
__device__ uint32_t g_wqh[3 * C_ * 512],  g_wql[3 * C_ * 512];   // qkv_w
__device__ uint32_t g_wph[C_ * 512],      g_wpl[C_ * 512];       // proj_w
__device__ uint32_t g_qh [BH_ * N_ * 32], g_ql [BH_ * N_ * 32];  // q (rope'd, /8)
__device__ uint32_t g_kh [BH_ * N_ * 32], g_kl [BH_ * N_ * 32];  // k (rope'd)
__device__ uint32_t g_aoh[M_ * 512],      g_aol[M_ * 512];       // attn out
__device__ float    g_v  [BH_ * N_ * DH_];                       // v (tf32-rounded)

__constant__ float c_invf[16] = {
    1.0f, 0.7498942093324559f, 0.5623413251903491f, 0.4216965034285822f,
    0.31622776601683794f, 0.23713737056616552f, 0.1778279410038923f,
    0.13335214321633237f, 0.1f, 0.07498942093324558f, 0.05623413251903491f,
    0.04216965034285822f, 0.031622776601683794f, 0.023713737056616552f,
    0.01778279410038923f, 0.013335214321633237f
};

__device__ __forceinline__ float tf32r(float x) {
    uint32_t u;
    asm("cvt.rna.tf32.f32 %0, %1;" : "=r"(u) : "f"(x));
    return __uint_as_float(u);
}
__device__ __forceinline__ uint2 split_bf16x2(float x0, float x1) {
    uint32_t hp, lp;
    asm("cvt.rn.bf16x2.f32 %0, %1, %2;" : "=r"(hp) : "f"(x1), "f"(x0));
    float h0 = __uint_as_float(hp << 16);
    float h1 = __uint_as_float(hp & 0xffff0000u);
    float l0 = x0 - h0, l1 = x1 - h1;
    asm("cvt.rn.bf16x2.f32 %0, %1, %2;" : "=r"(lp) : "f"(l1), "f"(l0));
    return make_uint2(hp, lp);
}
__device__ __forceinline__ void mma16(float* d, const uint32_t* a, const uint32_t* b) {
    asm volatile(
        "mma.sync.aligned.m16n8k16.row.col.f32.bf16.bf16.f32 "
        "{%0,%1,%2,%3}, {%4,%5,%6,%7}, {%8,%9}, {%0,%1,%2,%3};"
        : "+f"(d[0]), "+f"(d[1]), "+f"(d[2]), "+f"(d[3])
        : "r"(a[0]), "r"(a[1]), "r"(a[2]), "r"(a[3]), "r"(b[0]), "r"(b[1]));
}
__device__ __forceinline__ void mma8t(float* d, const uint32_t* a, const uint32_t* b) {
    asm volatile(
        "mma.sync.aligned.m16n8k8.row.col.f32.tf32.tf32.f32 "
        "{%0,%1,%2,%3}, {%4,%5,%6,%7}, {%8,%9}, {%0,%1,%2,%3};"
        : "+f"(d[0]), "+f"(d[1]), "+f"(d[2]), "+f"(d[3])
        : "r"(a[0]), "r"(a[1]), "r"(a[2]), "r"(a[3]), "r"(b[0]), "r"(b[1]));
}
__device__ __forceinline__ void ldsm4(uint32_t* d, uint32_t a) {
    asm volatile("ldmatrix.sync.aligned.m8n8.x4.shared.b16 {%0,%1,%2,%3}, [%4];"
        : "=r"(d[0]), "=r"(d[1]), "=r"(d[2]), "=r"(d[3]) : "r"(a));
}
__device__ __forceinline__ uint32_t smem_u32(const void* p) {
    uint32_t a;
    asm("{ .reg .u64 t; cvta.to.shared.u64 t, %1; cvt.u32.u64 %0, t; }"
        : "=r"(a) : "l"(p));
    return a;
}
__device__ __forceinline__ void cpa16(uint32_t dst, const void* src) {
    asm volatile("cp.async.ca.shared.global [%0], [%1], 16;" :: "r"(dst), "l"(src));
}
#define CP_COMMIT() asm volatile("cp.async.commit_group;" ::: "memory")
#define CP_WAIT0()  asm volatile("cp.async.wait_group 0;" ::: "memory")
#define CP_WAIT1()  asm volatile("cp.async.wait_group 1;" ::: "memory")

// ---------------------------------------------------------------------------
__global__ __launch_bounds__(256) void splitb_kernel(
    const float4* __restrict__ src, uint32_t* __restrict__ dh,
    uint32_t* __restrict__ dl, int n4)
{
    int i = blockIdx.x * blockDim.x + threadIdx.x;
    if (i < n4) {
        float4 v = src[i];
        uint2 p0 = split_bf16x2(v.x, v.y);
        uint2 p1 = split_bf16x2(v.z, v.w);
        *(uint2*)(dh + 2 * i) = make_uint2(p0.x, p1.x);
        *(uint2*)(dl + 2 * i) = make_uint2(p0.y, p1.y);
    }
}

// ===========================================================================
// GEMM mainloop: warp 64x32 of D[128x128] = A[m0:128,:1024] @ B[n0:128,:1024]^T
// Packed bf16 planes, cp.async 2-stage (one barrier/iter), ldmatrix fragments.
// BK=32 (16 u32). 3-pass bf16. 256 thr = 8 warps (2m x 4n).
// ===========================================================================
#define SG 20
#define GEMM_SMEM (4 * 2 * 128 * SG * 4)             // 81920 B

__device__ __forceinline__ void gemm_ml(
    const uint32_t* __restrict__ Ah, const uint32_t* __restrict__ Al,
    const uint32_t* __restrict__ Bh, const uint32_t* __restrict__ Bl,
    int m0, int n0, uint32_t* smu, float acc[4][4][4])
{
    uint32_t* sAh = smu;
    uint32_t* sAl = sAh + 2 * 128 * SG;
    uint32_t* sBh = sAl + 2 * 128 * SG;
    uint32_t* sBl = sBh + 2 * 128 * SG;
    const uint32_t uAh = smem_u32(sAh), uAl = smem_u32(sAl);
    const uint32_t uBh = smem_u32(sBh), uBl = smem_u32(sBl);

    const int tid = threadIdx.x, lane = tid & 31, wid = tid >> 5;
    const int wm = (wid >> 2) * 64, wn = (wid & 3) * 32;
    const int mq = lane >> 3, r = lane & 7;
    const uint32_t aOff = ((wm + (mq & 1) * 8 + r) * SG + (mq >> 1) * 4) * 4;
    const uint32_t bOff = ((wn + (mq >> 1) * 8 + r) * SG + (mq & 1) * 4) * 4;

#define GPREF(IT, ST) do {                                                      \
    int _ko = (IT) * 16;                                                        \
    _Pragma("unroll")                                                           \
    for (int s = 0; s < 2; ++s) {                                               \
        int c = tid + s * 256, row = c >> 2, q = (c & 3) * 4;                   \
        cpa16(uAh + (((ST)*128*SG) + row*SG + q)*4, Ah + (size_t)(m0+row)*512 + _ko + q); \
        cpa16(uAl + (((ST)*128*SG) + row*SG + q)*4, Al + (size_t)(m0+row)*512 + _ko + q); \
        cpa16(uBh + (((ST)*128*SG) + row*SG + q)*4, Bh + (size_t)(n0+row)*512 + _ko + q); \
        cpa16(uBl + (((ST)*128*SG) + row*SG + q)*4, Bl + (size_t)(n0+row)*512 + _ko + q); \
    }                                                                           \
} while (0)

    GPREF(0, 0); CP_COMMIT();

    for (int it = 0; it < 32; ++it) {
        const int st = it & 1;
        CP_WAIT0();                 // tile `it` landed
        __syncthreads();            // everyone done with stage st (prev use)
        if (it + 1 < 32) { GPREF(it + 1, st ^ 1); CP_COMMIT(); }

        const uint32_t so = st * 128 * SG * 4;
#pragma unroll
        for (int kc = 0; kc < 2; ++kc) {
            uint32_t bh[4][2], bl[4][2];
#pragma unroll
            for (int jp = 0; jp < 2; ++jp) {
                uint32_t t[4];
                ldsm4(t, uBh + so + bOff + (jp * 16 * SG + kc * 8) * 4);
                bh[2*jp][0] = t[0]; bh[2*jp][1] = t[1];
                bh[2*jp+1][0] = t[2]; bh[2*jp+1][1] = t[3];
                ldsm4(t, uBl + so + bOff + (jp * 16 * SG + kc * 8) * 4);
                bl[2*jp][0] = t[0]; bl[2*jp][1] = t[1];
                bl[2*jp+1][0] = t[2]; bl[2*jp+1][1] = t[3];
            }
#pragma unroll
            for (int i = 0; i < 4; ++i) {
                uint32_t ah[4], al[4];
                ldsm4(ah, uAh + so + aOff + (i * 16 * SG + kc * 8) * 4);
                ldsm4(al, uAl + so + aOff + (i * 16 * SG + kc * 8) * 4);
#pragma unroll
                for (int j = 0; j < 4; ++j) {
                    mma16(acc[i][j], ah, bh[j]);
                    mma16(acc[i][j], ah, bl[j]);
                    mma16(acc[i][j], al, bh[j]);
                }
            }
        }
    }
#undef GPREF
}

// ---------------------------------------------------------------------------
// Kernel A: qkv GEMM + RoPE; q/k packed bf16 planes, v tf32 f32. Grid (24,32).
// __launch_bounds__(256,2): cap regs at 128 so 2 CTAs co-reside per SM.
// ---------------------------------------------------------------------------
__global__ __launch_bounds__(256, 2) void qkv_mma_kernel(const int* __restrict__ pos)
{
    extern __shared__ uint32_t smu[];
    const int tid = threadIdx.x, lane = tid & 31, wid = tid >> 5;
    const int gid = lane >> 2, tig = lane & 3;
    const int wm = (wid >> 2) * 64, wn = (wid & 3) * 32;
    const int m0 = blockIdx.y * 128, n0 = blockIdx.x * 128;

    float acc[4][4][4];
#pragma unroll
    for (int i = 0; i < 4; ++i)
#pragma unroll
        for (int j = 0; j < 4; ++j)
#pragma unroll
            for (int c = 0; c < 4; ++c) acc[i][j][c] = 0.f;

    gemm_ml(g_xh, g_xl, g_wqh, g_wql, m0, n0, smu, acc);

    const int which = n0 >> 10;                    // 0=q 1=k 2=v
    const int h  = (((n0 & 1023) + wn) >> 6);
    const int db = wn & 32;
    const float sc = (which == 0) ? 0.125f : 1.f;
    uint32_t* dh = (which == 0) ? g_qh : g_kh;
    uint32_t* dl = (which == 0) ? g_ql : g_kl;

#pragma unroll
    for (int i = 0; i < 4; ++i) {
        int mA = m0 + wm + i * 16 + gid;
        int mB = mA + 8;
        int rowA = ((mA >> 11) * 16 + h) * 2048 + (mA & 2047);
        int rowB = ((mB >> 11) * 16 + h) * 2048 + (mB & 2047);
        if (which == 2) {
            float* oA = g_v + ((size_t)rowA << 6);
            float* oB = g_v + ((size_t)rowB << 6);
#pragma unroll
            for (int j = 0; j < 4; ++j) {
                int d = db + j * 8 + 2 * tig;
                *(float2*)(oA + d) = make_float2(tf32r(acc[i][j][0]), tf32r(acc[i][j][1]));
                *(float2*)(oB + d) = make_float2(tf32r(acc[i][j][2]), tf32r(acc[i][j][3]));
            }
        } else {
            size_t bAu = (size_t)rowA * 32 + (db >> 1);
            size_t bBu = (size_t)rowB * 32 + (db >> 1);
            int2 pA = ((const int2*)pos)[mA];
            int2 pB = ((const int2*)pos)[mB];
            float pa = db ? (float)pA.y : (float)pA.x;
            float pb = db ? (float)pB.y : (float)pB.x;
#pragma unroll
            for (int j = 0; j < 2; ++j) {
                int dd = j * 8 + 2 * tig;
                int ui = j * 4 + tig;
                float s0a,c0a,s1a,c1a,s0b,c0b,s1b,c1b;
                sincosf(pa * c_invf[dd],     &s0a, &c0a);
                sincosf(pa * c_invf[dd + 1], &s1a, &c1a);
                sincosf(pb * c_invf[dd],     &s0b, &c0b);
                sincosf(pb * c_invf[dd + 1], &s1b, &c1b);
                float y10 = acc[i][j][0], y20 = acc[i][j+2][0];
                float y11 = acc[i][j][1], y21 = acc[i][j+2][1];
                uint2 u;
                u = split_bf16x2((y10*c0a - y20*s0a)*sc, (y11*c1a - y21*s1a)*sc);
                dh[bAu + ui] = u.x;     dl[bAu + ui] = u.y;
                u = split_bf16x2((y10*s0a + y20*c0a)*sc, (y11*s1a + y21*c1a)*sc);
                dh[bAu + ui + 8] = u.x; dl[bAu + ui + 8] = u.y;
                float z10 = acc[i][j][2], z20 = acc[i][j+2][2];
                float z11 = acc[i][j][3], z21 = acc[i][j+2][3];
                u = split_bf16x2((z10*c0b - z20*s0b)*sc, (z11*c1b - z21*s1b)*sc);
                dh[bBu + ui] = u.x;     dl[bBu + ui] = u.y;
                u = split_bf16x2((z10*s0b + z20*c0b)*sc, (z11*s1b + z21*c1b)*sc);
                dh[bBu + ui + 8] = u.x; dl[bBu + ui + 8] = u.y;
            }
        }
    }
}

// ---------------------------------------------------------------------------
// Kernel C: out = ao @ proj_w^T + bias. Grid (8, 32). 2 CTAs/SM.
// ---------------------------------------------------------------------------
__global__ __launch_bounds__(256, 2) void proj_mma_kernel(
    const float* __restrict__ bias, float* __restrict__ out)
{
    extern __shared__ uint32_t smu[];
    const int tid = threadIdx.x, lane = tid & 31, wid = tid >> 5;
    const int gid = lane >> 2, tig = lane & 3;
    const int wm = (wid >> 2) * 64, wn = (wid & 3) * 32;
    const int m0 = blockIdx.y * 128, n0 = blockIdx.x * 128;

    float acc[4][4][4];
#pragma unroll
    for (int i = 0; i < 4; ++i)
#pragma unroll
        for (int j = 0; j < 4; ++j)
#pragma unroll
            for (int c = 0; c < 4; ++c) acc[i][j][c] = 0.f;

    gemm_ml(g_aoh, g_aol, g_wph, g_wpl, m0, n0, smu, acc);

#pragma unroll
    for (int i = 0; i < 4; ++i) {
        int mA = m0 + wm + i * 16 + gid;
#pragma unroll
        for (int j = 0; j < 4; ++j) {
            int n = n0 + wn + j * 8 + 2 * tig;
            float b0 = bias[n], b1 = bias[n + 1];
            *(float2*)(out + (size_t)mA * 1024 + n) =
                make_float2(acc[i][j][0] + b0, acc[i][j][1] + b1);
            *(float2*)(out + (size_t)(mA + 8) * 1024 + n) =
                make_float2(acc[i][j][2] + b0, acc[i][j][3] + b1);
        }
    }
}

// ---------------------------------------------------------------------------
// Kernel B: flash attention. Q bf16 frags in regs; K planes via ldmatrix,
// double-buffered with separate V/K commit groups; QK bf16 3-pass; PV tf32.
// ---------------------------------------------------------------------------
#define SKU 36
#define SVS 72
#define SPS 68
#define ATTN_SMEM ((2*2*64*SKU)*4 + (64*SVS)*4 + (4*16*SPS)*4)   // 72704 B

__global__ __launch_bounds__(128) void attn_mma_kernel()
{
    extern __shared__ uint32_t smu[];
    uint32_t* sKh = smu;                      // [2][64*SKU]
    uint32_t* sKl = sKh + 2 * 64 * SKU;       // [2][64*SKU]
    float*    sV  = (float*)(sKl + 2 * 64 * SKU);   // [64][SVS]
    float*    sP  = sV + 64 * SVS;            // [4][16][SPS]
    const uint32_t uKh = smem_u32(sKh), uKl = smem_u32(sKl), uV = smem_u32(sV);

    const int tid = threadIdx.x, lane = tid & 31, wid = tid >> 5;
    const int gid = lane >> 2, tig = lane & 3;
    const int mq = lane >> 3, r = lane & 7;
    const int bh = blockIdx.y, q0 = blockIdx.x * 64;
    const uint32_t kOff = (((mq >> 1) * 8 + r) * SKU + (mq & 1) * 4) * 4;

    const uint32_t* Qh = g_qh + (size_t)(bh * 2048 + q0) * 32;
    const uint32_t* Ql = g_ql + (size_t)(bh * 2048 + q0) * 32;
    const uint32_t* Kh = g_kh + (size_t)bh * 2048 * 32;
    const uint32_t* Kl = g_kl + (size_t)bh * 2048 * 32;
    const float*    Vg = g_v  + (size_t)bh * 2048 * 64;

    uint32_t qh[4][4], ql[4][4];
#pragma unroll
    for (int kc = 0; kc < 4; ++kc) {
#pragma unroll
        for (int e = 0; e < 4; ++e) {
            size_t a = (size_t)(wid * 16 + gid + ((e & 1) ? 8 : 0)) * 32
                     + kc * 8 + tig + ((e & 2) ? 4 : 0);
            qh[kc][e] = Qh[a];
            ql[kc][e] = Ql[a];
        }
    }

#define KPREF(KV0, ST) do {                                                     \
    _Pragma("unroll")                                                           \
    for (int s = 0; s < 4; ++s) {                                               \
        int c = tid + s * 128, row = c >> 3, q = (c & 7) * 4;                   \
        cpa16(uKh + (((ST)*64*SKU) + row*SKU + q)*4, Kh + (size_t)((KV0)+row)*32 + q); \
        cpa16(uKl + (((ST)*64*SKU) + row*SKU + q)*4, Kl + (size_t)((KV0)+row)*32 + q); \
    }                                                                           \
} while (0)

    KPREF(0, 0); CP_COMMIT();

    float o[8][4];
#pragma unroll
    for (int j = 0; j < 8; ++j)
#pragma unroll
        for (int c = 0; c < 4; ++c) o[j][c] = 0.f;
    float m0r = -1e30f, m1r = -1e30f, l0 = 0.f, l1 = 0.f;

    float* wP = sP + wid * 16 * SPS;
    const uint32_t* uPp = (const uint32_t*)wP;
    const uint32_t* uVp = (const uint32_t*)sV;

    for (int it = 0; it < 32; ++it) {
        const int kv0 = it * 64, st = it & 1;
        CP_WAIT0();              // K(it) landed
        __syncthreads();         // prev iteration fully done with sV/sP/stage st

#pragma unroll
        for (int s = 0; s < 8; ++s) {
            int c = tid + s * 128, row = c >> 4, q = (c & 15) * 4;
            cpa16(uV + (row * SVS + q) * 4, Vg + (size_t)(kv0 + row) * 64 + q);
        }
        CP_COMMIT();
        if (it + 1 < 32) { KPREF(kv0 + 64, st ^ 1); }
        CP_COMMIT();

        const uint32_t so = st * 64 * SKU * 4;
        float s8[8][4];
#pragma unroll
        for (int j = 0; j < 8; ++j)
#pragma unroll
            for (int c = 0; c < 4; ++c) s8[j][c] = 0.f;
#pragma unroll
        for (int kc = 0; kc < 4; ++kc) {
#pragma unroll
            for (int jp = 0; jp < 4; ++jp) {
                uint32_t th[4], tl[4];
                ldsm4(th, uKh + so + kOff + (jp * 16 * SKU + kc * 8) * 4);
                ldsm4(tl, uKl + so + kOff + (jp * 16 * SKU + kc * 8) * 4);
                mma16(s8[2*jp],   qh[kc], th);
                mma16(s8[2*jp],   qh[kc], tl);
                mma16(s8[2*jp],   ql[kc], th);
                mma16(s8[2*jp+1], qh[kc], th + 2);
                mma16(s8[2*jp+1], qh[kc], tl + 2);
                mma16(s8[2*jp+1], ql[kc], th + 2);
            }
        }

        CP_WAIT1();              // V(it) landed; K(it+1) still in flight
        __syncthreads();

        float mx0 = -1e30f, mx1 = -1e30f;
#pragma unroll
        for (int j = 0; j < 8; ++j) {
            mx0 = fmaxf(mx0, fmaxf(s8[j][0], s8[j][1]));
            mx1 = fmaxf(mx1, fmaxf(s8[j][2], s8[j][3]));
        }
        mx0 = fmaxf(mx0, __shfl_xor_sync(0xffffffffu, mx0, 1));
        mx0 = fmaxf(mx0, __shfl_xor_sync(0xffffffffu, mx0, 2));
        mx1 = fmaxf(mx1, __shfl_xor_sync(0xffffffffu, mx1, 1));
        mx1 = fmaxf(mx1, __shfl_xor_sync(0xffffffffu, mx1, 2));
        float mn0 = fmaxf(m0r, mx0), mn1 = fmaxf(m1r, mx1);
        float al0 = __expf(m0r - mn0), al1 = __expf(m1r - mn1);
        m0r = mn0; m1r = mn1;
        float sum0 = 0.f, sum1 = 0.f;
#pragma unroll
        for (int j = 0; j < 8; ++j) {
            s8[j][0] = __expf(s8[j][0] - mn0); sum0 += s8[j][0];
            s8[j][1] = __expf(s8[j][1] - mn0); sum0 += s8[j][1];
            s8[j][2] = __expf(s8[j][2] - mn1); sum1 += s8[j][2];
            s8[j][3] = __expf(s8[j][3] - mn1); sum1 += s8[j][3];
        }
        sum0 += __shfl_xor_sync(0xffffffffu, sum0, 1);
        sum0 += __shfl_xor_sync(0xffffffffu, sum0, 2);
        sum1 += __shfl_xor_sync(0xffffffffu, sum1, 1);
        sum1 += __shfl_xor_sync(0xffffffffu, sum1, 2);
        l0 = l0 * al0 + sum0;
        l1 = l1 * al1 + sum1;
#pragma unroll
        for (int j = 0; j < 8; ++j) {
            o[j][0] *= al0; o[j][1] *= al0;
            o[j][2] *= al1; o[j][3] *= al1;
        }

#pragma unroll
        for (int j = 0; j < 8; ++j) {
            *(float2*)(wP + gid * SPS + j * 8 + 2 * tig) =
                make_float2(tf32r(s8[j][0]), tf32r(s8[j][1]));
            *(float2*)(wP + (gid + 8) * SPS + j * 8 + 2 * tig) =
                make_float2(tf32r(s8[j][2]), tf32r(s8[j][3]));
        }
        __syncwarp();

#pragma unroll
        for (int kc = 0; kc < 8; ++kc) {
            uint32_t pa[4];
            int pb = gid * SPS + kc * 8 + tig;
            pa[0] = uPp[pb];     pa[1] = uPp[pb + 8 * SPS];
            pa[2] = uPp[pb + 4]; pa[3] = uPp[pb + 8 * SPS + 4];
#pragma unroll
            for (int j = 0; j < 8; ++j) {
                int vb = (kc * 8 + tig) * SVS + j * 8 + gid;
                uint32_t vv[2] = { uVp[vb], uVp[vb + 4 * SVS] };
                mma8t(o[j], pa, vv);
            }
        }
        __syncwarp();
    }
#undef KPREF

    const float linv0 = 1.f / l0, linv1 = 1.f / l1;
    const int b = bh >> 4, h = bh & 15;
    const int tok0 = q0 + wid * 16 + gid, tok1 = tok0 + 8;
    size_t b0u = (size_t)(b * 2048 + tok0) * 512 + h * 32;
    size_t b1u = (size_t)(b * 2048 + tok1) * 512 + h * 32;
#pragma unroll
    for (int j = 0; j < 8; ++j) {
        int ui = j * 4 + tig;
        uint2 u0 = split_bf16x2(o[j][0] * linv0, o[j][1] * linv0);
        g_aoh[b0u + ui] = u0.x; g_aol[b0u + ui] = u0.y;
        uint2 u1 = split_bf16x2(o[j][2] * linv1, o[j][3] * linv1);
        g_aoh[b1u + ui] = u1.x; g_aol[b1u + ui] = u1.y;
    }
}

// ---------------------------------------------------------------------------
extern "C" void kernel_launch(void* const* d_in, const int* in_sizes, int n_in,
                              void* d_out, int out_size)
{
    const float* x      = (const float*)d_in[0];
    const int*   pos    = (const int*)  d_in[1];
    const float* qkv_w  = (const float*)d_in[2];
    const float* proj_w = (const float*)d_in[3];
    const float* proj_b = (const float*)d_in[4];
    float*       out    = (float*)d_out;

    uint32_t *xh, *xl, *wqh, *wql, *wph, *wpl;
    cudaGetSymbolAddress((void**)&xh,  g_xh);
    cudaGetSymbolAddress((void**)&xl,  g_xl);
    cudaGetSymbolAddress((void**)&wqh, g_wqh);
    cudaGetSymbolAddress((void**)&wql, g_wql);
    cudaGetSymbolAddress((void**)&wph, g_wph);
    cudaGetSymbolAddress((void**)&wpl, g_wpl);

    splitb_kernel<<<(M_*C_/4 + 255)/256, 256>>>((const float4*)x, xh, xl, M_*C_/4);
    splitb_kernel<<<(3*C_*C_/4 + 255)/256, 256>>>((const float4*)qkv_w, wqh, wql, 3*C_*C_/4);
    splitb_kernel<<<(C_*C_/4 + 255)/256, 256>>>((const float4*)proj_w, wph, wpl, C_*C_/4);

    cudaFuncSetAttribute(qkv_mma_kernel,
                         cudaFuncAttributeMaxDynamicSharedMemorySize, GEMM_SMEM);
    cudaFuncSetAttribute(proj_mma_kernel,
                         cudaFuncAttributeMaxDynamicSharedMemorySize, GEMM_SMEM);
    cudaFuncSetAttribute(attn_mma_kernel,
                         cudaFuncAttributeMaxDynamicSharedMemorySize, ATTN_SMEM);

    qkv_mma_kernel<<<dim3(24, 32), 256, GEMM_SMEM>>>(pos);
    attn_mma_kernel<<<dim3(32, 32), 128, ATTN_SMEM>>>();
    proj_mma_kernel<<<dim3(8, 32), 256, GEMM_SMEM>>>(proj_b, out);
}

// round 10
// speedup vs baseline: 2.1713x; 1.0171x over previous
#include <cuda_runtime.h>
#include <math.h>
#include <stdint.h>

#define B_  2
#define N_  2048
#define C_  1024
#define H_  16
#define DH_ 64
#define M_  (B_*N_)
#define BH_ (B_*H_)

// Packed bf16 (hi,lo) planes. u32 = {bf16 k_even | bf16 k_odd<<16}.
__device__ uint32_t g_xh [M_ * 512],      g_xl [M_ * 512];       // x
__device__ uint32_t g_wqh[3 * C_ * 512],  g_wql[3 * C_ * 512];   // qkv_w
__device__ uint32_t g_wph[C_ * 512],      g_wpl[C_ * 512];       // proj_w
__device__ uint32_t g_qh [BH_ * N_ * 32], g_ql [BH_ * N_ * 32];  // q (rope'd, /8)
__device__ uint32_t g_kh [BH_ * N_ * 32], g_kl [BH_ * N_ * 32];  // k (rope'd)
__device__ uint32_t g_aoh[M_ * 512],      g_aol[M_ * 512];       // attn out
__device__ float    g_v  [BH_ * N_ * DH_];                       // v (tf32-rounded)

__constant__ float c_invf[16] = {
    1.0f, 0.7498942093324559f, 0.5623413251903491f, 0.4216965034285822f,
    0.31622776601683794f, 0.23713737056616552f, 0.1778279410038923f,
    0.13335214321633237f, 0.1f, 0.07498942093324558f, 0.05623413251903491f,
    0.04216965034285822f, 0.031622776601683794f, 0.023713737056616552f,
    0.01778279410038923f, 0.013335214321633237f
};

__device__ __forceinline__ float tf32r(float x) {
    uint32_t u;
    asm("cvt.rna.tf32.f32 %0, %1;" : "=r"(u) : "f"(x));
    return __uint_as_float(u);
}
__device__ __forceinline__ uint2 split_bf16x2(float x0, float x1) {
    uint32_t hp, lp;
    asm("cvt.rn.bf16x2.f32 %0, %1, %2;" : "=r"(hp) : "f"(x1), "f"(x0));
    float h0 = __uint_as_float(hp << 16);
    float h1 = __uint_as_float(hp & 0xffff0000u);
    float l0 = x0 - h0, l1 = x1 - h1;
    asm("cvt.rn.bf16x2.f32 %0, %1, %2;" : "=r"(lp) : "f"(l1), "f"(l0));
    return make_uint2(hp, lp);
}
__device__ __forceinline__ void mma16(float* d, const uint32_t* a, const uint32_t* b) {
    asm volatile(
        "mma.sync.aligned.m16n8k16.row.col.f32.bf16.bf16.f32 "
        "{%0,%1,%2,%3}, {%4,%5,%6,%7}, {%8,%9}, {%0,%1,%2,%3};"
        : "+f"(d[0]), "+f"(d[1]), "+f"(d[2]), "+f"(d[3])
        : "r"(a[0]), "r"(a[1]), "r"(a[2]), "r"(a[3]), "r"(b[0]), "r"(b[1]));
}
__device__ __forceinline__ void mma8t(float* d, const uint32_t* a, const uint32_t* b) {
    asm volatile(
        "mma.sync.aligned.m16n8k8.row.col.f32.tf32.tf32.f32 "
        "{%0,%1,%2,%3}, {%4,%5,%6,%7}, {%8,%9}, {%0,%1,%2,%3};"
        : "+f"(d[0]), "+f"(d[1]), "+f"(d[2]), "+f"(d[3])
        : "r"(a[0]), "r"(a[1]), "r"(a[2]), "r"(a[3]), "r"(b[0]), "r"(b[1]));
}
__device__ __forceinline__ void ldsm4(uint32_t* d, uint32_t a) {
    asm volatile("ldmatrix.sync.aligned.m8n8.x4.shared.b16 {%0,%1,%2,%3}, [%4];"
        : "=r"(d[0]), "=r"(d[1]), "=r"(d[2]), "=r"(d[3]) : "r"(a));
}
__device__ __forceinline__ uint32_t smem_u32(const void* p) {
    uint32_t a;
    asm("{ .reg .u64 t; cvta.to.shared.u64 t, %1; cvt.u32.u64 %0, t; }"
        : "=r"(a) : "l"(p));
    return a;
}
__device__ __forceinline__ void cpa16(uint32_t dst, const void* src) {
    asm volatile("cp.async.ca.shared.global [%0], [%1], 16;" :: "r"(dst), "l"(src));
}
#define CP_COMMIT() asm volatile("cp.async.commit_group;" ::: "memory")
#define CP_WAIT0()  asm volatile("cp.async.wait_group 0;" ::: "memory")
#define CP_WAIT1()  asm volatile("cp.async.wait_group 1;" ::: "memory")

// ---------------------------------------------------------------------------
__global__ __launch_bounds__(256) void splitb_kernel(
    const float4* __restrict__ src, uint32_t* __restrict__ dh,
    uint32_t* __restrict__ dl, int n4)
{
    int i = blockIdx.x * blockDim.x + threadIdx.x;
    if (i < n4) {
        float4 v = src[i];
        uint2 p0 = split_bf16x2(v.x, v.y);
        uint2 p1 = split_bf16x2(v.z, v.w);
        *(uint2*)(dh + 2 * i) = make_uint2(p0.x, p1.x);
        *(uint2*)(dl + 2 * i) = make_uint2(p0.y, p1.y);
    }
}

// ===========================================================================
// GEMM mainloop. Pass-major mma ordering over i-pairs: accumulator reuse
// distance 8 mmas (vs 1 before) -> HMMA latency hidden. Per-acc add order
// unchanged (hh, hl, lh) -> bit-identical results.
// ===========================================================================
#define SG 20
#define GEMM_SMEM (4 * 2 * 128 * SG * 4)             // 81920 B

__device__ __forceinline__ void gemm_ml(
    const uint32_t* __restrict__ Ah, const uint32_t* __restrict__ Al,
    const uint32_t* __restrict__ Bh, const uint32_t* __restrict__ Bl,
    int m0, int n0, uint32_t* smu, float acc[4][4][4])
{
    uint32_t* sAh = smu;
    uint32_t* sAl = sAh + 2 * 128 * SG;
    uint32_t* sBh = sAl + 2 * 128 * SG;
    uint32_t* sBl = sBh + 2 * 128 * SG;
    const uint32_t uAh = smem_u32(sAh), uAl = smem_u32(sAl);
    const uint32_t uBh = smem_u32(sBh), uBl = smem_u32(sBl);

    const int tid = threadIdx.x, lane = tid & 31, wid = tid >> 5;
    const int wm = (wid >> 2) * 64, wn = (wid & 3) * 32;
    const int mq = lane >> 3, r = lane & 7;
    const uint32_t aOff = ((wm + (mq & 1) * 8 + r) * SG + (mq >> 1) * 4) * 4;
    const uint32_t bOff = ((wn + (mq >> 1) * 8 + r) * SG + (mq & 1) * 4) * 4;

#define GPREF(IT, ST) do {                                                      \
    int _ko = (IT) * 16;                                                        \
    _Pragma("unroll")                                                           \
    for (int s = 0; s < 2; ++s) {                                               \
        int c = tid + s * 256, row = c >> 2, q = (c & 3) * 4;                   \
        cpa16(uAh + (((ST)*128*SG) + row*SG + q)*4, Ah + (size_t)(m0+row)*512 + _ko + q); \
        cpa16(uAl + (((ST)*128*SG) + row*SG + q)*4, Al + (size_t)(m0+row)*512 + _ko + q); \
        cpa16(uBh + (((ST)*128*SG) + row*SG + q)*4, Bh + (size_t)(n0+row)*512 + _ko + q); \
        cpa16(uBl + (((ST)*128*SG) + row*SG + q)*4, Bl + (size_t)(n0+row)*512 + _ko + q); \
    }                                                                           \
} while (0)

    GPREF(0, 0); CP_COMMIT();

    for (int it = 0; it < 32; ++it) {
        const int st = it & 1;
        CP_WAIT0();
        __syncthreads();
        if (it + 1 < 32) { GPREF(it + 1, st ^ 1); CP_COMMIT(); }

        const uint32_t so = st * 128 * SG * 4;
#pragma unroll
        for (int kc = 0; kc < 2; ++kc) {
            uint32_t bh[4][2], bl[4][2];
#pragma unroll
            for (int jp = 0; jp < 2; ++jp) {
                uint32_t t[4];
                ldsm4(t, uBh + so + bOff + (jp * 16 * SG + kc * 8) * 4);
                bh[2*jp][0] = t[0]; bh[2*jp][1] = t[1];
                bh[2*jp+1][0] = t[2]; bh[2*jp+1][1] = t[3];
                ldsm4(t, uBl + so + bOff + (jp * 16 * SG + kc * 8) * 4);
                bl[2*jp][0] = t[0]; bl[2*jp][1] = t[1];
                bl[2*jp+1][0] = t[2]; bl[2*jp+1][1] = t[3];
            }
#pragma unroll
            for (int ip = 0; ip < 2; ++ip) {
                uint32_t ah[2][4], al[2][4];
                ldsm4(ah[0], uAh + so + aOff + ((ip*2)   * 16 * SG + kc * 8) * 4);
                ldsm4(ah[1], uAh + so + aOff + ((ip*2+1) * 16 * SG + kc * 8) * 4);
                ldsm4(al[0], uAl + so + aOff + ((ip*2)   * 16 * SG + kc * 8) * 4);
                ldsm4(al[1], uAl + so + aOff + ((ip*2+1) * 16 * SG + kc * 8) * 4);
                // pass 1: hh  (8 independent mmas)
#pragma unroll
                for (int i2 = 0; i2 < 2; ++i2)
#pragma unroll
                    for (int j = 0; j < 4; ++j)
                        mma16(acc[ip*2+i2][j], ah[i2], bh[j]);
                // pass 2: hl
#pragma unroll
                for (int i2 = 0; i2 < 2; ++i2)
#pragma unroll
                    for (int j = 0; j < 4; ++j)
                        mma16(acc[ip*2+i2][j], ah[i2], bl[j]);
                // pass 3: lh
#pragma unroll
                for (int i2 = 0; i2 < 2; ++i2)
#pragma unroll
                    for (int j = 0; j < 4; ++j)
                        mma16(acc[ip*2+i2][j], al[i2], bh[j]);
            }
        }
    }
#undef GPREF
}

// ---------------------------------------------------------------------------
// Kernel A: qkv GEMM + RoPE; q/k packed bf16 planes, v tf32 f32. Grid (24,32).
// ---------------------------------------------------------------------------
__global__ __launch_bounds__(256, 2) void qkv_mma_kernel(const int* __restrict__ pos)
{
    extern __shared__ uint32_t smu[];
    const int tid = threadIdx.x, lane = tid & 31, wid = tid >> 5;
    const int gid = lane >> 2, tig = lane & 3;
    const int wm = (wid >> 2) * 64, wn = (wid & 3) * 32;
    const int m0 = blockIdx.y * 128, n0 = blockIdx.x * 128;

    float acc[4][4][4];
#pragma unroll
    for (int i = 0; i < 4; ++i)
#pragma unroll
        for (int j = 0; j < 4; ++j)
#pragma unroll
            for (int c = 0; c < 4; ++c) acc[i][j][c] = 0.f;

    gemm_ml(g_xh, g_xl, g_wqh, g_wql, m0, n0, smu, acc);

    const int which = n0 >> 10;                    // 0=q 1=k 2=v
    const int h  = (((n0 & 1023) + wn) >> 6);
    const int db = wn & 32;
    const float sc = (which == 0) ? 0.125f : 1.f;
    uint32_t* dh = (which == 0) ? g_qh : g_kh;
    uint32_t* dl = (which == 0) ? g_ql : g_kl;

#pragma unroll
    for (int i = 0; i < 4; ++i) {
        int mA = m0 + wm + i * 16 + gid;
        int mB = mA + 8;
        int rowA = ((mA >> 11) * 16 + h) * 2048 + (mA & 2047);
        int rowB = ((mB >> 11) * 16 + h) * 2048 + (mB & 2047);
        if (which == 2) {
            float* oA = g_v + ((size_t)rowA << 6);
            float* oB = g_v + ((size_t)rowB << 6);
#pragma unroll
            for (int j = 0; j < 4; ++j) {
                int d = db + j * 8 + 2 * tig;
                *(float2*)(oA + d) = make_float2(tf32r(acc[i][j][0]), tf32r(acc[i][j][1]));
                *(float2*)(oB + d) = make_float2(tf32r(acc[i][j][2]), tf32r(acc[i][j][3]));
            }
        } else {
            size_t bAu = (size_t)rowA * 32 + (db >> 1);
            size_t bBu = (size_t)rowB * 32 + (db >> 1);
            int2 pA = ((const int2*)pos)[mA];
            int2 pB = ((const int2*)pos)[mB];
            float pa = db ? (float)pA.y : (float)pA.x;
            float pb = db ? (float)pB.y : (float)pB.x;
#pragma unroll
            for (int j = 0; j < 2; ++j) {
                int dd = j * 8 + 2 * tig;
                int ui = j * 4 + tig;
                float s0a,c0a,s1a,c1a,s0b,c0b,s1b,c1b;
                sincosf(pa * c_invf[dd],     &s0a, &c0a);
                sincosf(pa * c_invf[dd + 1], &s1a, &c1a);
                sincosf(pb * c_invf[dd],     &s0b, &c0b);
                sincosf(pb * c_invf[dd + 1], &s1b, &c1b);
                float y10 = acc[i][j][0], y20 = acc[i][j+2][0];
                float y11 = acc[i][j][1], y21 = acc[i][j+2][1];
                uint2 u;
                u = split_bf16x2((y10*c0a - y20*s0a)*sc, (y11*c1a - y21*s1a)*sc);
                dh[bAu + ui] = u.x;     dl[bAu + ui] = u.y;
                u = split_bf16x2((y10*s0a + y20*c0a)*sc, (y11*s1a + y21*c1a)*sc);
                dh[bAu + ui + 8] = u.x; dl[bAu + ui + 8] = u.y;
                float z10 = acc[i][j][2], z20 = acc[i][j+2][2];
                float z11 = acc[i][j][3], z21 = acc[i][j+2][3];
                u = split_bf16x2((z10*c0b - z20*s0b)*sc, (z11*c1b - z21*s1b)*sc);
                dh[bBu + ui] = u.x;     dl[bBu + ui] = u.y;
                u = split_bf16x2((z10*s0b + z20*c0b)*sc, (z11*s1b + z21*c1b)*sc);
                dh[bBu + ui + 8] = u.x; dl[bBu + ui + 8] = u.y;
            }
        }
    }
}

// ---------------------------------------------------------------------------
// Kernel C: out = ao @ proj_w^T + bias. Grid (8, 32). 2 CTAs/SM.
// ---------------------------------------------------------------------------
__global__ __launch_bounds__(256, 2) void proj_mma_kernel(
    const float* __restrict__ bias, float* __restrict__ out)
{
    extern __shared__ uint32_t smu[];
    const int tid = threadIdx.x, lane = tid & 31, wid = tid >> 5;
    const int gid = lane >> 2, tig = lane & 3;
    const int wm = (wid >> 2) * 64, wn = (wid & 3) * 32;
    const int m0 = blockIdx.y * 128, n0 = blockIdx.x * 128;

    float acc[4][4][4];
#pragma unroll
    for (int i = 0; i < 4; ++i)
#pragma unroll
        for (int j = 0; j < 4; ++j)
#pragma unroll
            for (int c = 0; c < 4; ++c) acc[i][j][c] = 0.f;

    gemm_ml(g_aoh, g_aol, g_wph, g_wpl, m0, n0, smu, acc);

#pragma unroll
    for (int i = 0; i < 4; ++i) {
        int mA = m0 + wm + i * 16 + gid;
#pragma unroll
        for (int j = 0; j < 4; ++j) {
            int n = n0 + wn + j * 8 + 2 * tig;
            float b0 = bias[n], b1 = bias[n + 1];
            *(float2*)(out + (size_t)mA * 1024 + n) =
                make_float2(acc[i][j][0] + b0, acc[i][j][1] + b1);
            *(float2*)(out + (size_t)(mA + 8) * 1024 + n) =
                make_float2(acc[i][j][2] + b0, acc[i][j][3] + b1);
        }
    }
}

// ---------------------------------------------------------------------------
// Kernel B: flash attention. QK pass-major across all 4 jp fragments
// (reuse distance 8); K planes double-buffered; PV tf32 (8 indep accs).
// ---------------------------------------------------------------------------
#define SKU 36
#define SVS 72
#define SPS 68
#define ATTN_SMEM ((2*2*64*SKU)*4 + (64*SVS)*4 + (4*16*SPS)*4)   // 72704 B

__global__ __launch_bounds__(128) void attn_mma_kernel()
{
    extern __shared__ uint32_t smu[];
    uint32_t* sKh = smu;
    uint32_t* sKl = sKh + 2 * 64 * SKU;
    float*    sV  = (float*)(sKl + 2 * 64 * SKU);
    float*    sP  = sV + 64 * SVS;
    const uint32_t uKh = smem_u32(sKh), uKl = smem_u32(sKl), uV = smem_u32(sV);

    const int tid = threadIdx.x, lane = tid & 31, wid = tid >> 5;
    const int gid = lane >> 2, tig = lane & 3;
    const int mq = lane >> 3, r = lane & 7;
    const int bh = blockIdx.y, q0 = blockIdx.x * 64;
    const uint32_t kOff = (((mq >> 1) * 8 + r) * SKU + (mq & 1) * 4) * 4;

    const uint32_t* Qh = g_qh + (size_t)(bh * 2048 + q0) * 32;
    const uint32_t* Ql = g_ql + (size_t)(bh * 2048 + q0) * 32;
    const uint32_t* Kh = g_kh + (size_t)bh * 2048 * 32;
    const uint32_t* Kl = g_kl + (size_t)bh * 2048 * 32;
    const float*    Vg = g_v  + (size_t)bh * 2048 * 64;

    uint32_t qh[4][4], ql[4][4];
#pragma unroll
    for (int kc = 0; kc < 4; ++kc) {
#pragma unroll
        for (int e = 0; e < 4; ++e) {
            size_t a = (size_t)(wid * 16 + gid + ((e & 1) ? 8 : 0)) * 32
                     + kc * 8 + tig + ((e & 2) ? 4 : 0);
            qh[kc][e] = Qh[a];
            ql[kc][e] = Ql[a];
        }
    }

#define KPREF(KV0, ST) do {                                                     \
    _Pragma("unroll")                                                           \
    for (int s = 0; s < 4; ++s) {                                               \
        int c = tid + s * 128, row = c >> 3, q = (c & 7) * 4;                   \
        cpa16(uKh + (((ST)*64*SKU) + row*SKU + q)*4, Kh + (size_t)((KV0)+row)*32 + q); \
        cpa16(uKl + (((ST)*64*SKU) + row*SKU + q)*4, Kl + (size_t)((KV0)+row)*32 + q); \
    }                                                                           \
} while (0)

    KPREF(0, 0); CP_COMMIT();

    float o[8][4];
#pragma unroll
    for (int j = 0; j < 8; ++j)
#pragma unroll
        for (int c = 0; c < 4; ++c) o[j][c] = 0.f;
    float m0r = -1e30f, m1r = -1e30f, l0 = 0.f, l1 = 0.f;

    float* wP = sP + wid * 16 * SPS;
    const uint32_t* uPp = (const uint32_t*)wP;
    const uint32_t* uVp = (const uint32_t*)sV;

    for (int it = 0; it < 32; ++it) {
        const int kv0 = it * 64, st = it & 1;
        CP_WAIT0();
        __syncthreads();

#pragma unroll
        for (int s = 0; s < 8; ++s) {
            int c = tid + s * 128, row = c >> 4, q = (c & 15) * 4;
            cpa16(uV + (row * SVS + q) * 4, Vg + (size_t)(kv0 + row) * 64 + q);
        }
        CP_COMMIT();
        if (it + 1 < 32) { KPREF(kv0 + 64, st ^ 1); }
        CP_COMMIT();

        const uint32_t so = st * 64 * SKU * 4;
        float s8[8][4];
#pragma unroll
        for (int j = 0; j < 8; ++j)
#pragma unroll
            for (int c = 0; c < 4; ++c) s8[j][c] = 0.f;
#pragma unroll
        for (int kc = 0; kc < 4; ++kc) {
            uint32_t th[4][4], tl[4][4];
#pragma unroll
            for (int jp = 0; jp < 4; ++jp) {
                ldsm4(th[jp], uKh + so + kOff + (jp * 16 * SKU + kc * 8) * 4);
                ldsm4(tl[jp], uKl + so + kOff + (jp * 16 * SKU + kc * 8) * 4);
            }
            // pass 1: qh*th (8 independent)
#pragma unroll
            for (int jp = 0; jp < 4; ++jp) {
                mma16(s8[2*jp],   qh[kc], th[jp]);
                mma16(s8[2*jp+1], qh[kc], th[jp] + 2);
            }
            // pass 2: qh*tl
#pragma unroll
            for (int jp = 0; jp < 4; ++jp) {
                mma16(s8[2*jp],   qh[kc], tl[jp]);
                mma16(s8[2*jp+1], qh[kc], tl[jp] + 2);
            }
            // pass 3: ql*th
#pragma unroll
            for (int jp = 0; jp < 4; ++jp) {
                mma16(s8[2*jp],   ql[kc], th[jp]);
                mma16(s8[2*jp+1], ql[kc], th[jp] + 2);
            }
        }

        CP_WAIT1();
        __syncthreads();

        float mx0 = -1e30f, mx1 = -1e30f;
#pragma unroll
        for (int j = 0; j < 8; ++j) {
            mx0 = fmaxf(mx0, fmaxf(s8[j][0], s8[j][1]));
            mx1 = fmaxf(mx1, fmaxf(s8[j][2], s8[j][3]));
        }
        mx0 = fmaxf(mx0, __shfl_xor_sync(0xffffffffu, mx0, 1));
        mx0 = fmaxf(mx0, __shfl_xor_sync(0xffffffffu, mx0, 2));
        mx1 = fmaxf(mx1, __shfl_xor_sync(0xffffffffu, mx1, 1));
        mx1 = fmaxf(mx1, __shfl_xor_sync(0xffffffffu, mx1, 2));
        float mn0 = fmaxf(m0r, mx0), mn1 = fmaxf(m1r, mx1);
        float al0 = __expf(m0r - mn0), al1 = __expf(m1r - mn1);
        m0r = mn0; m1r = mn1;
        float sum0 = 0.f, sum1 = 0.f;
#pragma unroll
        for (int j = 0; j < 8; ++j) {
            s8[j][0] = __expf(s8[j][0] - mn0); sum0 += s8[j][0];
            s8[j][1] = __expf(s8[j][1] - mn0); sum0 += s8[j][1];
            s8[j][2] = __expf(s8[j][2] - mn1); sum1 += s8[j][2];
            s8[j][3] = __expf(s8[j][3] - mn1); sum1 += s8[j][3];
        }
        sum0 += __shfl_xor_sync(0xffffffffu, sum0, 1);
        sum0 += __shfl_xor_sync(0xffffffffu, sum0, 2);
        sum1 += __shfl_xor_sync(0xffffffffu, sum1, 1);
        sum1 += __shfl_xor_sync(0xffffffffu, sum1, 2);
        l0 = l0 * al0 + sum0;
        l1 = l1 * al1 + sum1;
#pragma unroll
        for (int j = 0; j < 8; ++j) {
            o[j][0] *= al0; o[j][1] *= al0;
            o[j][2] *= al1; o[j][3] *= al1;
        }

#pragma unroll
        for (int j = 0; j < 8; ++j) {
            *(float2*)(wP + gid * SPS + j * 8 + 2 * tig) =
                make_float2(tf32r(s8[j][0]), tf32r(s8[j][1]));
            *(float2*)(wP + (gid + 8) * SPS + j * 8 + 2 * tig) =
                make_float2(tf32r(s8[j][2]), tf32r(s8[j][3]));
        }
        __syncwarp();

#pragma unroll
        for (int kc = 0; kc < 8; ++kc) {
            uint32_t pa[4];
            int pb = gid * SPS + kc * 8 + tig;
            pa[0] = uPp[pb];     pa[1] = uPp[pb + 8 * SPS];
            pa[2] = uPp[pb + 4]; pa[3] = uPp[pb + 8 * SPS + 4];
#pragma unroll
            for (int j = 0; j < 8; ++j) {
                int vb = (kc * 8 + tig) * SVS + j * 8 + gid;
                uint32_t vv[2] = { uVp[vb], uVp[vb + 4 * SVS] };
                mma8t(o[j], pa, vv);
            }
        }
        __syncwarp();
    }
#undef KPREF

    const float linv0 = 1.f / l0, linv1 = 1.f / l1;
    const int b = bh >> 4, h = bh & 15;
    const int tok0 = q0 + wid * 16 + gid, tok1 = tok0 + 8;
    size_t b0u = (size_t)(b * 2048 + tok0) * 512 + h * 32;
    size_t b1u = (size_t)(b * 2048 + tok1) * 512 + h * 32;
#pragma unroll
    for (int j = 0; j < 8; ++j) {
        int ui = j * 4 + tig;
        uint2 u0 = split_bf16x2(o[j][0] * linv0, o[j][1] * linv0);
        g_aoh[b0u + ui] = u0.x; g_aol[b0u + ui] = u0.y;
        uint2 u1 = split_bf16x2(o[j][2] * linv1, o[j][3] * linv1);
        g_aoh[b1u + ui] = u1.x; g_aol[b1u + ui] = u1.y;
    }
}

// ---------------------------------------------------------------------------
extern "C" void kernel_launch(void* const* d_in, const int* in_sizes, int n_in,
                              void* d_out, int out_size)
{
    const float* x      = (const float*)d_in[0];
    const int*   pos    = (const int*)  d_in[1];
    const float* qkv_w  = (const float*)d_in[2];
    const float* proj_w = (const float*)d_in[3];
    const float* proj_b = (const float*)d_in[4];
    float*       out    = (float*)d_out;

    uint32_t *xh, *xl, *wqh, *wql, *wph, *wpl;
    cudaGetSymbolAddress((void**)&xh,  g_xh);
    cudaGetSymbolAddress((void**)&xl,  g_xl);
    cudaGetSymbolAddress((void**)&wqh, g_wqh);
    cudaGetSymbolAddress((void**)&wql, g_wql);
    cudaGetSymbolAddress((void**)&wph, g_wph);
    cudaGetSymbolAddress((void**)&wpl, g_wpl);

    splitb_kernel<<<(M_*C_/4 + 255)/256, 256>>>((const float4*)x, xh, xl, M_*C_/4);
    splitb_kernel<<<(3*C_*C_/4 + 255)/256, 256>>>((const float4*)qkv_w, wqh, wql, 3*C_*C_/4);
    splitb_kernel<<<(C_*C_/4 + 255)/256, 256>>>((const float4*)proj_w, wph, wpl, C_*C_/4);

    cudaFuncSetAttribute(qkv_mma_kernel,
                         cudaFuncAttributeMaxDynamicSharedMemorySize, GEMM_SMEM);
    cudaFuncSetAttribute(proj_mma_kernel,
                         cudaFuncAttributeMaxDynamicSharedMemorySize, GEMM_SMEM);
    cudaFuncSetAttribute(attn_mma_kernel,
                         cudaFuncAttributeMaxDynamicSharedMemorySize, ATTN_SMEM);

    qkv_mma_kernel<<<dim3(24, 32), 256, GEMM_SMEM>>>(pos);
    attn_mma_kernel<<<dim3(32, 32), 128, ATTN_SMEM>>>();
    proj_mma_kernel<<<dim3(8, 32), 256, GEMM_SMEM>>>(proj_b, out);
}

// round 13
// speedup vs baseline: 2.5705x; 1.1838x over previous
#include <cuda_runtime.h>
#include <math.h>
#include <stdint.h>

#define B_  2
#define N_  2048
#define C_  1024
#define H_  16
#define DH_ 64
#define M_  (B_*N_)
#define BH_ (B_*H_)

// Packed bf16 (hi,lo) planes. u32 = {bf16 k_even | bf16 k_odd<<16}.
__device__ uint32_t g_xh [M_ * 512],      g_xl [M_ * 512];       // x
__device__ uint32_t g_wqh[3 * C_ * 512],  g_wql[3 * C_ * 512];   // qkv_w
__device__ uint32_t g_wph[C_ * 512],      g_wpl[C_ * 512];       // proj_w
__device__ uint32_t g_qh [BH_ * N_ * 32], g_ql [BH_ * N_ * 32];  // q (rope'd, /8)
__device__ uint32_t g_kh [BH_ * N_ * 32], g_kl [BH_ * N_ * 32];  // k (rope'd)
__device__ uint32_t g_aoh[M_ * 512],      g_aol[M_ * 512];       // attn out
__device__ uint32_t g_v  [BH_ * N_ * 32];                        // v (fp16x2 packed)

__constant__ float c_invf[16] = {
    1.0f, 0.7498942093324559f, 0.5623413251903491f, 0.4216965034285822f,
    0.31622776601683794f, 0.23713737056616552f, 0.1778279410038923f,
    0.13335214321633237f, 0.1f, 0.07498942093324558f, 0.05623413251903491f,
    0.04216965034285822f, 0.031622776601683794f, 0.023713737056616552f,
    0.01778279410038923f, 0.013335214321633237f
};

__device__ __forceinline__ float tf32r(float x) {
    uint32_t u;
    asm("cvt.rna.tf32.f32 %0, %1;" : "=r"(u) : "f"(x));
    return __uint_as_float(u);
}
__device__ __forceinline__ uint32_t f16x2(float x0, float x1) {   // lo=x0, hi=x1
    uint32_t p;
    asm("cvt.rn.f16x2.f32 %0, %1, %2;" : "=r"(p) : "f"(x1), "f"(x0));
    return p;
}
__device__ __forceinline__ uint2 split_bf16x2(float x0, float x1) {
    uint32_t hp, lp;
    asm("cvt.rn.bf16x2.f32 %0, %1, %2;" : "=r"(hp) : "f"(x1), "f"(x0));
    float h0 = __uint_as_float(hp << 16);
    float h1 = __uint_as_float(hp & 0xffff0000u);
    float l0 = x0 - h0, l1 = x1 - h1;
    asm("cvt.rn.bf16x2.f32 %0, %1, %2;" : "=r"(lp) : "f"(l1), "f"(l0));
    return make_uint2(hp, lp);
}
__device__ __forceinline__ void mma16(float* d, const uint32_t* a, const uint32_t* b) {
    asm volatile(
        "mma.sync.aligned.m16n8k16.row.col.f32.bf16.bf16.f32 "
        "{%0,%1,%2,%3}, {%4,%5,%6,%7}, {%8,%9}, {%0,%1,%2,%3};"
        : "+f"(d[0]), "+f"(d[1]), "+f"(d[2]), "+f"(d[3])
        : "r"(a[0]), "r"(a[1]), "r"(a[2]), "r"(a[3]), "r"(b[0]), "r"(b[1]));
}
__device__ __forceinline__ void mma16f(float* d, const uint32_t* a, const uint32_t* b) {
    asm volatile(
        "mma.sync.aligned.m16n8k16.row.col.f32.f16.f16.f32 "
        "{%0,%1,%2,%3}, {%4,%5,%6,%7}, {%8,%9}, {%0,%1,%2,%3};"
        : "+f"(d[0]), "+f"(d[1]), "+f"(d[2]), "+f"(d[3])
        : "r"(a[0]), "r"(a[1]), "r"(a[2]), "r"(a[3]), "r"(b[0]), "r"(b[1]));
}
__device__ __forceinline__ void ldsm4(uint32_t* d, uint32_t a) {
    asm volatile("ldmatrix.sync.aligned.m8n8.x4.shared.b16 {%0,%1,%2,%3}, [%4];"
        : "=r"(d[0]), "=r"(d[1]), "=r"(d[2]), "=r"(d[3]) : "r"(a));
}
__device__ __forceinline__ void ldsm4t(uint32_t* d, uint32_t a) {
    asm volatile("ldmatrix.sync.aligned.m8n8.x4.trans.shared.b16 {%0,%1,%2,%3}, [%4];"
        : "=r"(d[0]), "=r"(d[1]), "=r"(d[2]), "=r"(d[3]) : "r"(a));
}
__device__ __forceinline__ uint32_t smem_u32(const void* p) {
    uint32_t a;
    asm("{ .reg .u64 t; cvta.to.shared.u64 t, %1; cvt.u32.u64 %0, t; }"
        : "=r"(a) : "l"(p));
    return a;
}
__device__ __forceinline__ void cpa16(uint32_t dst, const void* src) {
    asm volatile("cp.async.ca.shared.global [%0], [%1], 16;" :: "r"(dst), "l"(src));
}
#define CP_COMMIT() asm volatile("cp.async.commit_group;" ::: "memory")
#define CP_WAIT0()  asm volatile("cp.async.wait_group 0;" ::: "memory")
#define CP_WAIT1()  asm volatile("cp.async.wait_group 1;" ::: "memory")

// ---------------------------------------------------------------------------
__global__ __launch_bounds__(256) void splitb_kernel(
    const float4* __restrict__ src, uint32_t* __restrict__ dh,
    uint32_t* __restrict__ dl, int n4)
{
    int i = blockIdx.x * blockDim.x + threadIdx.x;
    if (i < n4) {
        float4 v = src[i];
        uint2 p0 = split_bf16x2(v.x, v.y);
        uint2 p1 = split_bf16x2(v.z, v.w);
        *(uint2*)(dh + 2 * i) = make_uint2(p0.x, p1.x);
        *(uint2*)(dl + 2 * i) = make_uint2(p0.y, p1.y);
    }
}

// ===========================================================================
// GEMM mainloop (unchanged from round 10).
// ===========================================================================
#define SG 20
#define GEMM_SMEM (4 * 2 * 128 * SG * 4)             // 81920 B

__device__ __forceinline__ void gemm_ml(
    const uint32_t* __restrict__ Ah, const uint32_t* __restrict__ Al,
    const uint32_t* __restrict__ Bh, const uint32_t* __restrict__ Bl,
    int m0, int n0, uint32_t* smu, float acc[4][4][4])
{
    uint32_t* sAh = smu;
    uint32_t* sAl = sAh + 2 * 128 * SG;
    uint32_t* sBh = sAl + 2 * 128 * SG;
    uint32_t* sBl = sBh + 2 * 128 * SG;
    const uint32_t uAh = smem_u32(sAh), uAl = smem_u32(sAl);
    const uint32_t uBh = smem_u32(sBh), uBl = smem_u32(sBl);

    const int tid = threadIdx.x, lane = tid & 31, wid = tid >> 5;
    const int wm = (wid >> 2) * 64, wn = (wid & 3) * 32;
    const int mq = lane >> 3, r = lane & 7;
    const uint32_t aOff = ((wm + (mq & 1) * 8 + r) * SG + (mq >> 1) * 4) * 4;
    const uint32_t bOff = ((wn + (mq >> 1) * 8 + r) * SG + (mq & 1) * 4) * 4;

#define GPREF(IT, ST) do {                                                      \
    int _ko = (IT) * 16;                                                        \
    _Pragma("unroll")                                                           \
    for (int s = 0; s < 2; ++s) {                                               \
        int c = tid + s * 256, row = c >> 2, q = (c & 3) * 4;                   \
        cpa16(uAh + (((ST)*128*SG) + row*SG + q)*4, Ah + (size_t)(m0+row)*512 + _ko + q); \
        cpa16(uAl + (((ST)*128*SG) + row*SG + q)*4, Al + (size_t)(m0+row)*512 + _ko + q); \
        cpa16(uBh + (((ST)*128*SG) + row*SG + q)*4, Bh + (size_t)(n0+row)*512 + _ko + q); \
        cpa16(uBl + (((ST)*128*SG) + row*SG + q)*4, Bl + (size_t)(n0+row)*512 + _ko + q); \
    }                                                                           \
} while (0)

    GPREF(0, 0); CP_COMMIT();

    for (int it = 0; it < 32; ++it) {
        const int st = it & 1;
        CP_WAIT0();
        __syncthreads();
        if (it + 1 < 32) { GPREF(it + 1, st ^ 1); CP_COMMIT(); }

        const uint32_t so = st * 128 * SG * 4;
#pragma unroll
        for (int kc = 0; kc < 2; ++kc) {
            uint32_t bh[4][2], bl[4][2];
#pragma unroll
            for (int jp = 0; jp < 2; ++jp) {
                uint32_t t[4];
                ldsm4(t, uBh + so + bOff + (jp * 16 * SG + kc * 8) * 4);
                bh[2*jp][0] = t[0]; bh[2*jp][1] = t[1];
                bh[2*jp+1][0] = t[2]; bh[2*jp+1][1] = t[3];
                ldsm4(t, uBl + so + bOff + (jp * 16 * SG + kc * 8) * 4);
                bl[2*jp][0] = t[0]; bl[2*jp][1] = t[1];
                bl[2*jp+1][0] = t[2]; bl[2*jp+1][1] = t[3];
            }
#pragma unroll
            for (int ip = 0; ip < 2; ++ip) {
                uint32_t ah[2][4], al[2][4];
                ldsm4(ah[0], uAh + so + aOff + ((ip*2)   * 16 * SG + kc * 8) * 4);
                ldsm4(ah[1], uAh + so + aOff + ((ip*2+1) * 16 * SG + kc * 8) * 4);
                ldsm4(al[0], uAl + so + aOff + ((ip*2)   * 16 * SG + kc * 8) * 4);
                ldsm4(al[1], uAl + so + aOff + ((ip*2+1) * 16 * SG + kc * 8) * 4);
#pragma unroll
                for (int i2 = 0; i2 < 2; ++i2)
#pragma unroll
                    for (int j = 0; j < 4; ++j)
                        mma16(acc[ip*2+i2][j], ah[i2], bh[j]);
#pragma unroll
                for (int i2 = 0; i2 < 2; ++i2)
#pragma unroll
                    for (int j = 0; j < 4; ++j)
                        mma16(acc[ip*2+i2][j], ah[i2], bl[j]);
#pragma unroll
                for (int i2 = 0; i2 < 2; ++i2)
#pragma unroll
                    for (int j = 0; j < 4; ++j)
                        mma16(acc[ip*2+i2][j], al[i2], bh[j]);
            }
        }
    }
#undef GPREF
}

// ---------------------------------------------------------------------------
// Kernel A: qkv GEMM + RoPE; q/k bf16 planes, v fp16x2. Grid (24,32).
// ---------------------------------------------------------------------------
__global__ __launch_bounds__(256, 2) void qkv_mma_kernel(const int* __restrict__ pos)
{
    extern __shared__ uint32_t smu[];
    const int tid = threadIdx.x, lane = tid & 31, wid = tid >> 5;
    const int gid = lane >> 2, tig = lane & 3;
    const int wm = (wid >> 2) * 64, wn = (wid & 3) * 32;
    const int m0 = blockIdx.y * 128, n0 = blockIdx.x * 128;

    float acc[4][4][4];
#pragma unroll
    for (int i = 0; i < 4; ++i)
#pragma unroll
        for (int j = 0; j < 4; ++j)
#pragma unroll
            for (int c = 0; c < 4; ++c) acc[i][j][c] = 0.f;

    gemm_ml(g_xh, g_xl, g_wqh, g_wql, m0, n0, smu, acc);

    const int which = n0 >> 10;                    // 0=q 1=k 2=v
    const int h  = (((n0 & 1023) + wn) >> 6);
    const int db = wn & 32;
    const float sc = (which == 0) ? 0.125f : 1.f;
    uint32_t* dh = (which == 0) ? g_qh : g_kh;
    uint32_t* dl = (which == 0) ? g_ql : g_kl;

#pragma unroll
    for (int i = 0; i < 4; ++i) {
        int mA = m0 + wm + i * 16 + gid;
        int mB = mA + 8;
        int rowA = ((mA >> 11) * 16 + h) * 2048 + (mA & 2047);
        int rowB = ((mB >> 11) * 16 + h) * 2048 + (mB & 2047);
        if (which == 2) {
            size_t bAu = (size_t)rowA * 32 + (db >> 1);
            size_t bBu = (size_t)rowB * 32 + (db >> 1);
#pragma unroll
            for (int j = 0; j < 4; ++j) {
                int ui = j * 4 + tig;
                g_v[bAu + ui] = f16x2(acc[i][j][0], acc[i][j][1]);
                g_v[bBu + ui] = f16x2(acc[i][j][2], acc[i][j][3]);
            }
        } else {
            size_t bAu = (size_t)rowA * 32 + (db >> 1);
            size_t bBu = (size_t)rowB * 32 + (db >> 1);
            int2 pA = ((const int2*)pos)[mA];
            int2 pB = ((const int2*)pos)[mB];
            float pa = db ? (float)pA.y : (float)pA.x;
            float pb = db ? (float)pB.y : (float)pB.x;
#pragma unroll
            for (int j = 0; j < 2; ++j) {
                int dd = j * 8 + 2 * tig;
                int ui = j * 4 + tig;
                float s0a,c0a,s1a,c1a,s0b,c0b,s1b,c1b;
                sincosf(pa * c_invf[dd],     &s0a, &c0a);
                sincosf(pa * c_invf[dd + 1], &s1a, &c1a);
                sincosf(pb * c_invf[dd],     &s0b, &c0b);
                sincosf(pb * c_invf[dd + 1], &s1b, &c1b);
                float y10 = acc[i][j][0], y20 = acc[i][j+2][0];
                float y11 = acc[i][j][1], y21 = acc[i][j+2][1];
                uint2 u;
                u = split_bf16x2((y10*c0a - y20*s0a)*sc, (y11*c1a - y21*s1a)*sc);
                dh[bAu + ui] = u.x;     dl[bAu + ui] = u.y;
                u = split_bf16x2((y10*s0a + y20*c0a)*sc, (y11*s1a + y21*c1a)*sc);
                dh[bAu + ui + 8] = u.x; dl[bAu + ui + 8] = u.y;
                float z10 = acc[i][j][2], z20 = acc[i][j+2][2];
                float z11 = acc[i][j][3], z21 = acc[i][j+2][3];
                u = split_bf16x2((z10*c0b - z20*s0b)*sc, (z11*c1b - z21*s1b)*sc);
                dh[bBu + ui] = u.x;     dl[bBu + ui] = u.y;
                u = split_bf16x2((z10*s0b + z20*c0b)*sc, (z11*s1b + z21*c1b)*sc);
                dh[bBu + ui + 8] = u.x; dl[bBu + ui + 8] = u.y;
            }
        }
    }
}

// ---------------------------------------------------------------------------
// Kernel C: out = ao @ proj_w^T + bias. Grid (8, 32). 2 CTAs/SM.
// ---------------------------------------------------------------------------
__global__ __launch_bounds__(256, 2) void proj_mma_kernel(
    const float* __restrict__ bias, float* __restrict__ out)
{
    extern __shared__ uint32_t smu[];
    const int tid = threadIdx.x, lane = tid & 31, wid = tid >> 5;
    const int gid = lane >> 2, tig = lane & 3;
    const int wm = (wid >> 2) * 64, wn = (wid & 3) * 32;
    const int m0 = blockIdx.y * 128, n0 = blockIdx.x * 128;

    float acc[4][4][4];
#pragma unroll
    for (int i = 0; i < 4; ++i)
#pragma unroll
        for (int j = 0; j < 4; ++j)
#pragma unroll
            for (int c = 0; c < 4; ++c) acc[i][j][c] = 0.f;

    gemm_ml(g_aoh, g_aol, g_wph, g_wpl, m0, n0, smu, acc);

#pragma unroll
    for (int i = 0; i < 4; ++i) {
        int mA = m0 + wm + i * 16 + gid;
#pragma unroll
        for (int j = 0; j < 4; ++j) {
            int n = n0 + wn + j * 8 + 2 * tig;
            float b0 = bias[n], b1 = bias[n + 1];
            *(float2*)(out + (size_t)mA * 1024 + n) =
                make_float2(acc[i][j][0] + b0, acc[i][j][1] + b1);
            *(float2*)(out + (size_t)(mA + 8) * 1024 + n) =
                make_float2(acc[i][j][2] + b0, acc[i][j][3] + b1);
        }
    }
}

// ---------------------------------------------------------------------------
// Kernel B: flash attention. QK bf16 3-pass pass-major; P kept in registers
// (D-frag == A-frag layout) as fp16; PV fp16 with V B-frags via ldmatrix.trans.
// No P smem round-trip. smem 46KB -> 4 CTAs/SM.
// ---------------------------------------------------------------------------
#define SKU 36
#define SVU 36   // u32 stride for fp16 V rows (64 fp16 = 32 u32 + 4 pad)
#define ATTN_SMEM ((2*2*64*SKU + 64*SVU) * 4)        // 46080 B

__global__ __launch_bounds__(128, 4) void attn_mma_kernel()
{
    extern __shared__ uint32_t smu[];
    uint32_t* sKh = smu;                      // [2][64*SKU]
    uint32_t* sKl = sKh + 2 * 64 * SKU;       // [2][64*SKU]
    uint32_t* sV  = sKl + 2 * 64 * SKU;       // [64][SVU] fp16x2
    const uint32_t uKh = smem_u32(sKh), uKl = smem_u32(sKl), uV = smem_u32(sV);

    const int tid = threadIdx.x, lane = tid & 31, wid = tid >> 5;
    const int gid = lane >> 2, tig = lane & 3;
    const int mq = lane >> 3, r = lane & 7;
    const int bh = blockIdx.y, q0 = blockIdx.x * 64;
    const uint32_t kOff = (((mq >> 1) * 8 + r) * SKU + (mq & 1) * 4) * 4;
    // V ldsm.trans per-lane offset: tile = lane>>3 (0..3), row-in-tile = r
    //   t0: kv rows 0-7 @ d0      t1: kv 8-15 @ d0
    //   t2: kv 0-7   @ d0+8      t3: kv 8-15 @ d0+8
    const uint32_t vOff = (((lane >> 3) & 1) * 8 + r) * SVU * 4 + ((lane >> 4) * 8) * 2;

    const uint32_t* Qh = g_qh + (size_t)(bh * 2048 + q0) * 32;
    const uint32_t* Ql = g_ql + (size_t)(bh * 2048 + q0) * 32;
    const uint32_t* Kh = g_kh + (size_t)bh * 2048 * 32;
    const uint32_t* Kl = g_kl + (size_t)bh * 2048 * 32;
    const uint32_t* Vg = g_v  + (size_t)bh * 2048 * 32;

    uint32_t qh[4][4], ql[4][4];
#pragma unroll
    for (int kc = 0; kc < 4; ++kc) {
#pragma unroll
        for (int e = 0; e < 4; ++e) {
            size_t a = (size_t)(wid * 16 + gid + ((e & 1) ? 8 : 0)) * 32
                     + kc * 8 + tig + ((e & 2) ? 4 : 0);
            qh[kc][e] = Qh[a];
            ql[kc][e] = Ql[a];
        }
    }

#define KPREF(KV0, ST) do {                                                     \
    _Pragma("unroll")                                                           \
    for (int s = 0; s < 4; ++s) {                                               \
        int c = tid + s * 128, row = c >> 3, q = (c & 7) * 4;                   \
        cpa16(uKh + (((ST)*64*SKU) + row*SKU + q)*4, Kh + (size_t)((KV0)+row)*32 + q); \
        cpa16(uKl + (((ST)*64*SKU) + row*SKU + q)*4, Kl + (size_t)((KV0)+row)*32 + q); \
    }                                                                           \
} while (0)

    KPREF(0, 0); CP_COMMIT();

    float o[8][4];
#pragma unroll
    for (int j = 0; j < 8; ++j)
#pragma unroll
        for (int c = 0; c < 4; ++c) o[j][c] = 0.f;
    float m0r = -1e30f, m1r = -1e30f, l0 = 0.f, l1 = 0.f;

    for (int it = 0; it < 32; ++it) {
        const int kv0 = it * 64, st = it & 1;
        CP_WAIT0();              // K(it) landed
        __syncthreads();         // prev iter done with sV / stage st

        // V(it) fp16x2 into sV: 64 rows x 32 u32 (own group)
#pragma unroll
        for (int s = 0; s < 4; ++s) {
            int c = tid + s * 128, row = c >> 3, q = (c & 7) * 4;
            cpa16(uV + (row * SVU + q) * 4, Vg + (size_t)(kv0 + row) * 32 + q);
        }
        CP_COMMIT();
        if (it + 1 < 32) { KPREF(kv0 + 64, st ^ 1); }
        CP_COMMIT();

        // S = (Q/8) K^T, bf16 3-pass pass-major
        const uint32_t so = st * 64 * SKU * 4;
        float s8[8][4];
#pragma unroll
        for (int j = 0; j < 8; ++j)
#pragma unroll
            for (int c = 0; c < 4; ++c) s8[j][c] = 0.f;
#pragma unroll
        for (int kc = 0; kc < 4; ++kc) {
            uint32_t th[4][4], tl[4][4];
#pragma unroll
            for (int jp = 0; jp < 4; ++jp) {
                ldsm4(th[jp], uKh + so + kOff + (jp * 16 * SKU + kc * 8) * 4);
                ldsm4(tl[jp], uKl + so + kOff + (jp * 16 * SKU + kc * 8) * 4);
            }
#pragma unroll
            for (int jp = 0; jp < 4; ++jp) {
                mma16(s8[2*jp],   qh[kc], th[jp]);
                mma16(s8[2*jp+1], qh[kc], th[jp] + 2);
            }
#pragma unroll
            for (int jp = 0; jp < 4; ++jp) {
                mma16(s8[2*jp],   qh[kc], tl[jp]);
                mma16(s8[2*jp+1], qh[kc], tl[jp] + 2);
            }
#pragma unroll
            for (int jp = 0; jp < 4; ++jp) {
                mma16(s8[2*jp],   ql[kc], th[jp]);
                mma16(s8[2*jp+1], ql[kc], th[jp] + 2);
            }
        }

        CP_WAIT1();              // V(it) landed; K(it+1) still in flight
        __syncthreads();

        // online softmax (rows gid, gid+8)
        float mx0 = -1e30f, mx1 = -1e30f;
#pragma unroll
        for (int j = 0; j < 8; ++j) {
            mx0 = fmaxf(mx0, fmaxf(s8[j][0], s8[j][1]));
            mx1 = fmaxf(mx1, fmaxf(s8[j][2], s8[j][3]));
        }
        mx0 = fmaxf(mx0, __shfl_xor_sync(0xffffffffu, mx0, 1));
        mx0 = fmaxf(mx0, __shfl_xor_sync(0xffffffffu, mx0, 2));
        mx1 = fmaxf(mx1, __shfl_xor_sync(0xffffffffu, mx1, 1));
        mx1 = fmaxf(mx1, __shfl_xor_sync(0xffffffffu, mx1, 2));
        float mn0 = fmaxf(m0r, mx0), mn1 = fmaxf(m1r, mx1);
        float al0 = __expf(m0r - mn0), al1 = __expf(m1r - mn1);
        m0r = mn0; m1r = mn1;
        float sum0 = 0.f, sum1 = 0.f;
#pragma unroll
        for (int j = 0; j < 8; ++j) {
            s8[j][0] = __expf(s8[j][0] - mn0); sum0 += s8[j][0];
            s8[j][1] = __expf(s8[j][1] - mn0); sum0 += s8[j][1];
            s8[j][2] = __expf(s8[j][2] - mn1); sum1 += s8[j][2];
            s8[j][3] = __expf(s8[j][3] - mn1); sum1 += s8[j][3];
        }
        sum0 += __shfl_xor_sync(0xffffffffu, sum0, 1);
        sum0 += __shfl_xor_sync(0xffffffffu, sum0, 2);
        sum1 += __shfl_xor_sync(0xffffffffu, sum1, 1);
        sum1 += __shfl_xor_sync(0xffffffffu, sum1, 2);
        l0 = l0 * al0 + sum0;
        l1 = l1 * al1 + sum1;
#pragma unroll
        for (int j = 0; j < 8; ++j) {
            o[j][0] *= al0; o[j][1] *= al0;
            o[j][2] *= al1; o[j][3] *= al1;
        }

        // O += P V : P fp16 from registers (D-frag == A-frag), V via ldsm.trans
#pragma unroll
        for (int kc = 0; kc < 4; ++kc) {
            uint32_t pa[4];
            pa[0] = f16x2(s8[2*kc][0],   s8[2*kc][1]);     // row gid,   k 2tig..
            pa[1] = f16x2(s8[2*kc][2],   s8[2*kc][3]);     // row gid+8
            pa[2] = f16x2(s8[2*kc+1][0], s8[2*kc+1][1]);   // row gid,   k+8
            pa[3] = f16x2(s8[2*kc+1][2], s8[2*kc+1][3]);   // row gid+8, k+8
#pragma unroll
            for (int dp = 0; dp < 4; ++dp) {
                uint32_t t[4];
                ldsm4t(t, uV + vOff + kc * 16 * SVU * 4 + dp * 32);
                mma16f(o[2*dp],   pa, t);
                mma16f(o[2*dp+1], pa, t + 2);
            }
        }
    }
#undef KPREF

    const float linv0 = 1.f / l0, linv1 = 1.f / l1;
    const int b = bh >> 4, h = bh & 15;
    const int tok0 = q0 + wid * 16 + gid, tok1 = tok0 + 8;
    size_t b0u = (size_t)(b * 2048 + tok0) * 512 + h * 32;
    size_t b1u = (size_t)(b * 2048 + tok1) * 512 + h * 32;
#pragma unroll
    for (int j = 0; j < 8; ++j) {
        int ui = j * 4 + tig;
        uint2 u0 = split_bf16x2(o[j][0] * linv0, o[j][1] * linv0);
        g_aoh[b0u + ui] = u0.x; g_aol[b0u + ui] = u0.y;
        uint2 u1 = split_bf16x2(o[j][2] * linv1, o[j][3] * linv1);
        g_aoh[b1u + ui] = u1.x; g_aol[b1u + ui] = u1.y;
    }
}

// ---------------------------------------------------------------------------
extern "C" void kernel_launch(void* const* d_in, const int* in_sizes, int n_in,
                              void* d_out, int out_size)
{
    const float* x      = (const float*)d_in[0];
    const int*   pos    = (const int*)  d_in[1];
    const float* qkv_w  = (const float*)d_in[2];
    const float* proj_w = (const float*)d_in[3];
    const float* proj_b = (const float*)d_in[4];
    float*       out    = (float*)d_out;

    uint32_t *xh, *xl, *wqh, *wql, *wph, *wpl;
    cudaGetSymbolAddress((void**)&xh,  g_xh);
    cudaGetSymbolAddress((void**)&xl,  g_xl);
    cudaGetSymbolAddress((void**)&wqh, g_wqh);
    cudaGetSymbolAddress((void**)&wql, g_wql);
    cudaGetSymbolAddress((void**)&wph, g_wph);
    cudaGetSymbolAddress((void**)&wpl, g_wpl);

    splitb_kernel<<<(M_*C_/4 + 255)/256, 256>>>((const float4*)x, xh, xl, M_*C_/4);
    splitb_kernel<<<(3*C_*C_/4 + 255)/256, 256>>>((const float4*)qkv_w, wqh, wql, 3*C_*C_/4);
    splitb_kernel<<<(C_*C_/4 + 255)/256, 256>>>((const float4*)proj_w, wph, wpl, C_*C_/4);

    cudaFuncSetAttribute(qkv_mma_kernel,
                         cudaFuncAttributeMaxDynamicSharedMemorySize, GEMM_SMEM);
    cudaFuncSetAttribute(proj_mma_kernel,
                         cudaFuncAttributeMaxDynamicSharedMemorySize, GEMM_SMEM);
    cudaFuncSetAttribute(attn_mma_kernel,
                         cudaFuncAttributeMaxDynamicSharedMemorySize, ATTN_SMEM);

    qkv_mma_kernel<<<dim3(24, 32), 256, GEMM_SMEM>>>(pos);
    attn_mma_kernel<<<dim3(32, 32), 128, ATTN_SMEM>>>();
    proj_mma_kernel<<<dim3(8, 32), 256, GEMM_SMEM>>>(proj_b, out);
}

// round 14
// speedup vs baseline: 3.4135x; 1.3280x over previous
#include <cuda_runtime.h>
#include <cuda_fp16.h>
#include <math.h>
#include <stdint.h>

#define B_  2
#define N_  2048
#define C_  1024
#define H_  16
#define DH_ 64
#define M_  (B_*N_)
#define BH_ (B_*H_)

// Packed fp16 planes. u32 = {f16 k_even | f16 k_odd<<16}.
// A-sides are single-plane (hi only, one-sided 2-pass); B-sides are (hi,lo).
__device__ uint32_t g_xh [M_ * 512];                             // x (A)
__device__ uint32_t g_wqh[3 * C_ * 512],  g_wql[3 * C_ * 512];   // qkv_w (B)
__device__ uint32_t g_wph[C_ * 512],      g_wpl[C_ * 512];       // proj_w (B)
__device__ uint32_t g_qh [BH_ * N_ * 32];                        // q /8 (A)
__device__ uint32_t g_kh [BH_ * N_ * 32], g_kl [BH_ * N_ * 32];  // k (B)
__device__ uint32_t g_aoh[M_ * 512];                             // attn out (A)
__device__ uint32_t g_v  [BH_ * N_ * 32];                        // v (fp16x2)

__constant__ float c_invf[16] = {
    1.0f, 0.7498942093324559f, 0.5623413251903491f, 0.4216965034285822f,
    0.31622776601683794f, 0.23713737056616552f, 0.1778279410038923f,
    0.13335214321633237f, 0.1f, 0.07498942093324558f, 0.05623413251903491f,
    0.04216965034285822f, 0.031622776601683794f, 0.023713737056616552f,
    0.01778279410038923f, 0.013335214321633237f
};

__device__ __forceinline__ uint32_t f16x2(float x0, float x1) {   // lo=x0, hi=x1
    uint32_t p;
    asm("cvt.rn.f16x2.f32 %0, %1, %2;" : "=r"(p) : "f"(x1), "f"(x0));
    return p;
}
__device__ __forceinline__ uint2 split_f16x2(float x0, float x1) {
    uint32_t hp;
    asm("cvt.rn.f16x2.f32 %0, %1, %2;" : "=r"(hp) : "f"(x1), "f"(x0));
    __half2 h = *(__half2*)&hp;
    float l0 = x0 - __low2float(h), l1 = x1 - __high2float(h);
    uint32_t lp;
    asm("cvt.rn.f16x2.f32 %0, %1, %2;" : "=r"(lp) : "f"(l1), "f"(l0));
    return make_uint2(hp, lp);
}
__device__ __forceinline__ void mma16f(float* d, const uint32_t* a, const uint32_t* b) {
    asm volatile(
        "mma.sync.aligned.m16n8k16.row.col.f32.f16.f16.f32 "
        "{%0,%1,%2,%3}, {%4,%5,%6,%7}, {%8,%9}, {%0,%1,%2,%3};"
        : "+f"(d[0]), "+f"(d[1]), "+f"(d[2]), "+f"(d[3])
        : "r"(a[0]), "r"(a[1]), "r"(a[2]), "r"(a[3]), "r"(b[0]), "r"(b[1]));
}
__device__ __forceinline__ void ldsm4(uint32_t* d, uint32_t a) {
    asm volatile("ldmatrix.sync.aligned.m8n8.x4.shared.b16 {%0,%1,%2,%3}, [%4];"
        : "=r"(d[0]), "=r"(d[1]), "=r"(d[2]), "=r"(d[3]) : "r"(a));
}
__device__ __forceinline__ void ldsm4t(uint32_t* d, uint32_t a) {
    asm volatile("ldmatrix.sync.aligned.m8n8.x4.trans.shared.b16 {%0,%1,%2,%3}, [%4];"
        : "=r"(d[0]), "=r"(d[1]), "=r"(d[2]), "=r"(d[3]) : "r"(a));
}
__device__ __forceinline__ uint32_t smem_u32(const void* p) {
    uint32_t a;
    asm("{ .reg .u64 t; cvta.to.shared.u64 t, %1; cvt.u32.u64 %0, t; }"
        : "=r"(a) : "l"(p));
    return a;
}
__device__ __forceinline__ void cpa16(uint32_t dst, const void* src) {
    asm volatile("cp.async.ca.shared.global [%0], [%1], 16;" :: "r"(dst), "l"(src));
}
#define CP_COMMIT() asm volatile("cp.async.commit_group;" ::: "memory")
#define CP_WAIT0()  asm volatile("cp.async.wait_group 0;" ::: "memory")
#define CP_WAIT1()  asm volatile("cp.async.wait_group 1;" ::: "memory")

// ---------------------------------------------------------------------------
// Split kernels: f32 -> fp16 (hi,lo) planes  /  f32 -> fp16 hi-only plane
// ---------------------------------------------------------------------------
__global__ __launch_bounds__(256) void splitw_kernel(
    const float4* __restrict__ src, uint32_t* __restrict__ dh,
    uint32_t* __restrict__ dl, int n4)
{
    int i = blockIdx.x * blockDim.x + threadIdx.x;
    if (i < n4) {
        float4 v = src[i];
        uint2 p0 = split_f16x2(v.x, v.y);
        uint2 p1 = split_f16x2(v.z, v.w);
        *(uint2*)(dh + 2 * i) = make_uint2(p0.x, p1.x);
        *(uint2*)(dl + 2 * i) = make_uint2(p0.y, p1.y);
    }
}
__global__ __launch_bounds__(256) void splith_kernel(
    const float4* __restrict__ src, uint32_t* __restrict__ dh, int n4)
{
    int i = blockIdx.x * blockDim.x + threadIdx.x;
    if (i < n4) {
        float4 v = src[i];
        *(uint2*)(dh + 2 * i) = make_uint2(f16x2(v.x, v.y), f16x2(v.z, v.w));
    }
}

// ===========================================================================
// GEMM mainloop: warp 64x32 of D[128x128] = A[m0:128,:1024] @ B[n0:128,:1024]^T
// fp16 one-sided 2-pass: ah*bh + ah*bl (A truncated to fp16, B split hi/lo).
// 3 smem planes, cp.async 2-stage, ldmatrix, pass-major. 256 thr (2m x 4n).
// ===========================================================================
#define SG 20
#define GEMM_SMEM (3 * 2 * 128 * SG * 4)             // 61440 B

__device__ __forceinline__ void gemm_ml(
    const uint32_t* __restrict__ Ah,
    const uint32_t* __restrict__ Bh, const uint32_t* __restrict__ Bl,
    int m0, int n0, uint32_t* smu, float acc[4][4][4])
{
    uint32_t* sAh = smu;
    uint32_t* sBh = sAh + 2 * 128 * SG;
    uint32_t* sBl = sBh + 2 * 128 * SG;
    const uint32_t uAh = smem_u32(sAh), uBh = smem_u32(sBh), uBl = smem_u32(sBl);

    const int tid = threadIdx.x, lane = tid & 31, wid = tid >> 5;
    const int wm = (wid >> 2) * 64, wn = (wid & 3) * 32;
    const int mq = lane >> 3, r = lane & 7;
    const uint32_t aOff = ((wm + (mq & 1) * 8 + r) * SG + (mq >> 1) * 4) * 4;
    const uint32_t bOff = ((wn + (mq >> 1) * 8 + r) * SG + (mq & 1) * 4) * 4;

#define GPREF(IT, ST) do {                                                      \
    int _ko = (IT) * 16;                                                        \
    _Pragma("unroll")                                                           \
    for (int s = 0; s < 2; ++s) {                                               \
        int c = tid + s * 256, row = c >> 2, q = (c & 3) * 4;                   \
        cpa16(uAh + (((ST)*128*SG) + row*SG + q)*4, Ah + (size_t)(m0+row)*512 + _ko + q); \
        cpa16(uBh + (((ST)*128*SG) + row*SG + q)*4, Bh + (size_t)(n0+row)*512 + _ko + q); \
        cpa16(uBl + (((ST)*128*SG) + row*SG + q)*4, Bl + (size_t)(n0+row)*512 + _ko + q); \
    }                                                                           \
} while (0)

    GPREF(0, 0); CP_COMMIT();

    for (int it = 0; it < 32; ++it) {
        const int st = it & 1;
        CP_WAIT0();
        __syncthreads();
        if (it + 1 < 32) { GPREF(it + 1, st ^ 1); CP_COMMIT(); }

        const uint32_t so = st * 128 * SG * 4;
#pragma unroll
        for (int kc = 0; kc < 2; ++kc) {
            uint32_t bh[4][2], bl[4][2];
#pragma unroll
            for (int jp = 0; jp < 2; ++jp) {
                uint32_t t[4];
                ldsm4(t, uBh + so + bOff + (jp * 16 * SG + kc * 8) * 4);
                bh[2*jp][0] = t[0]; bh[2*jp][1] = t[1];
                bh[2*jp+1][0] = t[2]; bh[2*jp+1][1] = t[3];
                ldsm4(t, uBl + so + bOff + (jp * 16 * SG + kc * 8) * 4);
                bl[2*jp][0] = t[0]; bl[2*jp][1] = t[1];
                bl[2*jp+1][0] = t[2]; bl[2*jp+1][1] = t[3];
            }
            uint32_t ah[4][4];
#pragma unroll
            for (int i = 0; i < 4; ++i)
                ldsm4(ah[i], uAh + so + aOff + (i * 16 * SG + kc * 8) * 4);
            // pass 1: ah*bh (16 independent)
#pragma unroll
            for (int i = 0; i < 4; ++i)
#pragma unroll
                for (int j = 0; j < 4; ++j)
                    mma16f(acc[i][j], ah[i], bh[j]);
            // pass 2: ah*bl
#pragma unroll
            for (int i = 0; i < 4; ++i)
#pragma unroll
                for (int j = 0; j < 4; ++j)
                    mma16f(acc[i][j], ah[i], bl[j]);
        }
    }
#undef GPREF
}

// ---------------------------------------------------------------------------
// Kernel A: qkv GEMM + RoPE; q fp16 hi-only (/8), k fp16 (hi,lo), v fp16.
// Grid (24, 32), 2 CTAs/SM.
// ---------------------------------------------------------------------------
__global__ __launch_bounds__(256, 2) void qkv_mma_kernel(const int* __restrict__ pos)
{
    extern __shared__ uint32_t smu[];
    const int tid = threadIdx.x, lane = tid & 31, wid = tid >> 5;
    const int gid = lane >> 2, tig = lane & 3;
    const int wm = (wid >> 2) * 64, wn = (wid & 3) * 32;
    const int m0 = blockIdx.y * 128, n0 = blockIdx.x * 128;

    float acc[4][4][4];
#pragma unroll
    for (int i = 0; i < 4; ++i)
#pragma unroll
        for (int j = 0; j < 4; ++j)
#pragma unroll
            for (int c = 0; c < 4; ++c) acc[i][j][c] = 0.f;

    gemm_ml(g_xh, g_wqh, g_wql, m0, n0, smu, acc);

    const int which = n0 >> 10;                    // 0=q 1=k 2=v
    const int h  = (((n0 & 1023) + wn) >> 6);
    const int db = wn & 32;

#pragma unroll
    for (int i = 0; i < 4; ++i) {
        int mA = m0 + wm + i * 16 + gid;
        int mB = mA + 8;
        int rowA = ((mA >> 11) * 16 + h) * 2048 + (mA & 2047);
        int rowB = ((mB >> 11) * 16 + h) * 2048 + (mB & 2047);
        size_t bAu = (size_t)rowA * 32 + (db >> 1);
        size_t bBu = (size_t)rowB * 32 + (db >> 1);
        if (which == 2) {
#pragma unroll
            for (int j = 0; j < 4; ++j) {
                int ui = j * 4 + tig;
                g_v[bAu + ui] = f16x2(acc[i][j][0], acc[i][j][1]);
                g_v[bBu + ui] = f16x2(acc[i][j][2], acc[i][j][3]);
            }
        } else {
            int2 pA = ((const int2*)pos)[mA];
            int2 pB = ((const int2*)pos)[mB];
            float pa = db ? (float)pA.y : (float)pA.x;
            float pb = db ? (float)pB.y : (float)pB.x;
            const float sc = (which == 0) ? 0.125f : 1.f;
#pragma unroll
            for (int j = 0; j < 2; ++j) {
                int dd = j * 8 + 2 * tig;
                int ui = j * 4 + tig;
                float s0a,c0a,s1a,c1a,s0b,c0b,s1b,c1b;
                sincosf(pa * c_invf[dd],     &s0a, &c0a);
                sincosf(pa * c_invf[dd + 1], &s1a, &c1a);
                sincosf(pb * c_invf[dd],     &s0b, &c0b);
                sincosf(pb * c_invf[dd + 1], &s1b, &c1b);
                float y10 = acc[i][j][0], y20 = acc[i][j+2][0];
                float y11 = acc[i][j][1], y21 = acc[i][j+2][1];
                float a0 = (y10*c0a - y20*s0a)*sc, a1 = (y11*c1a - y21*s1a)*sc;
                float a2 = (y10*s0a + y20*c0a)*sc, a3 = (y11*s1a + y21*c1a)*sc;
                float z10 = acc[i][j][2], z20 = acc[i][j+2][2];
                float z11 = acc[i][j][3], z21 = acc[i][j+2][3];
                float b0 = (z10*c0b - z20*s0b)*sc, b1 = (z11*c1b - z21*s1b)*sc;
                float b2 = (z10*s0b + z20*c0b)*sc, b3 = (z11*s1b + z21*c1b)*sc;
                if (which == 0) {          // q: single fp16 plane
                    g_qh[bAu + ui]     = f16x2(a0, a1);
                    g_qh[bAu + ui + 8] = f16x2(a2, a3);
                    g_qh[bBu + ui]     = f16x2(b0, b1);
                    g_qh[bBu + ui + 8] = f16x2(b2, b3);
                } else {                   // k: split (hi,lo)
                    uint2 u;
                    u = split_f16x2(a0, a1); g_kh[bAu + ui]     = u.x; g_kl[bAu + ui]     = u.y;
                    u = split_f16x2(a2, a3); g_kh[bAu + ui + 8] = u.x; g_kl[bAu + ui + 8] = u.y;
                    u = split_f16x2(b0, b1); g_kh[bBu + ui]     = u.x; g_kl[bBu + ui]     = u.y;
                    u = split_f16x2(b2, b3); g_kh[bBu + ui + 8] = u.x; g_kl[bBu + ui + 8] = u.y;
                }
            }
        }
    }
}

// ---------------------------------------------------------------------------
// Kernel C: out = ao @ proj_w^T + bias. Grid (8, 32). 2 CTAs/SM.
// ---------------------------------------------------------------------------
__global__ __launch_bounds__(256, 2) void proj_mma_kernel(
    const float* __restrict__ bias, float* __restrict__ out)
{
    extern __shared__ uint32_t smu[];
    const int tid = threadIdx.x, lane = tid & 31, wid = tid >> 5;
    const int gid = lane >> 2, tig = lane & 3;
    const int wm = (wid >> 2) * 64, wn = (wid & 3) * 32;
    const int m0 = blockIdx.y * 128, n0 = blockIdx.x * 128;

    float acc[4][4][4];
#pragma unroll
    for (int i = 0; i < 4; ++i)
#pragma unroll
        for (int j = 0; j < 4; ++j)
#pragma unroll
            for (int c = 0; c < 4; ++c) acc[i][j][c] = 0.f;

    gemm_ml(g_aoh, g_wph, g_wpl, m0, n0, smu, acc);

#pragma unroll
    for (int i = 0; i < 4; ++i) {
        int mA = m0 + wm + i * 16 + gid;
#pragma unroll
        for (int j = 0; j < 4; ++j) {
            int n = n0 + wn + j * 8 + 2 * tig;
            float b0 = bias[n], b1 = bias[n + 1];
            *(float2*)(out + (size_t)mA * 1024 + n) =
                make_float2(acc[i][j][0] + b0, acc[i][j][1] + b1);
            *(float2*)(out + (size_t)(mA + 8) * 1024 + n) =
                make_float2(acc[i][j][2] + b0, acc[i][j][3] + b1);
        }
    }
}

// ---------------------------------------------------------------------------
// Kernel B: flash attention. Q fp16 single-plane frags in regs; QK fp16
// 2-pass (qh*kh + qh*kl); P in registers as fp16; PV fp16 via ldsm.trans.
// smem 46KB -> 4 CTAs/SM.
// ---------------------------------------------------------------------------
#define SKU 36
#define SVU 36
#define ATTN_SMEM ((2*2*64*SKU + 64*SVU) * 4)        // 46080 B

__global__ __launch_bounds__(128, 4) void attn_mma_kernel()
{
    extern __shared__ uint32_t smu[];
    uint32_t* sKh = smu;
    uint32_t* sKl = sKh + 2 * 64 * SKU;
    uint32_t* sV  = sKl + 2 * 64 * SKU;
    const uint32_t uKh = smem_u32(sKh), uKl = smem_u32(sKl), uV = smem_u32(sV);

    const int tid = threadIdx.x, lane = tid & 31, wid = tid >> 5;
    const int gid = lane >> 2, tig = lane & 3;
    const int mq = lane >> 3, r = lane & 7;
    const int bh = blockIdx.y, q0 = blockIdx.x * 64;
    const uint32_t kOff = (((mq >> 1) * 8 + r) * SKU + (mq & 1) * 4) * 4;
    const uint32_t vOff = (((lane >> 3) & 1) * 8 + r) * SVU * 4 + ((lane >> 4) * 8) * 2;

    const uint32_t* Qh = g_qh + (size_t)(bh * 2048 + q0) * 32;
    const uint32_t* Kh = g_kh + (size_t)bh * 2048 * 32;
    const uint32_t* Kl = g_kl + (size_t)bh * 2048 * 32;
    const uint32_t* Vg = g_v  + (size_t)bh * 2048 * 32;

    uint32_t qh[4][4];
#pragma unroll
    for (int kc = 0; kc < 4; ++kc) {
#pragma unroll
        for (int e = 0; e < 4; ++e) {
            size_t a = (size_t)(wid * 16 + gid + ((e & 1) ? 8 : 0)) * 32
                     + kc * 8 + tig + ((e & 2) ? 4 : 0);
            qh[kc][e] = Qh[a];
        }
    }

#define KPREF(KV0, ST) do {                                                     \
    _Pragma("unroll")                                                           \
    for (int s = 0; s < 4; ++s) {                                               \
        int c = tid + s * 128, row = c >> 3, q = (c & 7) * 4;                   \
        cpa16(uKh + (((ST)*64*SKU) + row*SKU + q)*4, Kh + (size_t)((KV0)+row)*32 + q); \
        cpa16(uKl + (((ST)*64*SKU) + row*SKU + q)*4, Kl + (size_t)((KV0)+row)*32 + q); \
    }                                                                           \
} while (0)

    KPREF(0, 0); CP_COMMIT();

    float o[8][4];
#pragma unroll
    for (int j = 0; j < 8; ++j)
#pragma unroll
        for (int c = 0; c < 4; ++c) o[j][c] = 0.f;
    float m0r = -1e30f, m1r = -1e30f, l0 = 0.f, l1 = 0.f;

    for (int it = 0; it < 32; ++it) {
        const int kv0 = it * 64, st = it & 1;
        CP_WAIT0();
        __syncthreads();

#pragma unroll
        for (int s = 0; s < 4; ++s) {
            int c = tid + s * 128, row = c >> 3, q = (c & 7) * 4;
            cpa16(uV + (row * SVU + q) * 4, Vg + (size_t)(kv0 + row) * 32 + q);
        }
        CP_COMMIT();
        if (it + 1 < 32) { KPREF(kv0 + 64, st ^ 1); }
        CP_COMMIT();

        // S = (Q/8) K^T, fp16 2-pass pass-major
        const uint32_t so = st * 64 * SKU * 4;
        float s8[8][4];
#pragma unroll
        for (int j = 0; j < 8; ++j)
#pragma unroll
            for (int c = 0; c < 4; ++c) s8[j][c] = 0.f;
#pragma unroll
        for (int kc = 0; kc < 4; ++kc) {
            uint32_t th[4][4], tl[4][4];
#pragma unroll
            for (int jp = 0; jp < 4; ++jp) {
                ldsm4(th[jp], uKh + so + kOff + (jp * 16 * SKU + kc * 8) * 4);
                ldsm4(tl[jp], uKl + so + kOff + (jp * 16 * SKU + kc * 8) * 4);
            }
#pragma unroll
            for (int jp = 0; jp < 4; ++jp) {
                mma16f(s8[2*jp],   qh[kc], th[jp]);
                mma16f(s8[2*jp+1], qh[kc], th[jp] + 2);
            }
#pragma unroll
            for (int jp = 0; jp < 4; ++jp) {
                mma16f(s8[2*jp],   qh[kc], tl[jp]);
                mma16f(s8[2*jp+1], qh[kc], tl[jp] + 2);
            }
        }

        CP_WAIT1();
        __syncthreads();

        // online softmax (rows gid, gid+8)
        float mx0 = -1e30f, mx1 = -1e30f;
#pragma unroll
        for (int j = 0; j < 8; ++j) {
            mx0 = fmaxf(mx0, fmaxf(s8[j][0], s8[j][1]));
            mx1 = fmaxf(mx1, fmaxf(s8[j][2], s8[j][3]));
        }
        mx0 = fmaxf(mx0, __shfl_xor_sync(0xffffffffu, mx0, 1));
        mx0 = fmaxf(mx0, __shfl_xor_sync(0xffffffffu, mx0, 2));
        mx1 = fmaxf(mx1, __shfl_xor_sync(0xffffffffu, mx1, 1));
        mx1 = fmaxf(mx1, __shfl_xor_sync(0xffffffffu, mx1, 2));
        float mn0 = fmaxf(m0r, mx0), mn1 = fmaxf(m1r, mx1);
        float al0 = __expf(m0r - mn0), al1 = __expf(m1r - mn1);
        m0r = mn0; m1r = mn1;
        float sum0 = 0.f, sum1 = 0.f;
#pragma unroll
        for (int j = 0; j < 8; ++j) {
            s8[j][0] = __expf(s8[j][0] - mn0); sum0 += s8[j][0];
            s8[j][1] = __expf(s8[j][1] - mn0); sum0 += s8[j][1];
            s8[j][2] = __expf(s8[j][2] - mn1); sum1 += s8[j][2];
            s8[j][3] = __expf(s8[j][3] - mn1); sum1 += s8[j][3];
        }
        sum0 += __shfl_xor_sync(0xffffffffu, sum0, 1);
        sum0 += __shfl_xor_sync(0xffffffffu, sum0, 2);
        sum1 += __shfl_xor_sync(0xffffffffu, sum1, 1);
        sum1 += __shfl_xor_sync(0xffffffffu, sum1, 2);
        l0 = l0 * al0 + sum0;
        l1 = l1 * al1 + sum1;
#pragma unroll
        for (int j = 0; j < 8; ++j) {
            o[j][0] *= al0; o[j][1] *= al0;
            o[j][2] *= al1; o[j][3] *= al1;
        }

        // O += P V : P fp16 from registers, V via ldsm.trans
#pragma unroll
        for (int kc = 0; kc < 4; ++kc) {
            uint32_t pa[4];
            pa[0] = f16x2(s8[2*kc][0],   s8[2*kc][1]);
            pa[1] = f16x2(s8[2*kc][2],   s8[2*kc][3]);
            pa[2] = f16x2(s8[2*kc+1][0], s8[2*kc+1][1]);
            pa[3] = f16x2(s8[2*kc+1][2], s8[2*kc+1][3]);
#pragma unroll
            for (int dp = 0; dp < 4; ++dp) {
                uint32_t t[4];
                ldsm4t(t, uV + vOff + kc * 16 * SVU * 4 + dp * 32);
                mma16f(o[2*dp],   pa, t);
                mma16f(o[2*dp+1], pa, t + 2);
            }
        }
    }
#undef KPREF

    const float linv0 = 1.f / l0, linv1 = 1.f / l1;
    const int b = bh >> 4, h = bh & 15;
    const int tok0 = q0 + wid * 16 + gid, tok1 = tok0 + 8;
    size_t b0u = (size_t)(b * 2048 + tok0) * 512 + h * 32;
    size_t b1u = (size_t)(b * 2048 + tok1) * 512 + h * 32;
#pragma unroll
    for (int j = 0; j < 8; ++j) {
        int ui = j * 4 + tig;
        g_aoh[b0u + ui] = f16x2(o[j][0] * linv0, o[j][1] * linv0);
        g_aoh[b1u + ui] = f16x2(o[j][2] * linv1, o[j][3] * linv1);
    }
}

// ---------------------------------------------------------------------------
extern "C" void kernel_launch(void* const* d_in, const int* in_sizes, int n_in,
                              void* d_out, int out_size)
{
    const float* x      = (const float*)d_in[0];
    const int*   pos    = (const int*)  d_in[1];
    const float* qkv_w  = (const float*)d_in[2];
    const float* proj_w = (const float*)d_in[3];
    const float* proj_b = (const float*)d_in[4];
    float*       out    = (float*)d_out;

    uint32_t *xh, *wqh, *wql, *wph, *wpl;
    cudaGetSymbolAddress((void**)&xh,  g_xh);
    cudaGetSymbolAddress((void**)&wqh, g_wqh);
    cudaGetSymbolAddress((void**)&wql, g_wql);
    cudaGetSymbolAddress((void**)&wph, g_wph);
    cudaGetSymbolAddress((void**)&wpl, g_wpl);

    splith_kernel<<<(M_*C_/4 + 255)/256, 256>>>((const float4*)x, xh, M_*C_/4);
    splitw_kernel<<<(3*C_*C_/4 + 255)/256, 256>>>((const float4*)qkv_w, wqh, wql, 3*C_*C_/4);
    splitw_kernel<<<(C_*C_/4 + 255)/256, 256>>>((const float4*)proj_w, wph, wpl, C_*C_/4);

    cudaFuncSetAttribute(qkv_mma_kernel,
                         cudaFuncAttributeMaxDynamicSharedMemorySize, GEMM_SMEM);
    cudaFuncSetAttribute(proj_mma_kernel,
                         cudaFuncAttributeMaxDynamicSharedMemorySize, GEMM_SMEM);
    cudaFuncSetAttribute(attn_mma_kernel,
                         cudaFuncAttributeMaxDynamicSharedMemorySize, ATTN_SMEM);

    qkv_mma_kernel<<<dim3(24, 32), 256, GEMM_SMEM>>>(pos);
    attn_mma_kernel<<<dim3(32, 32), 128, ATTN_SMEM>>>();
    proj_mma_kernel<<<dim3(8, 32), 256, GEMM_SMEM>>>(proj_b, out);
}